// round 7
// baseline (speedup 1.0000x reference)
#include <cuda_runtime.h>
#include <cuda_bf16.h>
#include <math.h>
#include <stdint.h>

// ---------------- problem constants ----------------------------------------
#define B_ 1024
#define T_ 64
#define D_ 512
#define HD_ 512
#define L_ 3
#define NG 2048          // 4*HD gate columns (gate-interleaved)
#define KK 1024          // D + HD fused K
#define FN_ 64
#define ATT 63

// ---------------- device scratch -------------------------------------------
__device__ __align__(16) __nv_bfloat16 g_Whi[(size_t)L_ * NG * KK];   // [l][n][k]
__device__ __align__(16) __nv_bfloat16 g_Wlo[(size_t)L_ * NG * KK];
__device__ __align__(16) __nv_bfloat16 g_xhi[(size_t)T_ * B_ * D_];   // [t][b][d]
__device__ __align__(16) __nv_bfloat16 g_xlo[(size_t)T_ * B_ * D_];
__device__ __align__(16) __nv_bfloat16 g_hhi[(size_t)2 * L_ * B_ * HD_];
__device__ __align__(16) __nv_bfloat16 g_hlo[(size_t)2 * L_ * B_ * HD_];
__device__ float g_c[(size_t)L_ * B_ * HD_];
__device__ __align__(16) float g_bias[L_ * NG];
__device__ float g_ys[(size_t)T_ * B_ * HD_];
__device__ float g_effw[577];

// ---------------- small asm helpers ----------------------------------------
__device__ __forceinline__ uint32_t smem_u32(const void* p) {
    uint32_t a;
    asm("{ .reg .u64 t; cvta.to.shared.u64 t, %1; cvt.u32.u64 %0, t; }" : "=r"(a) : "l"(p));
    return a;
}
__device__ __forceinline__ void cp16(uint32_t dst, const void* src) {
    asm volatile("cp.async.cg.shared.global [%0], [%1], 16;" :: "r"(dst), "l"(src));
}
__device__ __forceinline__ void cp_commit() { asm volatile("cp.async.commit_group;"); }
__device__ __forceinline__ void cp_wait1() { asm volatile("cp.async.wait_group 1;" ::: "memory"); }
__device__ __forceinline__ void cp_wait0() { asm volatile("cp.async.wait_group 0;" ::: "memory"); }

__device__ __forceinline__ void ldsm4(uint32_t* r, uint32_t addr) {
    asm volatile("ldmatrix.sync.aligned.m8n8.x4.shared.b16 {%0,%1,%2,%3}, [%4];"
                 : "=r"(r[0]), "=r"(r[1]), "=r"(r[2]), "=r"(r[3]) : "r"(addr));
}
__device__ __forceinline__ void mma16816(float* c, const uint32_t* a, const uint32_t* b) {
    asm volatile("mma.sync.aligned.m16n8k16.row.col.f32.bf16.bf16.f32 "
                 "{%0,%1,%2,%3}, {%4,%5,%6,%7}, {%8,%9}, {%0,%1,%2,%3};"
                 : "+f"(c[0]), "+f"(c[1]), "+f"(c[2]), "+f"(c[3])
                 : "r"(a[0]), "r"(a[1]), "r"(a[2]), "r"(a[3]), "r"(b[0]), "r"(b[1]));
}
__device__ __forceinline__ float sigf(float x) { return 1.f / (1.f + expf(-x)); }

// ---------------- prep kernels ---------------------------------------------
__global__ void prep_w_kernel(const float* __restrict__ W_ih, const float* __restrict__ W_hh,
                              const float* __restrict__ b_ih, const float* __restrict__ b_hh) {
    size_t idx = (size_t)blockIdx.x * blockDim.x + threadIdx.x;
    const size_t total = (size_t)L_ * NG * KK;
    if (idx < total) {
        int l = (int)(idx / ((size_t)NG * KK));
        size_t r = idx % ((size_t)NG * KK);
        int n = (int)(r / KK), k = (int)(r % KK);
        int oc = (n & 3) * HD_ + (n >> 2);
        float v = (k < D_) ? W_ih[((size_t)l * NG + oc) * D_ + k]
                           : W_hh[((size_t)l * NG + oc) * HD_ + (k - D_)];
        __nv_bfloat16 hi = __float2bfloat16(v);
        g_Whi[idx] = hi;
        g_Wlo[idx] = __float2bfloat16(v - __bfloat162float(hi));
    }
    if (idx < (size_t)L_ * NG) {
        int l = (int)(idx / NG), n = (int)(idx % NG);
        int oc = (n & 3) * HD_ + (n >> 2);
        g_bias[idx] = b_ih[(size_t)l * NG + oc] + b_hh[(size_t)l * NG + oc];
    }
}

// merged: x split + state zero + folded output vector
__global__ void prep_misc_kernel(const float* __restrict__ x,
                                 const float* __restrict__ lin2_W, const float* __restrict__ lin2_b,
                                 const float* __restrict__ out_W, const float* __restrict__ out_b) {
    size_t idx = (size_t)blockIdx.x * blockDim.x + threadIdx.x;
    const size_t totx = (size_t)T_ * B_ * D_;
    if (idx < totx) {
        int t = (int)(idx / ((size_t)B_ * D_));
        size_t r = idx % ((size_t)B_ * D_);
        int b = (int)(r / D_), d = (int)(r % D_);
        float v = x[((size_t)b * T_ + t) * D_ + d];
        __nv_bfloat16 hi = __float2bfloat16(v);
        g_xhi[idx] = hi;
        g_xlo[idx] = __float2bfloat16(v - __bfloat162float(hi));
    }
    const size_t nh = (size_t)2 * L_ * B_ * HD_;
    if (idx < nh) { g_hhi[idx] = __float2bfloat16(0.f); g_hlo[idx] = __float2bfloat16(0.f); }
    if (idx < (size_t)L_ * B_ * HD_) g_c[idx] = 0.f;
    if (idx < 576) {
        float a = 0.f;
        for (int j = 0; j < HD_; j++) a += out_W[j] * lin2_W[(size_t)j * 576 + idx];
        g_effw[idx] = a;
    } else if (idx == 576) {
        float a = out_b[0];
        for (int j = 0; j < HD_; j++) a += out_W[j] * lin2_b[j];
        g_effw[576] = a;
    }
}

// ---------------- mma.sync LSTM step (wavefront cell) -----------------------
// CTA 128(M batch) x 128(N gates), 8 warps (4x2), warp tile 32x64.
// bf16 hi/lo 3-pass (AhBh + AlBh + AhBl), fp32 register accumulators.
// Mainloop: 3-stage smem pipeline + double-buffered register fragments.
#define KCH 64
#define NCH (KK / KCH)            // 16 chunks
#define ROWB 144                  // 128B payload + 16B pad (conflict-free ldmatrix)
#define TILE_BYTES (128 * ROWB)   // 18432
#define AH_OFF 0
#define AL_OFF (TILE_BYTES)
#define BH_OFF (2 * TILE_BYTES)
#define BL_OFF (3 * TILE_BYTES)
#define STAGE_BYTES (4 * TILE_BYTES)   // 73728
#define NSTAGE 3
#define DYN_SMEM (NSTAGE * STAGE_BYTES)  // 221184 (1 CTA/SM)

__global__ __launch_bounds__(256, 1)
void lstm_step_mma(int diag, int lmin) {
    extern __shared__ __align__(128) char dynsm[];
    const uint32_t smb = smem_u32(dynsm);

    const int tid  = threadIdx.x;
    const int lane = tid & 31;
    const int wid  = tid >> 5;
    const int wm   = (wid & 3) * 32;        // warp m offset
    const int wn   = (wid >> 2) * 64;       // warp n offset
    const int l = lmin + (int)blockIdx.z;
    const int t = diag - l;
    const int mBase = (int)blockIdx.y * 128;
    const int nBase = (int)blockIdx.x * 128;
    const int cur = t & 1, nxt = cur ^ 1;

    // operand bases
    const __nv_bfloat16 *A0h, *A0l;
    if (l == 0) {
        size_t o = (size_t)t * B_ * D_;
        A0h = g_xhi + o; A0l = g_xlo + o;
    } else {
        size_t o = (size_t)(nxt * L_ + (l - 1)) * B_ * HD_;
        A0h = g_hhi + o; A0l = g_hlo + o;
    }
    size_t o1 = (size_t)(cur * L_ + l) * B_ * HD_;
    const __nv_bfloat16 *A1h = g_hhi + o1, *A1l = g_hlo + o1;
    const __nv_bfloat16 *Wh = g_Whi + (size_t)l * NG * KK;
    const __nv_bfloat16 *Wl = g_Wlo + (size_t)l * NG * KK;

    // ---- chunk loader: 72KB per chunk via cp.async --------------------------
    auto load_chunk = [&](int c) {
        const int k0 = c * KCH;                      // multiple of 64 -> never splits A0/A1
        const __nv_bfloat16 *ah = (k0 < D_) ? A0h + k0 : A1h + (k0 - D_);
        const __nv_bfloat16 *al = (k0 < D_) ? A0l + k0 : A1l + (k0 - D_);
        const uint32_t sb = smb + (c % NSTAGE) * STAGE_BYTES;
        for (int i = tid; i < 1024; i += 256) {      // 128 rows x 8 x 16B per operand
            int row = i >> 3, ch = i & 7;
            uint32_t so = (uint32_t)(row * ROWB + ch * 16);
            size_t ga = (size_t)(mBase + row) * 512 + ch * 8;
            size_t gb = (size_t)(nBase + row) * (size_t)KK + k0 + ch * 8;
            cp16(sb + AH_OFF + so, ah + ga);
            cp16(sb + AL_OFF + so, al + ga);
            cp16(sb + BH_OFF + so, Wh + gb);
            cp16(sb + BL_OFF + so, Wl + gb);
        }
        cp_commit();
    };

    float acc[2][8][4];
#pragma unroll
    for (int i = 0; i < 2; i++)
#pragma unroll
        for (int j = 0; j < 8; j++)
#pragma unroll
            for (int q = 0; q < 4; q++) acc[i][j][q] = 0.f;

    // ldmatrix per-lane offsets (within a tile)
    const uint32_t a_off = (uint32_t)((wm + (lane & 15)) * ROWB + (lane >> 4) * 16);
    const uint32_t b_row = (uint32_t)(wn + (lane & 7) + ((lane >> 4) << 3));
    const uint32_t b_off = b_row * ROWB + (((lane >> 3) & 1) << 4);

    // double-buffered register fragments: [buf][hi/lo][...]
    uint32_t af[2][2][2][4];   // [buf][h/l][mt][4]
    uint32_t bf[2][2][8][2];   // [buf][h/l][nt][2]

    auto load_frags = [&](uint32_t sb, int kk, int buf) {
        const uint32_t kofs = (uint32_t)(kk * 32);
#pragma unroll
        for (int mt = 0; mt < 2; mt++) {
            uint32_t ad = sb + a_off + (uint32_t)(mt * 16 * ROWB) + kofs;
            ldsm4(af[buf][0][mt], ad + AH_OFF);
            ldsm4(af[buf][1][mt], ad + AL_OFF);
        }
#pragma unroll
        for (int g = 0; g < 4; g++) {
            uint32_t bd = sb + b_off + (uint32_t)(g * 16 * ROWB) + kofs;
            uint32_t r[4];
            ldsm4(r, bd + BH_OFF);
            bf[buf][0][2 * g][0] = r[0]; bf[buf][0][2 * g][1] = r[1];
            bf[buf][0][2 * g + 1][0] = r[2]; bf[buf][0][2 * g + 1][1] = r[3];
            ldsm4(r, bd + BL_OFF);
            bf[buf][1][2 * g][0] = r[0]; bf[buf][1][2 * g][1] = r[1];
            bf[buf][1][2 * g + 1][0] = r[2]; bf[buf][1][2 * g + 1][1] = r[3];
        }
    };
    auto mma_all = [&](int buf) {
#pragma unroll
        for (int mt = 0; mt < 2; mt++)
#pragma unroll
            for (int nt = 0; nt < 8; nt++) mma16816(acc[mt][nt], af[buf][0][mt], bf[buf][0][nt]);
#pragma unroll
        for (int mt = 0; mt < 2; mt++)
#pragma unroll
            for (int nt = 0; nt < 8; nt++) mma16816(acc[mt][nt], af[buf][1][mt], bf[buf][0][nt]);
#pragma unroll
        for (int mt = 0; mt < 2; mt++)
#pragma unroll
            for (int nt = 0; nt < 8; nt++) mma16816(acc[mt][nt], af[buf][0][mt], bf[buf][1][nt]);
    };

    load_chunk(0);
    load_chunk(1);

    for (int c = 0; c < NCH; c++) {
        if (c + 1 < NCH) cp_wait1(); else cp_wait0();
        __syncthreads();
        const uint32_t sb = smb + (c % NSTAGE) * STAGE_BYTES;

        // issue next-next chunk's cp.async EARLY (stage consumed at chunk c-1;
        // the barrier above makes the overwrite safe)
        if (c + 2 < NCH) load_chunk(c + 2);

        // software-pipelined fragment loop over 4 x k16
        load_frags(sb, 0, 0);
#pragma unroll
        for (int kk = 0; kk < 4; kk++) {
            if (kk < 3) load_frags(sb, kk + 1, (kk + 1) & 1);
            mma_all(kk & 1);
        }
    }

    // ---- fused LSTM-cell epilogue -----------------------------------------
    const int q = lane & 3;
    const bool active = (q & 1) == 0;
    float* cbase = g_c + (size_t)l * B_ * HD_;
    __nv_bfloat16* hh = g_hhi + (size_t)(nxt * L_ + l) * B_ * HD_;
    __nv_bfloat16* hl = g_hlo + (size_t)(nxt * L_ + l) * B_ * HD_;
    float* ys = (l == 2) ? (g_ys + (size_t)t * B_ * HD_) : nullptr;

#pragma unroll
    for (int mt = 0; mt < 2; mt++) {
#pragma unroll
        for (int nt = 0; nt < 8; nt++) {
            float* cc = acc[mt][nt];
            float p0 = __shfl_xor_sync(0xffffffffu, cc[0], 1);
            float p1 = __shfl_xor_sync(0xffffffffu, cc[1], 1);
            float p2 = __shfl_xor_sync(0xffffffffu, cc[2], 1);
            float p3 = __shfl_xor_sync(0xffffffffu, cc[3], 1);
            if (active) {
                int n0 = nBase + wn + nt * 8 + q * 2;     // multiple of 4
                int j = n0 >> 2;
                const float4 bs = *(const float4*)&g_bias[l * NG + n0];
                int r0 = mBase + wm + mt * 16 + (lane >> 2);
#pragma unroll
                for (int rg = 0; rg < 2; rg++) {
                    int row = r0 + rg * 8;
                    float gi = (rg ? cc[2] : cc[0]) + bs.x;
                    float gf = (rg ? cc[3] : cc[1]) + bs.y;
                    float gg = (rg ? p2 : p0) + bs.z;
                    float go = (rg ? p3 : p1) + bs.w;
                    size_t off = (size_t)row * HD_ + j;
                    float cold = cbase[off];
                    float cn = sigf(gf) * cold + sigf(gi) * tanhf(gg);
                    float hn = sigf(go) * tanhf(cn);
                    cbase[off] = cn;
                    __nv_bfloat16 hi = __float2bfloat16(hn);
                    hh[off] = hi;
                    hl[off] = __float2bfloat16(hn - __bfloat162float(hi));
                    if (ys) ys[off] = hn;
                }
            }
        }
    }
}

// ---------------- attention / TPA head --------------------------------------
#define HEAD_SMEM_FLOATS (32768 + 8064 + 4032 + 512 + 64 + 512 + 64 + 256)

__global__ __launch_bounds__(256)
void head_kernel(const float* __restrict__ conv_W, const float* __restrict__ conv_b,
                 const float* __restrict__ lin1_W, const float* __restrict__ lin1_b,
                 float* __restrict__ out) {
    extern __shared__ float sm[];
    float* conv_s  = sm;
    float* Hblk    = conv_s + 32768;
    float* kW_s    = Hblk + 8064;
    float* htt_s   = kW_s + 4032;
    float* w_s     = htt_s + 512;
    float* alpha_s = w_s + 64;
    float* v_s     = alpha_s + 512;
    float* red_s   = v_s + 64;

    const int b = blockIdx.x;
    const int tid = threadIdx.x;
    const int lane = tid & 31;
    const int warp = tid >> 5;

    for (int i = tid; i < FN_ * ATT; i += 256) kW_s[i] = conv_W[i];
    for (int i = tid; i < HD_; i += 256)
        htt_s[i] = g_ys[(size_t)(T_ - 1) * B_ * HD_ + (size_t)b * HD_ + i];
    __syncthreads();

    for (int qq = 0; qq < 8; qq++) {
        int qi = warp * 8 + qq;
        float p = 0.f;
        for (int k = lane; k < HD_; k += 32) p += htt_s[k] * lin1_W[(size_t)qi * HD_ + k];
#pragma unroll
        for (int o = 16; o; o >>= 1) p += __shfl_xor_sync(0xffffffffu, p, o);
        if (lane == 0) w_s[qi] = p + lin1_b[qi];
    }

    for (int fb = 0; fb < 4; fb++) {
        int f0 = fb * 128;
        for (int i = tid; i < ATT * 128; i += 256) {
            int tt = i >> 7, fi = i & 127;
            float v = g_ys[(size_t)tt * B_ * HD_ + (size_t)b * HD_ + f0 + fi];
            Hblk[i] = v > 0.f ? v : 0.f;
        }
        __syncthreads();
        int fi = tid & 127;
        int c0 = tid >> 7;
        for (int c = c0; c < FN_; c += 2) {
            float acc = conv_b[c];
            const float* kwr = &kW_s[c * ATT];
            for (int tt = 0; tt < ATT; tt++) acc += kwr[tt] * Hblk[tt * 128 + fi];
            conv_s[(c << 9) + f0 + fi] = acc > 0.f ? acc : 0.f;
        }
        __syncthreads();
    }

    for (int p = warp; p < 512; p += 8) {
        float a = conv_s[p * 64 + lane] * w_s[lane]
                + conv_s[p * 64 + 32 + lane] * w_s[32 + lane];
#pragma unroll
        for (int o = 16; o; o >>= 1) a += __shfl_xor_sync(0xffffffffu, a, o);
        if (lane == 0) alpha_s[p] = 1.f / (1.f + expf(-a));
    }
    __syncthreads();

    {
        int qn = tid & 63, part = tid >> 6;
        float a = 0.f;
        for (int p = part; p < 512; p += 4) a += alpha_s[p] * conv_s[p * 64 + qn];
        red_s[tid] = a;
    }
    __syncthreads();
    if (tid < 64) v_s[tid] = red_s[tid] + red_s[64 + tid] + red_s[128 + tid] + red_s[192 + tid];
    __syncthreads();

    float a = 0.f;
    for (int k = tid; k < HD_; k += 256) a += htt_s[k] * g_effw[k];
    if (tid < 64) a += v_s[tid] * g_effw[HD_ + tid];
#pragma unroll
    for (int o = 16; o; o >>= 1) a += __shfl_xor_sync(0xffffffffu, a, o);
    if (lane == 0) red_s[warp] = a;
    __syncthreads();
    if (tid == 0) {
        float tot = g_effw[576];
        for (int i = 0; i < 8; i++) tot += red_s[i];
        out[b] = tot;
    }
}

// ---------------- launch ----------------------------------------------------
extern "C" void kernel_launch(void* const* d_in, const int* in_sizes, int n_in,
                              void* d_out, int out_size) {
    const float* x      = (const float*)d_in[0];
    const float* W_ih   = (const float*)d_in[1];
    const float* W_hh   = (const float*)d_in[2];
    const float* b_ih   = (const float*)d_in[3];
    const float* b_hh   = (const float*)d_in[4];
    const float* conv_W = (const float*)d_in[5];
    const float* conv_b = (const float*)d_in[6];
    const float* lin1_W = (const float*)d_in[7];
    const float* lin1_b = (const float*)d_in[8];
    const float* lin2_W = (const float*)d_in[9];
    const float* lin2_b = (const float*)d_in[10];
    const float* out_W  = (const float*)d_in[11];
    const float* out_b  = (const float*)d_in[12];
    float* out = (float*)d_out;

    {   // prep (2 launches)
        size_t tw = (size_t)L_ * NG * KK;
        prep_w_kernel<<<(unsigned)((tw + 255) / 256), 256>>>(W_ih, W_hh, b_ih, b_hh);
        size_t tx = (size_t)T_ * B_ * D_;
        prep_misc_kernel<<<(unsigned)((tx + 255) / 256), 256>>>(x, lin2_W, lin2_b, out_W, out_b);
    }

    // wavefront recurrence over diagonals d = t + l
    cudaFuncSetAttribute(lstm_step_mma, cudaFuncAttributeMaxDynamicSharedMemorySize, DYN_SMEM);
    for (int d = 0; d < T_ + L_ - 1; d++) {
        int lmin = d - (T_ - 1); if (lmin < 0) lmin = 0;
        int lmax = (d < L_ - 1) ? d : (L_ - 1);
        dim3 grid(NG / 128, B_ / 128, lmax - lmin + 1);   // (16, 8, nc)
        lstm_step_mma<<<grid, 256, DYN_SMEM>>>(d, lmin);
    }

    // head
    cudaFuncSetAttribute(head_kernel, cudaFuncAttributeMaxDynamicSharedMemorySize,
                         HEAD_SMEM_FLOATS * (int)sizeof(float));
    head_kernel<<<B_, 256, HEAD_SMEM_FLOATS * (int)sizeof(float)>>>(
        conv_W, conv_b, lin1_W, lin1_b, out);
}

// round 8
// speedup vs baseline: 1.1184x; 1.1184x over previous
#include <cuda_runtime.h>
#include <cuda_bf16.h>
#include <math.h>
#include <stdint.h>

// ---------------- problem constants ----------------------------------------
#define B_ 1024
#define T_ 64
#define D_ 512
#define HD_ 512
#define L_ 3
#define NG 2048          // 4*HD gate columns (gate-interleaved)
#define KK 1024          // D + HD fused K
#define FN_ 64
#define ATT 63

// ---------------- device scratch -------------------------------------------
__device__ __align__(16) __nv_bfloat16 g_Whi[(size_t)L_ * NG * KK];   // [l][n][k]
__device__ __align__(16) __nv_bfloat16 g_Wlo[(size_t)L_ * NG * KK];
__device__ __align__(16) __nv_bfloat16 g_xhi[(size_t)T_ * B_ * D_];   // [t][b][d]
__device__ __align__(16) __nv_bfloat16 g_xlo[(size_t)T_ * B_ * D_];
__device__ __align__(16) __nv_bfloat16 g_hhi[(size_t)2 * L_ * B_ * HD_];
__device__ __align__(16) __nv_bfloat16 g_hlo[(size_t)2 * L_ * B_ * HD_];
__device__ float g_c[(size_t)L_ * B_ * HD_];
__device__ __align__(16) float g_bias[L_ * NG];
__device__ float g_ys[(size_t)T_ * B_ * HD_];
__device__ float g_effw[577];

// ---------------- small asm helpers ----------------------------------------
__device__ __forceinline__ uint32_t smem_u32(const void* p) {
    uint32_t a;
    asm("{ .reg .u64 t; cvta.to.shared.u64 t, %1; cvt.u32.u64 %0, t; }" : "=r"(a) : "l"(p));
    return a;
}
__device__ __forceinline__ void cp16(uint32_t dst, const void* src) {
    asm volatile("cp.async.cg.shared.global [%0], [%1], 16;" :: "r"(dst), "l"(src));
}
__device__ __forceinline__ void cp_commit() { asm volatile("cp.async.commit_group;"); }
__device__ __forceinline__ void cp_wait1() { asm volatile("cp.async.wait_group 1;" ::: "memory"); }
__device__ __forceinline__ void cp_wait0() { asm volatile("cp.async.wait_group 0;" ::: "memory"); }

__device__ __forceinline__ void ldsm4(uint32_t* r, uint32_t addr) {
    asm volatile("ldmatrix.sync.aligned.m8n8.x4.shared.b16 {%0,%1,%2,%3}, [%4];"
                 : "=r"(r[0]), "=r"(r[1]), "=r"(r[2]), "=r"(r[3]) : "r"(addr));
}
__device__ __forceinline__ void mma16816(float* c, const uint32_t* a, const uint32_t* b) {
    asm volatile("mma.sync.aligned.m16n8k16.row.col.f32.bf16.bf16.f32 "
                 "{%0,%1,%2,%3}, {%4,%5,%6,%7}, {%8,%9}, {%0,%1,%2,%3};"
                 : "+f"(c[0]), "+f"(c[1]), "+f"(c[2]), "+f"(c[3])
                 : "r"(a[0]), "r"(a[1]), "r"(a[2]), "r"(a[3]), "r"(b[0]), "r"(b[1]));
}
__device__ __forceinline__ float sigf(float x) { return 1.f / (1.f + expf(-x)); }

// ---------------- prep kernels ---------------------------------------------
__global__ void prep_w_kernel(const float* __restrict__ W_ih, const float* __restrict__ W_hh,
                              const float* __restrict__ b_ih, const float* __restrict__ b_hh) {
    size_t idx = (size_t)blockIdx.x * blockDim.x + threadIdx.x;
    const size_t total = (size_t)L_ * NG * KK;
    if (idx < total) {
        int l = (int)(idx / ((size_t)NG * KK));
        size_t r = idx % ((size_t)NG * KK);
        int n = (int)(r / KK), k = (int)(r % KK);
        int oc = (n & 3) * HD_ + (n >> 2);
        float v = (k < D_) ? W_ih[((size_t)l * NG + oc) * D_ + k]
                           : W_hh[((size_t)l * NG + oc) * HD_ + (k - D_)];
        __nv_bfloat16 hi = __float2bfloat16(v);
        g_Whi[idx] = hi;
        g_Wlo[idx] = __float2bfloat16(v - __bfloat162float(hi));
    }
    if (idx < (size_t)L_ * NG) {
        int l = (int)(idx / NG), n = (int)(idx % NG);
        int oc = (n & 3) * HD_ + (n >> 2);
        g_bias[idx] = b_ih[(size_t)l * NG + oc] + b_hh[(size_t)l * NG + oc];
    }
}

// merged: x split + state zero + folded output vector
__global__ void prep_misc_kernel(const float* __restrict__ x,
                                 const float* __restrict__ lin2_W, const float* __restrict__ lin2_b,
                                 const float* __restrict__ out_W, const float* __restrict__ out_b) {
    size_t idx = (size_t)blockIdx.x * blockDim.x + threadIdx.x;
    const size_t totx = (size_t)T_ * B_ * D_;
    if (idx < totx) {
        int t = (int)(idx / ((size_t)B_ * D_));
        size_t r = idx % ((size_t)B_ * D_);
        int b = (int)(r / D_), d = (int)(r % D_);
        float v = x[((size_t)b * T_ + t) * D_ + d];
        __nv_bfloat16 hi = __float2bfloat16(v);
        g_xhi[idx] = hi;
        g_xlo[idx] = __float2bfloat16(v - __bfloat162float(hi));
    }
    const size_t nh = (size_t)2 * L_ * B_ * HD_;
    if (idx < nh) { g_hhi[idx] = __float2bfloat16(0.f); g_hlo[idx] = __float2bfloat16(0.f); }
    if (idx < (size_t)L_ * B_ * HD_) g_c[idx] = 0.f;
    if (idx < 576) {
        float a = 0.f;
        for (int j = 0; j < HD_; j++) a += out_W[j] * lin2_W[(size_t)j * 576 + idx];
        g_effw[idx] = a;
    } else if (idx == 576) {
        float a = out_b[0];
        for (int j = 0; j < HD_; j++) a += out_W[j] * lin2_b[j];
        g_effw[576] = a;
    }
}

// ---------------- mma.sync LSTM step (wavefront cell) -----------------------
// CTA 128(M batch) x 128(N gates), 16 warps (4x4), warp tile 32x32.
// bf16 hi/lo 3-pass (AhBh + AlBh + AhBl), fp32 register accumulators.
#define KCH 64
#define NCH (KK / KCH)            // 16 chunks
#define ROWB 144                  // 128B payload + 16B pad (conflict-free ldmatrix)
#define TILE_BYTES (128 * ROWB)   // 18432
#define AH_OFF 0
#define AL_OFF (TILE_BYTES)
#define BH_OFF (2 * TILE_BYTES)
#define BL_OFF (3 * TILE_BYTES)
#define STAGE_BYTES (4 * TILE_BYTES)   // 73728
#define NSTAGE 3
#define DYN_SMEM (NSTAGE * STAGE_BYTES)  // 221184 (1 CTA/SM)
#define NTHR 512

__global__ __launch_bounds__(NTHR, 1)
void lstm_step_mma(int diag, int lmin) {
    extern __shared__ __align__(128) char dynsm[];
    const uint32_t smb = smem_u32(dynsm);

    const int tid  = threadIdx.x;
    const int lane = tid & 31;
    const int wid  = tid >> 5;               // 0..15
    const int wm   = (wid & 3) * 32;         // warp m offset (4 m-warps)
    const int wn   = (wid >> 2) * 32;        // warp n offset (4 n-warps)
    const int l = lmin + (int)blockIdx.z;
    const int t = diag - l;
    const int mBase = (int)blockIdx.y * 128;
    const int nBase = (int)blockIdx.x * 128;
    const int cur = t & 1, nxt = cur ^ 1;

    // operand bases
    const __nv_bfloat16 *A0h, *A0l;
    if (l == 0) {
        size_t o = (size_t)t * B_ * D_;
        A0h = g_xhi + o; A0l = g_xlo + o;
    } else {
        size_t o = (size_t)(nxt * L_ + (l - 1)) * B_ * HD_;
        A0h = g_hhi + o; A0l = g_hlo + o;
    }
    size_t o1 = (size_t)(cur * L_ + l) * B_ * HD_;
    const __nv_bfloat16 *A1h = g_hhi + o1, *A1l = g_hlo + o1;
    const __nv_bfloat16 *Wh = g_Whi + (size_t)l * NG * KK;
    const __nv_bfloat16 *Wl = g_Wlo + (size_t)l * NG * KK;

    // ---- chunk loader: 72KB per chunk via cp.async --------------------------
    auto load_chunk = [&](int c) {
        const int k0 = c * KCH;                      // multiple of 64 -> never splits A0/A1
        const __nv_bfloat16 *ah = (k0 < D_) ? A0h + k0 : A1h + (k0 - D_);
        const __nv_bfloat16 *al = (k0 < D_) ? A0l + k0 : A1l + (k0 - D_);
        const uint32_t sb = smb + (c % NSTAGE) * STAGE_BYTES;
        for (int i = tid; i < 1024; i += NTHR) {     // 128 rows x 8 x 16B per operand
            int row = i >> 3, ch = i & 7;
            uint32_t so = (uint32_t)(row * ROWB + ch * 16);
            size_t ga = (size_t)(mBase + row) * 512 + ch * 8;
            size_t gb = (size_t)(nBase + row) * (size_t)KK + k0 + ch * 8;
            cp16(sb + AH_OFF + so, ah + ga);
            cp16(sb + AL_OFF + so, al + ga);
            cp16(sb + BH_OFF + so, Wh + gb);
            cp16(sb + BL_OFF + so, Wl + gb);
        }
        cp_commit();
    };

    float acc[2][4][4];
#pragma unroll
    for (int i = 0; i < 2; i++)
#pragma unroll
        for (int j = 0; j < 4; j++)
#pragma unroll
            for (int q = 0; q < 4; q++) acc[i][j][q] = 0.f;

    // ldmatrix per-lane offsets (within a tile)
    const uint32_t a_off = (uint32_t)((wm + (lane & 15)) * ROWB + (lane >> 4) * 16);
    const uint32_t b_row = (uint32_t)(wn + (lane & 7) + ((lane >> 4) << 3));
    const uint32_t b_off = b_row * ROWB + (((lane >> 3) & 1) << 4);

    load_chunk(0);
    load_chunk(1);

    for (int c = 0; c < NCH; c++) {
        if (c + 1 < NCH) cp_wait1(); else cp_wait0();
        __syncthreads();
        const uint32_t sb = smb + (c % NSTAGE) * STAGE_BYTES;

#pragma unroll
        for (int kk = 0; kk < 4; kk++) {             // 4 x k16 per 64-k chunk
            const uint32_t kofs = (uint32_t)(kk * 32);
            uint32_t a_hi[2][4], a_lo[2][4];
#pragma unroll
            for (int mt = 0; mt < 2; mt++) {
                uint32_t ad = sb + a_off + (uint32_t)(mt * 16 * ROWB) + kofs;
                ldsm4(a_hi[mt], ad + AH_OFF);
                ldsm4(a_lo[mt], ad + AL_OFF);
            }
            uint32_t b_hi[4][2], b_lo[4][2];
#pragma unroll
            for (int g = 0; g < 2; g++) {            // warp n width 32 -> 2 ldsm4 per h/l
                uint32_t bd = sb + b_off + (uint32_t)(g * 16 * ROWB) + kofs;
                uint32_t r[4];
                ldsm4(r, bd + BH_OFF);
                b_hi[2 * g][0] = r[0]; b_hi[2 * g][1] = r[1];
                b_hi[2 * g + 1][0] = r[2]; b_hi[2 * g + 1][1] = r[3];
                ldsm4(r, bd + BL_OFF);
                b_lo[2 * g][0] = r[0]; b_lo[2 * g][1] = r[1];
                b_lo[2 * g + 1][0] = r[2]; b_lo[2 * g + 1][1] = r[3];
            }
#pragma unroll
            for (int mt = 0; mt < 2; mt++)
#pragma unroll
                for (int nt = 0; nt < 4; nt++) mma16816(acc[mt][nt], a_hi[mt], b_hi[nt]);
#pragma unroll
            for (int mt = 0; mt < 2; mt++)
#pragma unroll
                for (int nt = 0; nt < 4; nt++) mma16816(acc[mt][nt], a_lo[mt], b_hi[nt]);
#pragma unroll
            for (int mt = 0; mt < 2; mt++)
#pragma unroll
                for (int nt = 0; nt < 4; nt++) mma16816(acc[mt][nt], a_hi[mt], b_lo[nt]);
        }
        // stage (c+2)%NSTAGE was fully consumed at chunk c-1; barrier above protects it
        if (c + 2 < NCH) load_chunk(c + 2);
    }

    // ---- fused LSTM-cell epilogue -----------------------------------------
    const int q = lane & 3;
    const bool active = (q & 1) == 0;
    float* cbase = g_c + (size_t)l * B_ * HD_;
    __nv_bfloat16* hh = g_hhi + (size_t)(nxt * L_ + l) * B_ * HD_;
    __nv_bfloat16* hl = g_hlo + (size_t)(nxt * L_ + l) * B_ * HD_;
    float* ys = (l == 2) ? (g_ys + (size_t)t * B_ * HD_) : nullptr;

#pragma unroll
    for (int mt = 0; mt < 2; mt++) {
#pragma unroll
        for (int nt = 0; nt < 4; nt++) {
            float* cc = acc[mt][nt];
            float p0 = __shfl_xor_sync(0xffffffffu, cc[0], 1);
            float p1 = __shfl_xor_sync(0xffffffffu, cc[1], 1);
            float p2 = __shfl_xor_sync(0xffffffffu, cc[2], 1);
            float p3 = __shfl_xor_sync(0xffffffffu, cc[3], 1);
            if (active) {
                int n0 = nBase + wn + nt * 8 + q * 2;     // multiple of 4
                int j = n0 >> 2;
                const float4 bs = *(const float4*)&g_bias[l * NG + n0];
                int r0 = mBase + wm + mt * 16 + (lane >> 2);
#pragma unroll
                for (int rg = 0; rg < 2; rg++) {
                    int row = r0 + rg * 8;
                    float gi = (rg ? cc[2] : cc[0]) + bs.x;
                    float gf = (rg ? cc[3] : cc[1]) + bs.y;
                    float gg = (rg ? p2 : p0) + bs.z;
                    float go = (rg ? p3 : p1) + bs.w;
                    size_t off = (size_t)row * HD_ + j;
                    float cold = cbase[off];
                    float cn = sigf(gf) * cold + sigf(gi) * tanhf(gg);
                    float hn = sigf(go) * tanhf(cn);
                    cbase[off] = cn;
                    __nv_bfloat16 hi = __float2bfloat16(hn);
                    hh[off] = hi;
                    hl[off] = __float2bfloat16(hn - __bfloat162float(hi));
                    if (ys) ys[off] = hn;
                }
            }
        }
    }
}

// ---------------- attention / TPA head --------------------------------------
#define HEAD_SMEM_FLOATS (32768 + 8064 + 4032 + 512 + 64 + 512 + 64 + 256)

__global__ __launch_bounds__(256)
void head_kernel(const float* __restrict__ conv_W, const float* __restrict__ conv_b,
                 const float* __restrict__ lin1_W, const float* __restrict__ lin1_b,
                 float* __restrict__ out) {
    extern __shared__ float sm[];
    float* conv_s  = sm;
    float* Hblk    = conv_s + 32768;
    float* kW_s    = Hblk + 8064;
    float* htt_s   = kW_s + 4032;
    float* w_s     = htt_s + 512;
    float* alpha_s = w_s + 64;
    float* v_s     = alpha_s + 512;
    float* red_s   = v_s + 64;

    const int b = blockIdx.x;
    const int tid = threadIdx.x;
    const int lane = tid & 31;
    const int warp = tid >> 5;

    for (int i = tid; i < FN_ * ATT; i += 256) kW_s[i] = conv_W[i];
    for (int i = tid; i < HD_; i += 256)
        htt_s[i] = g_ys[(size_t)(T_ - 1) * B_ * HD_ + (size_t)b * HD_ + i];
    __syncthreads();

    for (int qq = 0; qq < 8; qq++) {
        int qi = warp * 8 + qq;
        float p = 0.f;
        for (int k = lane; k < HD_; k += 32) p += htt_s[k] * lin1_W[(size_t)qi * HD_ + k];
#pragma unroll
        for (int o = 16; o; o >>= 1) p += __shfl_xor_sync(0xffffffffu, p, o);
        if (lane == 0) w_s[qi] = p + lin1_b[qi];
    }

    for (int fb = 0; fb < 4; fb++) {
        int f0 = fb * 128;
        for (int i = tid; i < ATT * 128; i += 256) {
            int tt = i >> 7, fi = i & 127;
            float v = g_ys[(size_t)tt * B_ * HD_ + (size_t)b * HD_ + f0 + fi];
            Hblk[i] = v > 0.f ? v : 0.f;
        }
        __syncthreads();
        int fi = tid & 127;
        int c0 = tid >> 7;
        for (int c = c0; c < FN_; c += 2) {
            float acc = conv_b[c];
            const float* kwr = &kW_s[c * ATT];
            for (int tt = 0; tt < ATT; tt++) acc += kwr[tt] * Hblk[tt * 128 + fi];
            conv_s[(c << 9) + f0 + fi] = acc > 0.f ? acc : 0.f;
        }
        __syncthreads();
    }

    for (int p = warp; p < 512; p += 8) {
        float a = conv_s[p * 64 + lane] * w_s[lane]
                + conv_s[p * 64 + 32 + lane] * w_s[32 + lane];
#pragma unroll
        for (int o = 16; o; o >>= 1) a += __shfl_xor_sync(0xffffffffu, a, o);
        if (lane == 0) alpha_s[p] = 1.f / (1.f + expf(-a));
    }
    __syncthreads();

    {
        int qn = tid & 63, part = tid >> 6;
        float a = 0.f;
        for (int p = part; p < 512; p += 4) a += alpha_s[p] * conv_s[p * 64 + qn];
        red_s[tid] = a;
    }
    __syncthreads();
    if (tid < 64) v_s[tid] = red_s[tid] + red_s[64 + tid] + red_s[128 + tid] + red_s[192 + tid];
    __syncthreads();

    float a = 0.f;
    for (int k = tid; k < HD_; k += 256) a += htt_s[k] * g_effw[k];
    if (tid < 64) a += v_s[tid] * g_effw[HD_ + tid];
#pragma unroll
    for (int o = 16; o; o >>= 1) a += __shfl_xor_sync(0xffffffffu, a, o);
    if (lane == 0) red_s[warp] = a;
    __syncthreads();
    if (tid == 0) {
        float tot = g_effw[576];
        for (int i = 0; i < 8; i++) tot += red_s[i];
        out[b] = tot;
    }
}

// ---------------- launch ----------------------------------------------------
extern "C" void kernel_launch(void* const* d_in, const int* in_sizes, int n_in,
                              void* d_out, int out_size) {
    const float* x      = (const float*)d_in[0];
    const float* W_ih   = (const float*)d_in[1];
    const float* W_hh   = (const float*)d_in[2];
    const float* b_ih   = (const float*)d_in[3];
    const float* b_hh   = (const float*)d_in[4];
    const float* conv_W = (const float*)d_in[5];
    const float* conv_b = (const float*)d_in[6];
    const float* lin1_W = (const float*)d_in[7];
    const float* lin1_b = (const float*)d_in[8];
    const float* lin2_W = (const float*)d_in[9];
    const float* lin2_b = (const float*)d_in[10];
    const float* out_W  = (const float*)d_in[11];
    const float* out_b  = (const float*)d_in[12];
    float* out = (float*)d_out;

    {   // prep (2 launches)
        size_t tw = (size_t)L_ * NG * KK;
        prep_w_kernel<<<(unsigned)((tw + 255) / 256), 256>>>(W_ih, W_hh, b_ih, b_hh);
        size_t tx = (size_t)T_ * B_ * D_;
        prep_misc_kernel<<<(unsigned)((tx + 255) / 256), 256>>>(x, lin2_W, lin2_b, out_W, out_b);
    }

    // wavefront recurrence over diagonals d = t + l
    cudaFuncSetAttribute(lstm_step_mma, cudaFuncAttributeMaxDynamicSharedMemorySize, DYN_SMEM);
    for (int d = 0; d < T_ + L_ - 1; d++) {
        int lmin = d - (T_ - 1); if (lmin < 0) lmin = 0;
        int lmax = (d < L_ - 1) ? d : (L_ - 1);
        dim3 grid(NG / 128, B_ / 128, lmax - lmin + 1);   // (16, 8, nc)
        lstm_step_mma<<<grid, NTHR, DYN_SMEM>>>(d, lmin);
    }

    // head
    cudaFuncSetAttribute(head_kernel, cudaFuncAttributeMaxDynamicSharedMemorySize,
                         HEAD_SMEM_FLOATS * (int)sizeof(float));
    head_kernel<<<B_, 256, HEAD_SMEM_FLOATS * (int)sizeof(float)>>>(
        conv_W, conv_b, lin1_W, lin1_b, out);
}

// round 9
// speedup vs baseline: 1.1632x; 1.0401x over previous
#include <cuda_runtime.h>
#include <cuda_bf16.h>
#include <math.h>
#include <stdint.h>

// ---------------- problem constants ----------------------------------------
#define B_ 1024
#define T_ 64
#define D_ 512
#define HD_ 512
#define L_ 3
#define NG 2048          // 4*HD gate columns (gate-interleaved)
#define KK 1024          // D + HD fused K
#define FN_ 64
#define ATT 63

// ---------------- device scratch -------------------------------------------
__device__ __align__(16) __nv_bfloat16 g_Whi[(size_t)L_ * NG * KK];   // [l][n][k]
__device__ __align__(16) __nv_bfloat16 g_Wlo[(size_t)L_ * NG * KK];
__device__ __align__(16) __nv_bfloat16 g_xhi[(size_t)T_ * B_ * D_];   // [t][b][d]
__device__ __align__(16) __nv_bfloat16 g_xlo[(size_t)T_ * B_ * D_];
__device__ __align__(16) __nv_bfloat16 g_hhi[(size_t)2 * L_ * B_ * HD_];
__device__ __align__(16) __nv_bfloat16 g_hlo[(size_t)2 * L_ * B_ * HD_];
__device__ float g_c[(size_t)L_ * B_ * HD_];
__device__ __align__(16) float g_bias[L_ * NG];
__device__ float g_ys[(size_t)T_ * B_ * HD_];
__device__ float g_effw[577];

// ---------------- small asm helpers ----------------------------------------
__device__ __forceinline__ uint32_t smem_u32(const void* p) {
    uint32_t a;
    asm("{ .reg .u64 t; cvta.to.shared.u64 t, %1; cvt.u32.u64 %0, t; }" : "=r"(a) : "l"(p));
    return a;
}
__device__ __forceinline__ void cp16(uint32_t dst, const void* src) {
    asm volatile("cp.async.cg.shared.global [%0], [%1], 16;" :: "r"(dst), "l"(src));
}
// arrive-on-mbarrier when this thread's prior cp.asyncs complete (count -1, no inc)
__device__ __forceinline__ void cp_mbar_arrive(uint32_t mbar) {
    asm volatile("cp.async.mbarrier.arrive.noinc.shared.b64 [%0];" :: "r"(mbar) : "memory");
}
#define MBARRIER_INIT(addr, cnt) \
    asm volatile("mbarrier.init.shared.b64 [%0], %1;" :: "r"((uint32_t)(addr)), "r"((uint32_t)(cnt)) : "memory")
#define MBARRIER_ARRIVE(addr) \
    asm volatile("mbarrier.arrive.shared.b64 _, [%0];" :: "r"((uint32_t)(addr)) : "memory")
#define MBARRIER_WAIT_PARITY(addr, par) do { \
    uint32_t _m = (uint32_t)(addr); uint32_t _p = (uint32_t)(par); uint32_t _d; \
    asm volatile("{ .reg .pred p; mbarrier.try_wait.parity.acquire.cta.shared::cta.b64 p, [%1], %2; selp.b32 %0,1,0,p; }" \
        : "=r"(_d) : "r"(_m), "r"(_p) : "memory"); \
    if (!_d) { \
        asm volatile("{ .reg .pred P1; WL%=: mbarrier.try_wait.parity.acquire.cta.shared::cta.b64 P1, [%0], %1, 0x989680; @P1 bra.uni WD%=; bra.uni WL%=; WD%=: }" \
            :: "r"(_m), "r"(_p) : "memory"); \
    } } while (0)

__device__ __forceinline__ void ldsm4(uint32_t* r, uint32_t addr) {
    asm volatile("ldmatrix.sync.aligned.m8n8.x4.shared.b16 {%0,%1,%2,%3}, [%4];"
                 : "=r"(r[0]), "=r"(r[1]), "=r"(r[2]), "=r"(r[3]) : "r"(addr));
}
__device__ __forceinline__ void mma16816(float* c, const uint32_t* a, const uint32_t* b) {
    asm volatile("mma.sync.aligned.m16n8k16.row.col.f32.bf16.bf16.f32 "
                 "{%0,%1,%2,%3}, {%4,%5,%6,%7}, {%8,%9}, {%0,%1,%2,%3};"
                 : "+f"(c[0]), "+f"(c[1]), "+f"(c[2]), "+f"(c[3])
                 : "r"(a[0]), "r"(a[1]), "r"(a[2]), "r"(a[3]), "r"(b[0]), "r"(b[1]));
}
__device__ __forceinline__ float sigf(float x) { return 1.f / (1.f + expf(-x)); }

// ---------------- prep kernels ---------------------------------------------
__global__ void prep_w_kernel(const float* __restrict__ W_ih, const float* __restrict__ W_hh,
                              const float* __restrict__ b_ih, const float* __restrict__ b_hh) {
    size_t idx = (size_t)blockIdx.x * blockDim.x + threadIdx.x;
    const size_t total = (size_t)L_ * NG * KK;
    if (idx < total) {
        int l = (int)(idx / ((size_t)NG * KK));
        size_t r = idx % ((size_t)NG * KK);
        int n = (int)(r / KK), k = (int)(r % KK);
        int oc = (n & 3) * HD_ + (n >> 2);
        float v = (k < D_) ? W_ih[((size_t)l * NG + oc) * D_ + k]
                           : W_hh[((size_t)l * NG + oc) * HD_ + (k - D_)];
        __nv_bfloat16 hi = __float2bfloat16(v);
        g_Whi[idx] = hi;
        g_Wlo[idx] = __float2bfloat16(v - __bfloat162float(hi));
    }
    if (idx < (size_t)L_ * NG) {
        int l = (int)(idx / NG), n = (int)(idx % NG);
        int oc = (n & 3) * HD_ + (n >> 2);
        g_bias[idx] = b_ih[(size_t)l * NG + oc] + b_hh[(size_t)l * NG + oc];
    }
}

// merged: x split + state zero + folded output vector
__global__ void prep_misc_kernel(const float* __restrict__ x,
                                 const float* __restrict__ lin2_W, const float* __restrict__ lin2_b,
                                 const float* __restrict__ out_W, const float* __restrict__ out_b) {
    size_t idx = (size_t)blockIdx.x * blockDim.x + threadIdx.x;
    const size_t totx = (size_t)T_ * B_ * D_;
    if (idx < totx) {
        int t = (int)(idx / ((size_t)B_ * D_));
        size_t r = idx % ((size_t)B_ * D_);
        int b = (int)(r / D_), d = (int)(r % D_);
        float v = x[((size_t)b * T_ + t) * D_ + d];
        __nv_bfloat16 hi = __float2bfloat16(v);
        g_xhi[idx] = hi;
        g_xlo[idx] = __float2bfloat16(v - __bfloat162float(hi));
    }
    const size_t nh = (size_t)2 * L_ * B_ * HD_;
    if (idx < nh) { g_hhi[idx] = __float2bfloat16(0.f); g_hlo[idx] = __float2bfloat16(0.f); }
    if (idx < (size_t)L_ * B_ * HD_) g_c[idx] = 0.f;
    if (idx < 576) {
        float a = 0.f;
        for (int j = 0; j < HD_; j++) a += out_W[j] * lin2_W[(size_t)j * 576 + idx];
        g_effw[idx] = a;
    } else if (idx == 576) {
        float a = out_b[0];
        for (int j = 0; j < HD_; j++) a += out_W[j] * lin2_b[j];
        g_effw[576] = a;
    }
}

// ---------------- mma.sync LSTM step (wavefront cell) -----------------------
// CTA 128(M batch) x 128(N gates), 16 warps (4x4), warp tile 32x32.
// bf16 hi/lo 3-pass (AhBh + AlBh + AhBl), fp32 register accumulators.
// Pipeline: 3-stage smem ring with mbarrier full/empty (NO __syncthreads in
// mainloop -> warps desync and hide each other's ldsm/mma latency).
#define KCH 64
#define NCH (KK / KCH)            // 16 chunks
#define ROWB 144                  // 128B payload + 16B pad (conflict-free ldmatrix)
#define TILE_BYTES (128 * ROWB)   // 18432
#define AH_OFF 0
#define AL_OFF (TILE_BYTES)
#define BH_OFF (2 * TILE_BYTES)
#define BL_OFF (3 * TILE_BYTES)
#define STAGE_BYTES (4 * TILE_BYTES)   // 73728
#define NSTAGE 3
#define DYN_SMEM (NSTAGE * STAGE_BYTES)  // 221184 (1 CTA/SM)
#define NTHR 512

__global__ __launch_bounds__(NTHR, 1)
void lstm_step_mma(int diag, int lmin) {
    extern __shared__ __align__(128) char dynsm[];
    __shared__ __align__(8) unsigned long long s_full[NSTAGE], s_empty[NSTAGE];
    const uint32_t smb = smem_u32(dynsm);
    const uint32_t mb_full = smem_u32(s_full);
    const uint32_t mb_empty = smem_u32(s_empty);

    const int tid  = threadIdx.x;
    const int lane = tid & 31;
    const int wid  = tid >> 5;               // 0..15
    const int wm   = (wid & 3) * 32;         // warp m offset (4 m-warps)
    const int wn   = (wid >> 2) * 32;        // warp n offset (4 n-warps)
    const int l = lmin + (int)blockIdx.z;
    const int t = diag - l;
    const int mBase = (int)blockIdx.y * 128;
    const int nBase = (int)blockIdx.x * 128;
    const int cur = t & 1, nxt = cur ^ 1;

    if (tid == 0) {
#pragma unroll
        for (int s = 0; s < NSTAGE; s++) {
            MBARRIER_INIT(mb_full + s * 8, NTHR);    // cp-completion arrivals
            MBARRIER_INIT(mb_empty + s * 8, NTHR);   // consumer done-reading arrivals
        }
    }
    __syncthreads();   // the ONLY cta-wide barrier

    // operand bases
    const __nv_bfloat16 *A0h, *A0l;
    if (l == 0) {
        size_t o = (size_t)t * B_ * D_;
        A0h = g_xhi + o; A0l = g_xlo + o;
    } else {
        size_t o = (size_t)(nxt * L_ + (l - 1)) * B_ * HD_;
        A0h = g_hhi + o; A0l = g_hlo + o;
    }
    size_t o1 = (size_t)(cur * L_ + l) * B_ * HD_;
    const __nv_bfloat16 *A1h = g_hhi + o1, *A1l = g_hlo + o1;
    const __nv_bfloat16 *Wh = g_Whi + (size_t)l * NG * KK;
    const __nv_bfloat16 *Wl = g_Wlo + (size_t)l * NG * KK;

    // ---- chunk loader: 72KB per chunk via cp.async, signals full[s] ---------
    auto load_chunk = [&](int c) {
        const int k0 = c * KCH;                      // multiple of 64 -> never splits A0/A1
        const __nv_bfloat16 *ah = (k0 < D_) ? A0h + k0 : A1h + (k0 - D_);
        const __nv_bfloat16 *al = (k0 < D_) ? A0l + k0 : A1l + (k0 - D_);
        const int s = c % NSTAGE;
        const uint32_t sb = smb + s * STAGE_BYTES;
        for (int i = tid; i < 1024; i += NTHR) {     // 128 rows x 8 x 16B per operand
            int row = i >> 3, ch = i & 7;
            uint32_t so = (uint32_t)(row * ROWB + ch * 16);
            size_t ga = (size_t)(mBase + row) * 512 + ch * 8;
            size_t gb = (size_t)(nBase + row) * (size_t)KK + k0 + ch * 8;
            cp16(sb + AH_OFF + so, ah + ga);
            cp16(sb + AL_OFF + so, al + ga);
            cp16(sb + BH_OFF + so, Wh + gb);
            cp16(sb + BL_OFF + so, Wl + gb);
        }
        cp_mbar_arrive(mb_full + s * 8);
    };

    float acc[2][4][4];
#pragma unroll
    for (int i = 0; i < 2; i++)
#pragma unroll
        for (int j = 0; j < 4; j++)
#pragma unroll
            for (int q = 0; q < 4; q++) acc[i][j][q] = 0.f;

    // ldmatrix per-lane offsets (within a tile)
    const uint32_t a_off = (uint32_t)((wm + (lane & 15)) * ROWB + (lane >> 4) * 16);
    const uint32_t b_row = (uint32_t)(wn + (lane & 7) + ((lane >> 4) << 3));
    const uint32_t b_off = b_row * ROWB + (((lane >> 3) & 1) << 4);

    load_chunk(0);
    load_chunk(1);

    for (int c = 0; c < NCH; c++) {
        const int s = c % NSTAGE;
        const int k = c / NSTAGE;
        MBARRIER_WAIT_PARITY(mb_full + s * 8, k & 1);   // chunk c landed
        const uint32_t sb = smb + s * STAGE_BYTES;

#pragma unroll
        for (int kk = 0; kk < 4; kk++) {             // 4 x k16 per 64-k chunk
            const uint32_t kofs = (uint32_t)(kk * 32);
            uint32_t a_hi[2][4], a_lo[2][4];
#pragma unroll
            for (int mt = 0; mt < 2; mt++) {
                uint32_t ad = sb + a_off + (uint32_t)(mt * 16 * ROWB) + kofs;
                ldsm4(a_hi[mt], ad + AH_OFF);
                ldsm4(a_lo[mt], ad + AL_OFF);
            }
            uint32_t b_hi[4][2], b_lo[4][2];
#pragma unroll
            for (int g = 0; g < 2; g++) {            // warp n width 32 -> 2 ldsm4 per h/l
                uint32_t bd = sb + b_off + (uint32_t)(g * 16 * ROWB) + kofs;
                uint32_t r[4];
                ldsm4(r, bd + BH_OFF);
                b_hi[2 * g][0] = r[0]; b_hi[2 * g][1] = r[1];
                b_hi[2 * g + 1][0] = r[2]; b_hi[2 * g + 1][1] = r[3];
                ldsm4(r, bd + BL_OFF);
                b_lo[2 * g][0] = r[0]; b_lo[2 * g][1] = r[1];
                b_lo[2 * g + 1][0] = r[2]; b_lo[2 * g + 1][1] = r[3];
            }
#pragma unroll
            for (int mt = 0; mt < 2; mt++)
#pragma unroll
                for (int nt = 0; nt < 4; nt++) mma16816(acc[mt][nt], a_hi[mt], b_hi[nt]);
#pragma unroll
            for (int mt = 0; mt < 2; mt++)
#pragma unroll
                for (int nt = 0; nt < 4; nt++) mma16816(acc[mt][nt], a_lo[mt], b_hi[nt]);
#pragma unroll
            for (int mt = 0; mt < 2; mt++)
#pragma unroll
                for (int nt = 0; nt < 4; nt++) mma16816(acc[mt][nt], a_hi[mt], b_lo[nt]);
        }
        MBARRIER_ARRIVE(mb_empty + s * 8);           // done reading stage s (phase k)

        const int c2 = c + 2;
        if (c2 < NCH) {
            const int s2 = c2 % NSTAGE;
            const int k2 = c2 / NSTAGE;
            // stage s2's previous occupant is chunk c2-NSTAGE (phase k2-1):
            // wait until every warp finished reading it (skip for first lap)
            if (k2 >= 1) MBARRIER_WAIT_PARITY(mb_empty + s2 * 8, (k2 - 1) & 1);
            load_chunk(c2);
        }
    }

    // ---- fused LSTM-cell epilogue -----------------------------------------
    const int q = lane & 3;
    const bool active = (q & 1) == 0;
    float* cbase = g_c + (size_t)l * B_ * HD_;
    __nv_bfloat16* hh = g_hhi + (size_t)(nxt * L_ + l) * B_ * HD_;
    __nv_bfloat16* hl = g_hlo + (size_t)(nxt * L_ + l) * B_ * HD_;
    float* ys = (l == 2) ? (g_ys + (size_t)t * B_ * HD_) : nullptr;

#pragma unroll
    for (int mt = 0; mt < 2; mt++) {
#pragma unroll
        for (int nt = 0; nt < 4; nt++) {
            float* cc = acc[mt][nt];
            float p0 = __shfl_xor_sync(0xffffffffu, cc[0], 1);
            float p1 = __shfl_xor_sync(0xffffffffu, cc[1], 1);
            float p2 = __shfl_xor_sync(0xffffffffu, cc[2], 1);
            float p3 = __shfl_xor_sync(0xffffffffu, cc[3], 1);
            if (active) {
                int n0 = nBase + wn + nt * 8 + q * 2;     // multiple of 4
                int j = n0 >> 2;
                const float4 bs = *(const float4*)&g_bias[l * NG + n0];
                int r0 = mBase + wm + mt * 16 + (lane >> 2);
#pragma unroll
                for (int rg = 0; rg < 2; rg++) {
                    int row = r0 + rg * 8;
                    float gi = (rg ? cc[2] : cc[0]) + bs.x;
                    float gf = (rg ? cc[3] : cc[1]) + bs.y;
                    float gg = (rg ? p2 : p0) + bs.z;
                    float go = (rg ? p3 : p1) + bs.w;
                    size_t off = (size_t)row * HD_ + j;
                    float cold = cbase[off];
                    float cn = sigf(gf) * cold + sigf(gi) * tanhf(gg);
                    float hn = sigf(go) * tanhf(cn);
                    cbase[off] = cn;
                    __nv_bfloat16 hi = __float2bfloat16(hn);
                    hh[off] = hi;
                    hl[off] = __float2bfloat16(hn - __bfloat162float(hi));
                    if (ys) ys[off] = hn;
                }
            }
        }
    }
}

// ---------------- attention / TPA head --------------------------------------
#define HEAD_SMEM_FLOATS (32768 + 8064 + 4032 + 512 + 64 + 512 + 64 + 256)

__global__ __launch_bounds__(256)
void head_kernel(const float* __restrict__ conv_W, const float* __restrict__ conv_b,
                 const float* __restrict__ lin1_W, const float* __restrict__ lin1_b,
                 float* __restrict__ out) {
    extern __shared__ float sm[];
    float* conv_s  = sm;
    float* Hblk    = conv_s + 32768;
    float* kW_s    = Hblk + 8064;
    float* htt_s   = kW_s + 4032;
    float* w_s     = htt_s + 512;
    float* alpha_s = w_s + 64;
    float* v_s     = alpha_s + 512;
    float* red_s   = v_s + 64;

    const int b = blockIdx.x;
    const int tid = threadIdx.x;
    const int lane = tid & 31;
    const int warp = tid >> 5;

    for (int i = tid; i < FN_ * ATT; i += 256) kW_s[i] = conv_W[i];
    for (int i = tid; i < HD_; i += 256)
        htt_s[i] = g_ys[(size_t)(T_ - 1) * B_ * HD_ + (size_t)b * HD_ + i];
    __syncthreads();

    for (int qq = 0; qq < 8; qq++) {
        int qi = warp * 8 + qq;
        float p = 0.f;
        for (int k = lane; k < HD_; k += 32) p += htt_s[k] * lin1_W[(size_t)qi * HD_ + k];
#pragma unroll
        for (int o = 16; o; o >>= 1) p += __shfl_xor_sync(0xffffffffu, p, o);
        if (lane == 0) w_s[qi] = p + lin1_b[qi];
    }

    for (int fb = 0; fb < 4; fb++) {
        int f0 = fb * 128;
        for (int i = tid; i < ATT * 128; i += 256) {
            int tt = i >> 7, fi = i & 127;
            float v = g_ys[(size_t)tt * B_ * HD_ + (size_t)b * HD_ + f0 + fi];
            Hblk[i] = v > 0.f ? v : 0.f;
        }
        __syncthreads();
        int fi = tid & 127;
        int c0 = tid >> 7;
        for (int c = c0; c < FN_; c += 2) {
            float acc = conv_b[c];
            const float* kwr = &kW_s[c * ATT];
            for (int tt = 0; tt < ATT; tt++) acc += kwr[tt] * Hblk[tt * 128 + fi];
            conv_s[(c << 9) + f0 + fi] = acc > 0.f ? acc : 0.f;
        }
        __syncthreads();
    }

    for (int p = warp; p < 512; p += 8) {
        float a = conv_s[p * 64 + lane] * w_s[lane]
                + conv_s[p * 64 + 32 + lane] * w_s[32 + lane];
#pragma unroll
        for (int o = 16; o; o >>= 1) a += __shfl_xor_sync(0xffffffffu, a, o);
        if (lane == 0) alpha_s[p] = 1.f / (1.f + expf(-a));
    }
    __syncthreads();

    {
        int qn = tid & 63, part = tid >> 6;
        float a = 0.f;
        for (int p = part; p < 512; p += 4) a += alpha_s[p] * conv_s[p * 64 + qn];
        red_s[tid] = a;
    }
    __syncthreads();
    if (tid < 64) v_s[tid] = red_s[tid] + red_s[64 + tid] + red_s[128 + tid] + red_s[192 + tid];
    __syncthreads();

    float a = 0.f;
    for (int k = tid; k < HD_; k += 256) a += htt_s[k] * g_effw[k];
    if (tid < 64) a += v_s[tid] * g_effw[HD_ + tid];
#pragma unroll
    for (int o = 16; o; o >>= 1) a += __shfl_xor_sync(0xffffffffu, a, o);
    if (lane == 0) red_s[warp] = a;
    __syncthreads();
    if (tid == 0) {
        float tot = g_effw[576];
        for (int i = 0; i < 8; i++) tot += red_s[i];
        out[b] = tot;
    }
}

// ---------------- launch ----------------------------------------------------
extern "C" void kernel_launch(void* const* d_in, const int* in_sizes, int n_in,
                              void* d_out, int out_size) {
    const float* x      = (const float*)d_in[0];
    const float* W_ih   = (const float*)d_in[1];
    const float* W_hh   = (const float*)d_in[2];
    const float* b_ih   = (const float*)d_in[3];
    const float* b_hh   = (const float*)d_in[4];
    const float* conv_W = (const float*)d_in[5];
    const float* conv_b = (const float*)d_in[6];
    const float* lin1_W = (const float*)d_in[7];
    const float* lin1_b = (const float*)d_in[8];
    const float* lin2_W = (const float*)d_in[9];
    const float* lin2_b = (const float*)d_in[10];
    const float* out_W  = (const float*)d_in[11];
    const float* out_b  = (const float*)d_in[12];
    float* out = (float*)d_out;

    {   // prep (2 launches)
        size_t tw = (size_t)L_ * NG * KK;
        prep_w_kernel<<<(unsigned)((tw + 255) / 256), 256>>>(W_ih, W_hh, b_ih, b_hh);
        size_t tx = (size_t)T_ * B_ * D_;
        prep_misc_kernel<<<(unsigned)((tx + 255) / 256), 256>>>(x, lin2_W, lin2_b, out_W, out_b);
    }

    // wavefront recurrence over diagonals d = t + l
    cudaFuncSetAttribute(lstm_step_mma, cudaFuncAttributeMaxDynamicSharedMemorySize, DYN_SMEM);
    for (int d = 0; d < T_ + L_ - 1; d++) {
        int lmin = d - (T_ - 1); if (lmin < 0) lmin = 0;
        int lmax = (d < L_ - 1) ? d : (L_ - 1);
        dim3 grid(NG / 128, B_ / 128, lmax - lmin + 1);   // (16, 8, nc)
        lstm_step_mma<<<grid, NTHR, DYN_SMEM>>>(d, lmin);
    }

    // head
    cudaFuncSetAttribute(head_kernel, cudaFuncAttributeMaxDynamicSharedMemorySize,
                         HEAD_SMEM_FLOATS * (int)sizeof(float));
    head_kernel<<<B_, 256, HEAD_SMEM_FLOATS * (int)sizeof(float)>>>(
        conv_W, conv_b, lin1_W, lin1_b, out);
}

// round 10
// speedup vs baseline: 1.3080x; 1.1245x over previous
#include <cuda_runtime.h>
#include <cuda_bf16.h>
#include <math.h>
#include <stdint.h>

// ---------------- problem constants ----------------------------------------
#define B_ 1024
#define T_ 64
#define D_ 512
#define HD_ 512
#define L_ 3
#define NG 2048          // 4*HD gate columns (gate-interleaved)
#define KK 1024          // D + HD fused K
#define FN_ 64
#define ATT 63
#define NCELL (T_ * L_)          // 192
#define NITEM (NCELL * 128)      // 24576 tiles

// ---------------- device scratch -------------------------------------------
__device__ __align__(16) __nv_bfloat16 g_Whi[(size_t)L_ * NG * KK];   // [l][n][k]
__device__ __align__(16) __nv_bfloat16 g_Wlo[(size_t)L_ * NG * KK];
__device__ __align__(16) __nv_bfloat16 g_xhi[(size_t)T_ * B_ * D_];   // [t][b][d]
__device__ __align__(16) __nv_bfloat16 g_xlo[(size_t)T_ * B_ * D_];
// write-once hidden state: slot s = t+1 holds h(t,l); slot 0 = zeros
__device__ __align__(16) __nv_bfloat16 g_Hhi[(size_t)(T_ + 1) * L_ * B_ * HD_];
__device__ __align__(16) __nv_bfloat16 g_Hlo[(size_t)(T_ + 1) * L_ * B_ * HD_];
__device__ float g_c[(size_t)L_ * B_ * HD_];
__device__ __align__(16) float g_bias[L_ * NG];
__device__ float g_ys[(size_t)T_ * B_ * HD_];
__device__ float g_effw[577];
// dataflow scheduling state
__device__ int g_next;
__device__ int g_cnt[T_ * L_ * 8];     // [t][l][mBi] -> arrives 0..16
__device__ int g_cell_tl[NCELL];       // diagonal-major (t<<2)|l

// ---------------- small asm helpers ----------------------------------------
__device__ __forceinline__ uint32_t smem_u32(const void* p) {
    uint32_t a;
    asm("{ .reg .u64 t; cvta.to.shared.u64 t, %1; cvt.u32.u64 %0, t; }" : "=r"(a) : "l"(p));
    return a;
}
__device__ __forceinline__ void cp16(uint32_t dst, const void* src) {
    asm volatile("cp.async.cg.shared.global [%0], [%1], 16;" :: "r"(dst), "l"(src));
}
__device__ __forceinline__ void cp_mbar_arrive(uint32_t mbar) {
    asm volatile("cp.async.mbarrier.arrive.noinc.shared.b64 [%0];" :: "r"(mbar) : "memory");
}
#define MBARRIER_INIT(addr, cnt) \
    asm volatile("mbarrier.init.shared.b64 [%0], %1;" :: "r"((uint32_t)(addr)), "r"((uint32_t)(cnt)) : "memory")
#define MBARRIER_ARRIVE(addr) \
    asm volatile("mbarrier.arrive.shared.b64 _, [%0];" :: "r"((uint32_t)(addr)) : "memory")
#define MBARRIER_WAIT_PARITY(addr, par) do { \
    uint32_t _m = (uint32_t)(addr); uint32_t _p = (uint32_t)(par); uint32_t _d; \
    asm volatile("{ .reg .pred p; mbarrier.try_wait.parity.acquire.cta.shared::cta.b64 p, [%1], %2; selp.b32 %0,1,0,p; }" \
        : "=r"(_d) : "r"(_m), "r"(_p) : "memory"); \
    if (!_d) { \
        asm volatile("{ .reg .pred P1; WL%=: mbarrier.try_wait.parity.acquire.cta.shared::cta.b64 P1, [%0], %1, 0x989680; @P1 bra.uni WD%=; bra.uni WL%=; WD%=: }" \
            :: "r"(_m), "r"(_p) : "memory"); \
    } } while (0)

__device__ __forceinline__ int ld_acq(const int* p) {
    int v;
    asm volatile("ld.acquire.gpu.global.s32 %0, [%1];" : "=r"(v) : "l"(p) : "memory");
    return v;
}
__device__ __forceinline__ void red_rel_add1(int* p) {
    asm volatile("red.release.gpu.global.add.s32 [%0], %1;" :: "l"(p), "r"(1) : "memory");
}

__device__ __forceinline__ void ldsm4(uint32_t* r, uint32_t addr) {
    asm volatile("ldmatrix.sync.aligned.m8n8.x4.shared.b16 {%0,%1,%2,%3}, [%4];"
                 : "=r"(r[0]), "=r"(r[1]), "=r"(r[2]), "=r"(r[3]) : "r"(addr));
}
__device__ __forceinline__ void mma16816(float* c, const uint32_t* a, const uint32_t* b) {
    asm volatile("mma.sync.aligned.m16n8k16.row.col.f32.bf16.bf16.f32 "
                 "{%0,%1,%2,%3}, {%4,%5,%6,%7}, {%8,%9}, {%0,%1,%2,%3};"
                 : "+f"(c[0]), "+f"(c[1]), "+f"(c[2]), "+f"(c[3])
                 : "r"(a[0]), "r"(a[1]), "r"(a[2]), "r"(a[3]), "r"(b[0]), "r"(b[1]));
}
__device__ __forceinline__ float sigf(float x) { return 1.f / (1.f + expf(-x)); }

// ---------------- prep kernels ---------------------------------------------
__global__ void prep_w_kernel(const float* __restrict__ W_ih, const float* __restrict__ W_hh,
                              const float* __restrict__ b_ih, const float* __restrict__ b_hh) {
    size_t idx = (size_t)blockIdx.x * blockDim.x + threadIdx.x;
    const size_t total = (size_t)L_ * NG * KK;
    if (idx < total) {
        int l = (int)(idx / ((size_t)NG * KK));
        size_t r = idx % ((size_t)NG * KK);
        int n = (int)(r / KK), k = (int)(r % KK);
        int oc = (n & 3) * HD_ + (n >> 2);
        float v = (k < D_) ? W_ih[((size_t)l * NG + oc) * D_ + k]
                           : W_hh[((size_t)l * NG + oc) * HD_ + (k - D_)];
        __nv_bfloat16 hi = __float2bfloat16(v);
        g_Whi[idx] = hi;
        g_Wlo[idx] = __float2bfloat16(v - __bfloat162float(hi));
    }
    if (idx < (size_t)L_ * NG) {
        int l = (int)(idx / NG), n = (int)(idx % NG);
        int oc = (n & 3) * HD_ + (n >> 2);
        g_bias[idx] = b_ih[(size_t)l * NG + oc] + b_hh[(size_t)l * NG + oc];
    }
}

// merged: x split + h-slot0/c zero + scheduler reset + folded output vector
__global__ void prep_misc_kernel(const float* __restrict__ x,
                                 const float* __restrict__ lin2_W, const float* __restrict__ lin2_b,
                                 const float* __restrict__ out_W, const float* __restrict__ out_b) {
    size_t idx = (size_t)blockIdx.x * blockDim.x + threadIdx.x;
    const size_t totx = (size_t)T_ * B_ * D_;
    if (idx < totx) {
        int t = (int)(idx / ((size_t)B_ * D_));
        size_t r = idx % ((size_t)B_ * D_);
        int b = (int)(r / D_), d = (int)(r % D_);
        float v = x[((size_t)b * T_ + t) * D_ + d];
        __nv_bfloat16 hi = __float2bfloat16(v);
        g_xhi[idx] = hi;
        g_xlo[idx] = __float2bfloat16(v - __bfloat162float(hi));
    }
    const size_t slot0 = (size_t)L_ * B_ * HD_;
    if (idx < slot0) { g_Hhi[idx] = __float2bfloat16(0.f); g_Hlo[idx] = __float2bfloat16(0.f); g_c[idx] = 0.f; }
    if (idx < (size_t)(T_ * L_ * 8)) g_cnt[idx] = 0;
    if (idx == 0) {
        g_next = 0;
        int i = 0;
        for (int d = 0; d < T_ + L_ - 1; d++) {
            int lmin = d - (T_ - 1); if (lmin < 0) lmin = 0;
            int lmax = (d < L_ - 1) ? d : (L_ - 1);
            for (int l = lmin; l <= lmax; l++) g_cell_tl[i++] = ((d - l) << 2) | l;
        }
    }
    if (idx < 576) {
        float a = 0.f;
        for (int j = 0; j < HD_; j++) a += out_W[j] * lin2_W[(size_t)j * 576 + idx];
        g_effw[idx] = a;
    } else if (idx == 576) {
        float a = out_b[0];
        for (int j = 0; j < HD_; j++) a += out_W[j] * lin2_b[j];
        g_effw[576] = a;
    }
}

// ---------------- persistent dataflow LSTM ----------------------------------
// 148 persistent CTAs; work item = (cell, mB-tile, nB-tile); deps via
// release/acquire counters (row-block granularity). Mainloop per item is the
// proven 16-warp / 3-stage mbarrier-ring mma.sync pipeline.
#define KCH 64
#define NCH (KK / KCH)            // 16 chunks
#define ROWB 144
#define TILE_BYTES (128 * ROWB)   // 18432
#define AH_OFF 0
#define AL_OFF (TILE_BYTES)
#define BH_OFF (2 * TILE_BYTES)
#define BL_OFF (3 * TILE_BYTES)
#define STAGE_BYTES (4 * TILE_BYTES)   // 73728
#define NSTAGE 3
#define DYN_SMEM (NSTAGE * STAGE_BYTES)  // 221184 (1 CTA/SM)
#define NTHR 512
#define NPERS 148

__global__ __launch_bounds__(NTHR, 1)
void lstm_persist() {
    extern __shared__ __align__(128) char dynsm[];
    __shared__ __align__(8) unsigned long long s_full[NSTAGE], s_empty[NSTAGE];
    __shared__ int s_item;
    const uint32_t smb = smem_u32(dynsm);
    const uint32_t mb_full = smem_u32(s_full);
    const uint32_t mb_empty = smem_u32(s_empty);

    const int tid  = threadIdx.x;
    const int lane = tid & 31;
    const int wid  = tid >> 5;               // 0..15
    const int wm   = (wid & 3) * 32;
    const int wn   = (wid >> 2) * 32;

    const uint32_t a_off = (uint32_t)((wm + (lane & 15)) * ROWB + (lane >> 4) * 16);
    const uint32_t b_row = (uint32_t)(wn + (lane & 7) + ((lane >> 4) << 3));
    const uint32_t b_off = b_row * ROWB + (((lane >> 3) & 1) << 4);

    for (;;) {
        // ---- grab next item; init barriers; wait deps ----------------------
        if (tid == 0) s_item = atomicAdd(&g_next, 1);
        __syncthreads();
        const int item = s_item;
        if (item >= NITEM) break;

        const int cell = item >> 7;
        const int tl = g_cell_tl[cell];
        const int t = tl >> 2, l = tl & 3;
        const int tile = item & 127;
        const int mBi = tile & 7, nBi = tile >> 3;
        const int mBase = mBi * 128, nBase = nBi * 128;

        if (tid == 0) {
#pragma unroll
            for (int s = 0; s < NSTAGE; s++) {
                MBARRIER_INIT(mb_full + s * 8, NTHR);
                MBARRIER_INIT(mb_empty + s * 8, NTHR);
            }
            if (t > 0) {
                int* p = &g_cnt[((t - 1) * L_ + l) * 8 + mBi];
                while (ld_acq(p) < 16) __nanosleep(64);
            }
            if (l > 0) {
                int* p = &g_cnt[(t * L_ + (l - 1)) * 8 + mBi];
                while (ld_acq(p) < 16) __nanosleep(64);
            }
        }
        __syncthreads();

        // ---- operand bases --------------------------------------------------
        const __nv_bfloat16 *A0h, *A0l;
        if (l == 0) {
            size_t o = (size_t)t * B_ * D_;
            A0h = g_xhi + o; A0l = g_xlo + o;
        } else {
            size_t o = ((size_t)(t + 1) * L_ + (l - 1)) * B_ * HD_;   // h(t, l-1)
            A0h = g_Hhi + o; A0l = g_Hlo + o;
        }
        size_t o1 = ((size_t)t * L_ + l) * B_ * HD_;                  // h(t-1, l)
        const __nv_bfloat16 *A1h = g_Hhi + o1, *A1l = g_Hlo + o1;
        const __nv_bfloat16 *Wh = g_Whi + (size_t)l * NG * KK;
        const __nv_bfloat16 *Wl = g_Wlo + (size_t)l * NG * KK;

        auto load_chunk = [&](int c) {
            const int k0 = c * KCH;
            const __nv_bfloat16 *ah = (k0 < D_) ? A0h + k0 : A1h + (k0 - D_);
            const __nv_bfloat16 *al = (k0 < D_) ? A0l + k0 : A1l + (k0 - D_);
            const int s = c % NSTAGE;
            const uint32_t sb = smb + s * STAGE_BYTES;
            for (int i = tid; i < 1024; i += NTHR) {
                int row = i >> 3, ch = i & 7;
                uint32_t so = (uint32_t)(row * ROWB + ch * 16);
                size_t ga = (size_t)(mBase + row) * 512 + ch * 8;
                size_t gb = (size_t)(nBase + row) * (size_t)KK + k0 + ch * 8;
                cp16(sb + AH_OFF + so, ah + ga);
                cp16(sb + AL_OFF + so, al + ga);
                cp16(sb + BH_OFF + so, Wh + gb);
                cp16(sb + BL_OFF + so, Wl + gb);
            }
            cp_mbar_arrive(mb_full + s * 8);
        };

        float acc[2][4][4];
#pragma unroll
        for (int i = 0; i < 2; i++)
#pragma unroll
            for (int j = 0; j < 4; j++)
#pragma unroll
                for (int q = 0; q < 4; q++) acc[i][j][q] = 0.f;

        load_chunk(0);
        load_chunk(1);

        for (int c = 0; c < NCH; c++) {
            const int s = c % NSTAGE;
            const int k = c / NSTAGE;
            MBARRIER_WAIT_PARITY(mb_full + s * 8, k & 1);
            const uint32_t sb = smb + s * STAGE_BYTES;

#pragma unroll
            for (int kk = 0; kk < 4; kk++) {
                const uint32_t kofs = (uint32_t)(kk * 32);
                uint32_t a_hi[2][4], a_lo[2][4];
#pragma unroll
                for (int mt = 0; mt < 2; mt++) {
                    uint32_t ad = sb + a_off + (uint32_t)(mt * 16 * ROWB) + kofs;
                    ldsm4(a_hi[mt], ad + AH_OFF);
                    ldsm4(a_lo[mt], ad + AL_OFF);
                }
                uint32_t b_hi[4][2], b_lo[4][2];
#pragma unroll
                for (int g = 0; g < 2; g++) {
                    uint32_t bd = sb + b_off + (uint32_t)(g * 16 * ROWB) + kofs;
                    uint32_t r[4];
                    ldsm4(r, bd + BH_OFF);
                    b_hi[2 * g][0] = r[0]; b_hi[2 * g][1] = r[1];
                    b_hi[2 * g + 1][0] = r[2]; b_hi[2 * g + 1][1] = r[3];
                    ldsm4(r, bd + BL_OFF);
                    b_lo[2 * g][0] = r[0]; b_lo[2 * g][1] = r[1];
                    b_lo[2 * g + 1][0] = r[2]; b_lo[2 * g + 1][1] = r[3];
                }
#pragma unroll
                for (int mt = 0; mt < 2; mt++)
#pragma unroll
                    for (int nt = 0; nt < 4; nt++) mma16816(acc[mt][nt], a_hi[mt], b_hi[nt]);
#pragma unroll
                for (int mt = 0; mt < 2; mt++)
#pragma unroll
                    for (int nt = 0; nt < 4; nt++) mma16816(acc[mt][nt], a_lo[mt], b_hi[nt]);
#pragma unroll
                for (int mt = 0; mt < 2; mt++)
#pragma unroll
                    for (int nt = 0; nt < 4; nt++) mma16816(acc[mt][nt], a_hi[mt], b_lo[nt]);
            }
            MBARRIER_ARRIVE(mb_empty + s * 8);

            const int c2 = c + 2;
            if (c2 < NCH) {
                const int s2 = c2 % NSTAGE;
                const int k2 = c2 / NSTAGE;
                if (k2 >= 1) MBARRIER_WAIT_PARITY(mb_empty + s2 * 8, (k2 - 1) & 1);
                load_chunk(c2);
            }
        }

        // ---- fused LSTM-cell epilogue ---------------------------------------
        {
            const int q = lane & 3;
            const bool active = (q & 1) == 0;
            float* cbase = g_c + (size_t)l * B_ * HD_;
            __nv_bfloat16* hh = g_Hhi + ((size_t)(t + 1) * L_ + l) * B_ * HD_;
            __nv_bfloat16* hl = g_Hlo + ((size_t)(t + 1) * L_ + l) * B_ * HD_;
            float* ys = (l == 2) ? (g_ys + (size_t)t * B_ * HD_) : nullptr;

#pragma unroll
            for (int mt = 0; mt < 2; mt++) {
#pragma unroll
                for (int nt = 0; nt < 4; nt++) {
                    float* cc = acc[mt][nt];
                    float p0 = __shfl_xor_sync(0xffffffffu, cc[0], 1);
                    float p1 = __shfl_xor_sync(0xffffffffu, cc[1], 1);
                    float p2 = __shfl_xor_sync(0xffffffffu, cc[2], 1);
                    float p3 = __shfl_xor_sync(0xffffffffu, cc[3], 1);
                    if (active) {
                        int n0 = nBase + wn + nt * 8 + q * 2;
                        int j = n0 >> 2;
                        const float4 bs = *(const float4*)&g_bias[l * NG + n0];
                        int r0 = mBase + wm + mt * 16 + (lane >> 2);
#pragma unroll
                        for (int rg = 0; rg < 2; rg++) {
                            int row = r0 + rg * 8;
                            float gi = (rg ? cc[2] : cc[0]) + bs.x;
                            float gf = (rg ? cc[3] : cc[1]) + bs.y;
                            float gg = (rg ? p2 : p0) + bs.z;
                            float go = (rg ? p3 : p1) + bs.w;
                            size_t off = (size_t)row * HD_ + j;
                            float cold = cbase[off];
                            float cn = sigf(gf) * cold + sigf(gi) * tanhf(gg);
                            float hn = sigf(go) * tanhf(cn);
                            cbase[off] = cn;
                            __nv_bfloat16 hi = __float2bfloat16(hn);
                            hh[off] = hi;
                            hl[off] = __float2bfloat16(hn - __bfloat162float(hi));
                            if (ys) ys[off] = hn;
                        }
                    }
                }
            }
        }

        // publish: all threads' stores -> cta barrier -> release increment
        __threadfence();
        __syncthreads();
        if (tid == 0) red_rel_add1(&g_cnt[(t * L_ + l) * 8 + mBi]);
    }
}

// ---------------- attention / TPA head --------------------------------------
#define HEAD_SMEM_FLOATS (32768 + 8064 + 4032 + 512 + 64 + 512 + 64 + 256)

__global__ __launch_bounds__(256)
void head_kernel(const float* __restrict__ conv_W, const float* __restrict__ conv_b,
                 const float* __restrict__ lin1_W, const float* __restrict__ lin1_b,
                 float* __restrict__ out) {
    extern __shared__ float sm[];
    float* conv_s  = sm;
    float* Hblk    = conv_s + 32768;
    float* kW_s    = Hblk + 8064;
    float* htt_s   = kW_s + 4032;
    float* w_s     = htt_s + 512;
    float* alpha_s = w_s + 64;
    float* v_s     = alpha_s + 512;
    float* red_s   = v_s + 64;

    const int b = blockIdx.x;
    const int tid = threadIdx.x;
    const int lane = tid & 31;
    const int warp = tid >> 5;

    for (int i = tid; i < FN_ * ATT; i += 256) kW_s[i] = conv_W[i];
    for (int i = tid; i < HD_; i += 256)
        htt_s[i] = g_ys[(size_t)(T_ - 1) * B_ * HD_ + (size_t)b * HD_ + i];
    __syncthreads();

    for (int qq = 0; qq < 8; qq++) {
        int qi = warp * 8 + qq;
        float p = 0.f;
        for (int k = lane; k < HD_; k += 32) p += htt_s[k] * lin1_W[(size_t)qi * HD_ + k];
#pragma unroll
        for (int o = 16; o; o >>= 1) p += __shfl_xor_sync(0xffffffffu, p, o);
        if (lane == 0) w_s[qi] = p + lin1_b[qi];
    }

    for (int fb = 0; fb < 4; fb++) {
        int f0 = fb * 128;
        for (int i = tid; i < ATT * 128; i += 256) {
            int tt = i >> 7, fi = i & 127;
            float v = g_ys[(size_t)tt * B_ * HD_ + (size_t)b * HD_ + f0 + fi];
            Hblk[i] = v > 0.f ? v : 0.f;
        }
        __syncthreads();
        int fi = tid & 127;
        int c0 = tid >> 7;
        for (int c = c0; c < FN_; c += 2) {
            float acc = conv_b[c];
            const float* kwr = &kW_s[c * ATT];
            for (int tt = 0; tt < ATT; tt++) acc += kwr[tt] * Hblk[tt * 128 + fi];
            conv_s[(c << 9) + f0 + fi] = acc > 0.f ? acc : 0.f;
        }
        __syncthreads();
    }

    for (int p = warp; p < 512; p += 8) {
        float a = conv_s[p * 64 + lane] * w_s[lane]
                + conv_s[p * 64 + 32 + lane] * w_s[32 + lane];
#pragma unroll
        for (int o = 16; o; o >>= 1) a += __shfl_xor_sync(0xffffffffu, a, o);
        if (lane == 0) alpha_s[p] = 1.f / (1.f + expf(-a));
    }
    __syncthreads();

    {
        int qn = tid & 63, part = tid >> 6;
        float a = 0.f;
        for (int p = part; p < 512; p += 4) a += alpha_s[p] * conv_s[p * 64 + qn];
        red_s[tid] = a;
    }
    __syncthreads();
    if (tid < 64) v_s[tid] = red_s[tid] + red_s[64 + tid] + red_s[128 + tid] + red_s[192 + tid];
    __syncthreads();

    float a = 0.f;
    for (int k = tid; k < HD_; k += 256) a += htt_s[k] * g_effw[k];
    if (tid < 64) a += v_s[tid] * g_effw[HD_ + tid];
#pragma unroll
    for (int o = 16; o; o >>= 1) a += __shfl_xor_sync(0xffffffffu, a, o);
    if (lane == 0) red_s[warp] = a;
    __syncthreads();
    if (tid == 0) {
        float tot = g_effw[576];
        for (int i = 0; i < 8; i++) tot += red_s[i];
        out[b] = tot;
    }
}

// ---------------- launch ----------------------------------------------------
extern "C" void kernel_launch(void* const* d_in, const int* in_sizes, int n_in,
                              void* d_out, int out_size) {
    const float* x      = (const float*)d_in[0];
    const float* W_ih   = (const float*)d_in[1];
    const float* W_hh   = (const float*)d_in[2];
    const float* b_ih   = (const float*)d_in[3];
    const float* b_hh   = (const float*)d_in[4];
    const float* conv_W = (const float*)d_in[5];
    const float* conv_b = (const float*)d_in[6];
    const float* lin1_W = (const float*)d_in[7];
    const float* lin1_b = (const float*)d_in[8];
    const float* lin2_W = (const float*)d_in[9];
    const float* lin2_b = (const float*)d_in[10];
    const float* out_W  = (const float*)d_in[11];
    const float* out_b  = (const float*)d_in[12];
    float* out = (float*)d_out;

    {   // prep (2 launches)
        size_t tw = (size_t)L_ * NG * KK;
        prep_w_kernel<<<(unsigned)((tw + 255) / 256), 256>>>(W_ih, W_hh, b_ih, b_hh);
        size_t tx = (size_t)T_ * B_ * D_;
        prep_misc_kernel<<<(unsigned)((tx + 255) / 256), 256>>>(x, lin2_W, lin2_b, out_W, out_b);
    }

    // persistent dataflow wavefront (single launch for all 192 cells)
    cudaFuncSetAttribute(lstm_persist, cudaFuncAttributeMaxDynamicSharedMemorySize, DYN_SMEM);
    lstm_persist<<<NPERS, NTHR, DYN_SMEM>>>();

    // head
    cudaFuncSetAttribute(head_kernel, cudaFuncAttributeMaxDynamicSharedMemorySize,
                         HEAD_SMEM_FLOATS * (int)sizeof(float));
    head_kernel<<<B_, 256, HEAD_SMEM_FLOATS * (int)sizeof(float)>>>(
        conv_W, conv_b, lin1_W, lin1_b, out);
}

// round 11
// speedup vs baseline: 1.3884x; 1.0615x over previous
#include <cuda_runtime.h>
#include <cuda_bf16.h>
#include <math.h>
#include <stdint.h>

// ---------------- problem constants ----------------------------------------
#define B_ 1024
#define T_ 64
#define D_ 512
#define HD_ 512
#define L_ 3
#define NG 2048          // 4*HD gate columns (gate-interleaved)
#define KK 1024          // D + HD fused K
#define FN_ 64
#define ATT 63
#define NCELL (T_ * L_)          // 192
#define NITEM (NCELL * 128)      // 24576 tiles

// ---------------- device scratch -------------------------------------------
__device__ __align__(16) __nv_bfloat16 g_Whi[(size_t)L_ * NG * KK];   // [l][n][k]
__device__ __align__(16) __nv_bfloat16 g_Wlo[(size_t)L_ * NG * KK];
__device__ __align__(16) __nv_bfloat16 g_xhi[(size_t)T_ * B_ * D_];   // [t][b][d]
__device__ __align__(16) __nv_bfloat16 g_xlo[(size_t)T_ * B_ * D_];
// write-once hidden state: slot s = t+1 holds h(t,l); slot 0 = zeros
__device__ __align__(16) __nv_bfloat16 g_Hhi[(size_t)(T_ + 1) * L_ * B_ * HD_];
__device__ __align__(16) __nv_bfloat16 g_Hlo[(size_t)(T_ + 1) * L_ * B_ * HD_];
__device__ float g_c[(size_t)L_ * B_ * HD_];
__device__ __align__(16) float g_bias[L_ * NG];
__device__ __align__(16) float g_ys[(size_t)T_ * B_ * HD_];
__device__ float g_effw[577];
// dataflow scheduling state
__device__ int g_next;
__device__ int g_cnt[T_ * L_ * 8];     // [t][l][mBi] -> arrives 0..16
__device__ int g_cell_tl[NCELL];       // diagonal-major (t<<2)|l

// ---------------- small asm helpers ----------------------------------------
__device__ __forceinline__ uint32_t smem_u32(const void* p) {
    uint32_t a;
    asm("{ .reg .u64 t; cvta.to.shared.u64 t, %1; cvt.u32.u64 %0, t; }" : "=r"(a) : "l"(p));
    return a;
}
__device__ __forceinline__ void cp16(uint32_t dst, const void* src) {
    asm volatile("cp.async.cg.shared.global [%0], [%1], 16;" :: "r"(dst), "l"(src));
}
__device__ __forceinline__ void cp_mbar_arrive(uint32_t mbar) {
    asm volatile("cp.async.mbarrier.arrive.noinc.shared.b64 [%0];" :: "r"(mbar) : "memory");
}
#define MBARRIER_INIT(addr, cnt) \
    asm volatile("mbarrier.init.shared.b64 [%0], %1;" :: "r"((uint32_t)(addr)), "r"((uint32_t)(cnt)) : "memory")
#define MBARRIER_ARRIVE(addr) \
    asm volatile("mbarrier.arrive.shared.b64 _, [%0];" :: "r"((uint32_t)(addr)) : "memory")
#define MBARRIER_WAIT_PARITY(addr, par) do { \
    uint32_t _m = (uint32_t)(addr); uint32_t _p = (uint32_t)(par); uint32_t _d; \
    asm volatile("{ .reg .pred p; mbarrier.try_wait.parity.acquire.cta.shared::cta.b64 p, [%1], %2; selp.b32 %0,1,0,p; }" \
        : "=r"(_d) : "r"(_m), "r"(_p) : "memory"); \
    if (!_d) { \
        asm volatile("{ .reg .pred P1; WL%=: mbarrier.try_wait.parity.acquire.cta.shared::cta.b64 P1, [%0], %1, 0x989680; @P1 bra.uni WD%=; bra.uni WL%=; WD%=: }" \
            :: "r"(_m), "r"(_p) : "memory"); \
    } } while (0)

__device__ __forceinline__ int ld_acq(const int* p) {
    int v;
    asm volatile("ld.acquire.gpu.global.s32 %0, [%1];" : "=r"(v) : "l"(p) : "memory");
    return v;
}
__device__ __forceinline__ void red_rel_add1(int* p) {
    asm volatile("red.release.gpu.global.add.s32 [%0], %1;" :: "l"(p), "r"(1) : "memory");
}

__device__ __forceinline__ void ldsm4(uint32_t* r, uint32_t addr) {
    asm volatile("ldmatrix.sync.aligned.m8n8.x4.shared.b16 {%0,%1,%2,%3}, [%4];"
                 : "=r"(r[0]), "=r"(r[1]), "=r"(r[2]), "=r"(r[3]) : "r"(addr));
}
__device__ __forceinline__ void mma16816(float* c, const uint32_t* a, const uint32_t* b) {
    asm volatile("mma.sync.aligned.m16n8k16.row.col.f32.bf16.bf16.f32 "
                 "{%0,%1,%2,%3}, {%4,%5,%6,%7}, {%8,%9}, {%0,%1,%2,%3};"
                 : "+f"(c[0]), "+f"(c[1]), "+f"(c[2]), "+f"(c[3])
                 : "r"(a[0]), "r"(a[1]), "r"(a[2]), "r"(a[3]), "r"(b[0]), "r"(b[1]));
}
__device__ __forceinline__ float sigf(float x) { return 1.f / (1.f + expf(-x)); }

// ---------------- prep kernels ---------------------------------------------
__global__ void prep_w_kernel(const float* __restrict__ W_ih, const float* __restrict__ W_hh,
                              const float* __restrict__ b_ih, const float* __restrict__ b_hh) {
    size_t idx = (size_t)blockIdx.x * blockDim.x + threadIdx.x;
    const size_t total = (size_t)L_ * NG * KK;
    if (idx < total) {
        int l = (int)(idx / ((size_t)NG * KK));
        size_t r = idx % ((size_t)NG * KK);
        int n = (int)(r / KK), k = (int)(r % KK);
        int oc = (n & 3) * HD_ + (n >> 2);
        float v = (k < D_) ? W_ih[((size_t)l * NG + oc) * D_ + k]
                           : W_hh[((size_t)l * NG + oc) * HD_ + (k - D_)];
        __nv_bfloat16 hi = __float2bfloat16(v);
        g_Whi[idx] = hi;
        g_Wlo[idx] = __float2bfloat16(v - __bfloat162float(hi));
    }
    if (idx < (size_t)L_ * NG) {
        int l = (int)(idx / NG), n = (int)(idx % NG);
        int oc = (n & 3) * HD_ + (n >> 2);
        g_bias[idx] = b_ih[(size_t)l * NG + oc] + b_hh[(size_t)l * NG + oc];
    }
}

// merged: x split + h-slot0/c zero + scheduler reset + folded output vector
__global__ void prep_misc_kernel(const float* __restrict__ x,
                                 const float* __restrict__ lin2_W, const float* __restrict__ lin2_b,
                                 const float* __restrict__ out_W, const float* __restrict__ out_b) {
    size_t idx = (size_t)blockIdx.x * blockDim.x + threadIdx.x;
    const size_t totx = (size_t)T_ * B_ * D_;
    if (idx < totx) {
        int t = (int)(idx / ((size_t)B_ * D_));
        size_t r = idx % ((size_t)B_ * D_);
        int b = (int)(r / D_), d = (int)(r % D_);
        float v = x[((size_t)b * T_ + t) * D_ + d];
        __nv_bfloat16 hi = __float2bfloat16(v);
        g_xhi[idx] = hi;
        g_xlo[idx] = __float2bfloat16(v - __bfloat162float(hi));
    }
    const size_t slot0 = (size_t)L_ * B_ * HD_;
    if (idx < slot0) { g_Hhi[idx] = __float2bfloat16(0.f); g_Hlo[idx] = __float2bfloat16(0.f); g_c[idx] = 0.f; }
    if (idx < (size_t)(T_ * L_ * 8)) g_cnt[idx] = 0;
    if (idx == 0) {
        g_next = 0;
        int i = 0;
        for (int d = 0; d < T_ + L_ - 1; d++) {
            int lmin = d - (T_ - 1); if (lmin < 0) lmin = 0;
            int lmax = (d < L_ - 1) ? d : (L_ - 1);
            for (int l = lmin; l <= lmax; l++) g_cell_tl[i++] = ((d - l) << 2) | l;
        }
    }
    if (idx < 576) {
        float a = 0.f;
        for (int j = 0; j < HD_; j++) a += out_W[j] * lin2_W[(size_t)j * 576 + idx];
        g_effw[idx] = a;
    } else if (idx == 576) {
        float a = out_b[0];
        for (int j = 0; j < HD_; j++) a += out_W[j] * lin2_b[j];
        g_effw[576] = a;
    }
}

// ---------------- persistent dataflow LSTM ----------------------------------
// 148 persistent CTAs; work item = (cell, mB-tile, nB-tile); deps via
// release/acquire counters (row-block granularity). Mainloop per item is the
// proven 16-warp / 3-stage mbarrier-ring mma.sync pipeline.
#define KCH 64
#define NCH (KK / KCH)            // 16 chunks
#define ROWB 144
#define TILE_BYTES (128 * ROWB)   // 18432
#define AH_OFF 0
#define AL_OFF (TILE_BYTES)
#define BH_OFF (2 * TILE_BYTES)
#define BL_OFF (3 * TILE_BYTES)
#define STAGE_BYTES (4 * TILE_BYTES)   // 73728
#define NSTAGE 3
#define DYN_SMEM (NSTAGE * STAGE_BYTES)  // 221184 (1 CTA/SM)
#define NTHR 512
#define NPERS 148

__global__ __launch_bounds__(NTHR, 1)
void lstm_persist() {
    extern __shared__ __align__(128) char dynsm[];
    __shared__ __align__(8) unsigned long long s_full[NSTAGE], s_empty[NSTAGE];
    __shared__ int s_item;
    const uint32_t smb = smem_u32(dynsm);
    const uint32_t mb_full = smem_u32(s_full);
    const uint32_t mb_empty = smem_u32(s_empty);

    const int tid  = threadIdx.x;
    const int lane = tid & 31;
    const int wid  = tid >> 5;               // 0..15
    const int wm   = (wid & 3) * 32;
    const int wn   = (wid >> 2) * 32;

    const uint32_t a_off = (uint32_t)((wm + (lane & 15)) * ROWB + (lane >> 4) * 16);
    const uint32_t b_row = (uint32_t)(wn + (lane & 7) + ((lane >> 4) << 3));
    const uint32_t b_off = b_row * ROWB + (((lane >> 3) & 1) << 4);

    for (;;) {
        // ---- grab next item; init barriers; wait deps ----------------------
        if (tid == 0) s_item = atomicAdd(&g_next, 1);
        __syncthreads();
        const int item = s_item;
        if (item >= NITEM) break;

        const int cell = item >> 7;
        const int tl = g_cell_tl[cell];
        const int t = tl >> 2, l = tl & 3;
        const int tile = item & 127;
        const int mBi = tile & 7, nBi = tile >> 3;
        const int mBase = mBi * 128, nBase = nBi * 128;

        if (tid == 0) {
#pragma unroll
            for (int s = 0; s < NSTAGE; s++) {
                MBARRIER_INIT(mb_full + s * 8, NTHR);
                MBARRIER_INIT(mb_empty + s * 8, NTHR);
            }
            if (t > 0) {
                int* p = &g_cnt[((t - 1) * L_ + l) * 8 + mBi];
                while (ld_acq(p) < 16) __nanosleep(64);
            }
            if (l > 0) {
                int* p = &g_cnt[(t * L_ + (l - 1)) * 8 + mBi];
                while (ld_acq(p) < 16) __nanosleep(64);
            }
        }
        __syncthreads();

        // ---- operand bases --------------------------------------------------
        const __nv_bfloat16 *A0h, *A0l;
        if (l == 0) {
            size_t o = (size_t)t * B_ * D_;
            A0h = g_xhi + o; A0l = g_xlo + o;
        } else {
            size_t o = ((size_t)(t + 1) * L_ + (l - 1)) * B_ * HD_;   // h(t, l-1)
            A0h = g_Hhi + o; A0l = g_Hlo + o;
        }
        size_t o1 = ((size_t)t * L_ + l) * B_ * HD_;                  // h(t-1, l)
        const __nv_bfloat16 *A1h = g_Hhi + o1, *A1l = g_Hlo + o1;
        const __nv_bfloat16 *Wh = g_Whi + (size_t)l * NG * KK;
        const __nv_bfloat16 *Wl = g_Wlo + (size_t)l * NG * KK;

        auto load_chunk = [&](int c) {
            const int k0 = c * KCH;
            const __nv_bfloat16 *ah = (k0 < D_) ? A0h + k0 : A1h + (k0 - D_);
            const __nv_bfloat16 *al = (k0 < D_) ? A0l + k0 : A1l + (k0 - D_);
            const int s = c % NSTAGE;
            const uint32_t sb = smb + s * STAGE_BYTES;
            for (int i = tid; i < 1024; i += NTHR) {
                int row = i >> 3, ch = i & 7;
                uint32_t so = (uint32_t)(row * ROWB + ch * 16);
                size_t ga = (size_t)(mBase + row) * 512 + ch * 8;
                size_t gb = (size_t)(nBase + row) * (size_t)KK + k0 + ch * 8;
                cp16(sb + AH_OFF + so, ah + ga);
                cp16(sb + AL_OFF + so, al + ga);
                cp16(sb + BH_OFF + so, Wh + gb);
                cp16(sb + BL_OFF + so, Wl + gb);
            }
            cp_mbar_arrive(mb_full + s * 8);
        };

        float acc[2][4][4];
#pragma unroll
        for (int i = 0; i < 2; i++)
#pragma unroll
            for (int j = 0; j < 4; j++)
#pragma unroll
                for (int q = 0; q < 4; q++) acc[i][j][q] = 0.f;

        load_chunk(0);
        load_chunk(1);

        for (int c = 0; c < NCH; c++) {
            const int s = c % NSTAGE;
            const int k = c / NSTAGE;
            MBARRIER_WAIT_PARITY(mb_full + s * 8, k & 1);
            const uint32_t sb = smb + s * STAGE_BYTES;

#pragma unroll
            for (int kk = 0; kk < 4; kk++) {
                const uint32_t kofs = (uint32_t)(kk * 32);
                uint32_t a_hi[2][4], a_lo[2][4];
#pragma unroll
                for (int mt = 0; mt < 2; mt++) {
                    uint32_t ad = sb + a_off + (uint32_t)(mt * 16 * ROWB) + kofs;
                    ldsm4(a_hi[mt], ad + AH_OFF);
                    ldsm4(a_lo[mt], ad + AL_OFF);
                }
                uint32_t b_hi[4][2], b_lo[4][2];
#pragma unroll
                for (int g = 0; g < 2; g++) {
                    uint32_t bd = sb + b_off + (uint32_t)(g * 16 * ROWB) + kofs;
                    uint32_t r[4];
                    ldsm4(r, bd + BH_OFF);
                    b_hi[2 * g][0] = r[0]; b_hi[2 * g][1] = r[1];
                    b_hi[2 * g + 1][0] = r[2]; b_hi[2 * g + 1][1] = r[3];
                    ldsm4(r, bd + BL_OFF);
                    b_lo[2 * g][0] = r[0]; b_lo[2 * g][1] = r[1];
                    b_lo[2 * g + 1][0] = r[2]; b_lo[2 * g + 1][1] = r[3];
                }
#pragma unroll
                for (int mt = 0; mt < 2; mt++)
#pragma unroll
                    for (int nt = 0; nt < 4; nt++) mma16816(acc[mt][nt], a_hi[mt], b_hi[nt]);
#pragma unroll
                for (int mt = 0; mt < 2; mt++)
#pragma unroll
                    for (int nt = 0; nt < 4; nt++) mma16816(acc[mt][nt], a_lo[mt], b_hi[nt]);
#pragma unroll
                for (int mt = 0; mt < 2; mt++)
#pragma unroll
                    for (int nt = 0; nt < 4; nt++) mma16816(acc[mt][nt], a_hi[mt], b_lo[nt]);
            }
            MBARRIER_ARRIVE(mb_empty + s * 8);

            const int c2 = c + 2;
            if (c2 < NCH) {
                const int s2 = c2 % NSTAGE;
                const int k2 = c2 / NSTAGE;
                if (k2 >= 1) MBARRIER_WAIT_PARITY(mb_empty + s2 * 8, (k2 - 1) & 1);
                load_chunk(c2);
            }
        }

        // ---- fused LSTM-cell epilogue ---------------------------------------
        {
            const int q = lane & 3;
            const bool active = (q & 1) == 0;
            float* cbase = g_c + (size_t)l * B_ * HD_;
            __nv_bfloat16* hh = g_Hhi + ((size_t)(t + 1) * L_ + l) * B_ * HD_;
            __nv_bfloat16* hl = g_Hlo + ((size_t)(t + 1) * L_ + l) * B_ * HD_;
            float* ys = (l == 2) ? (g_ys + (size_t)t * B_ * HD_) : nullptr;

#pragma unroll
            for (int mt = 0; mt < 2; mt++) {
#pragma unroll
                for (int nt = 0; nt < 4; nt++) {
                    float* cc = acc[mt][nt];
                    float p0 = __shfl_xor_sync(0xffffffffu, cc[0], 1);
                    float p1 = __shfl_xor_sync(0xffffffffu, cc[1], 1);
                    float p2 = __shfl_xor_sync(0xffffffffu, cc[2], 1);
                    float p3 = __shfl_xor_sync(0xffffffffu, cc[3], 1);
                    if (active) {
                        int n0 = nBase + wn + nt * 8 + q * 2;
                        int j = n0 >> 2;
                        const float4 bs = *(const float4*)&g_bias[l * NG + n0];
                        int r0 = mBase + wm + mt * 16 + (lane >> 2);
#pragma unroll
                        for (int rg = 0; rg < 2; rg++) {
                            int row = r0 + rg * 8;
                            float gi = (rg ? cc[2] : cc[0]) + bs.x;
                            float gf = (rg ? cc[3] : cc[1]) + bs.y;
                            float gg = (rg ? p2 : p0) + bs.z;
                            float go = (rg ? p3 : p1) + bs.w;
                            size_t off = (size_t)row * HD_ + j;
                            float cold = cbase[off];
                            float cn = sigf(gf) * cold + sigf(gi) * tanhf(gg);
                            float hn = sigf(go) * tanhf(cn);
                            cbase[off] = cn;
                            __nv_bfloat16 hi = __float2bfloat16(hn);
                            hh[off] = hi;
                            hl[off] = __float2bfloat16(hn - __bfloat162float(hi));
                            if (ys) ys[off] = hn;
                        }
                    }
                }
            }
        }

        // publish: all threads' stores -> cta barrier -> release increment
        __threadfence();
        __syncthreads();
        if (tid == 0) red_rel_add1(&g_cnt[(t * L_ + l) * 8 + mBi]);
    }
}

// ---------------- attention / TPA head --------------------------------------
// conv phase register-blocked: thread = (float4 of features) x (8 channels),
// 1 LDS128 + 8 broadcast LDS per tap instead of 2 scalar LDS per (c,t).
#define HEAD_SMEM_FLOATS (32768 + 8064 + 4032 + 512 + 64 + 512 + 64 + 256)

__global__ __launch_bounds__(256)
void head_kernel(const float* __restrict__ conv_W, const float* __restrict__ conv_b,
                 const float* __restrict__ lin1_W, const float* __restrict__ lin1_b,
                 float* __restrict__ out) {
    extern __shared__ float sm[];
    float* conv_s  = sm;                 // [64][512] flat c*512+f
    float* Hblk    = conv_s + 32768;     // [63][128] as float4[63][32]
    float* kW_s    = Hblk + 8064;        // [64][63]
    float* htt_s   = kW_s + 4032;
    float* w_s     = htt_s + 512;
    float* alpha_s = w_s + 64;
    float* v_s     = alpha_s + 512;
    float* red_s   = v_s + 64;

    const int b = blockIdx.x;
    const int tid = threadIdx.x;
    const int lane = tid & 31;
    const int warp = tid >> 5;

    for (int i = tid; i < FN_ * ATT; i += 256) kW_s[i] = conv_W[i];
    for (int i = tid; i < HD_; i += 256)
        htt_s[i] = g_ys[(size_t)(T_ - 1) * B_ * HD_ + (size_t)b * HD_ + i];
    __syncthreads();

    // w = htt @ lin1_W^T + lin1_b
    for (int qq = 0; qq < 8; qq++) {
        int qi = warp * 8 + qq;
        float p = 0.f;
        for (int k = lane; k < HD_; k += 32) p += htt_s[k] * lin1_W[(size_t)qi * HD_ + k];
#pragma unroll
        for (int o = 16; o; o >>= 1) p += __shfl_xor_sync(0xffffffffu, p, o);
        if (lane == 0) w_s[qi] = p + lin1_b[qi];
    }

    // conv: register-blocked GEMM. 4 feature blocks of 128.
    float4* Hblk4 = (float4*)Hblk;
    float4* conv_s4 = (float4*)conv_s;
    const int fi4 = tid & 31;           // float4 index within 128-f block
    const int cgrp = tid >> 5;          // 0..7; channels c = cgrp + 8*k
    for (int fb = 0; fb < 4; fb++) {
        int f0 = fb * 128;
        // fill Hblk (relu'd) with float4 global loads
        for (int i = tid; i < ATT * 32; i += 256) {
            int tt = i >> 5, f4 = i & 31;
            float4 v = *(const float4*)&g_ys[(size_t)tt * B_ * HD_ + (size_t)b * HD_ + f0 + f4 * 4];
            v.x = fmaxf(v.x, 0.f); v.y = fmaxf(v.y, 0.f);
            v.z = fmaxf(v.z, 0.f); v.w = fmaxf(v.w, 0.f);
            Hblk4[i] = v;
        }
        __syncthreads();

        float4 acc[8];
#pragma unroll
        for (int k = 0; k < 8; k++) {
            float bb = conv_b[cgrp + 8 * k];
            acc[k] = make_float4(bb, bb, bb, bb);
        }
        for (int t = 0; t < ATT; t++) {
            float4 h = Hblk4[t * 32 + fi4];
#pragma unroll
            for (int k = 0; k < 8; k++) {
                float w = kW_s[(cgrp + 8 * k) * ATT + t];   // warp-uniform -> broadcast
                acc[k].x += w * h.x; acc[k].y += w * h.y;
                acc[k].z += w * h.z; acc[k].w += w * h.w;
            }
        }
#pragma unroll
        for (int k = 0; k < 8; k++) {
            int c = cgrp + 8 * k;
            float4 v = acc[k];
            v.x = fmaxf(v.x, 0.f); v.y = fmaxf(v.y, 0.f);
            v.z = fmaxf(v.z, 0.f); v.w = fmaxf(v.w, 0.f);
            conv_s4[(c << 7) + (f0 >> 2) + fi4] = v;        // conv_s[c*512 + f0 + fi4*4]
        }
        __syncthreads();
    }

    // alpha[p] = sigmoid( sum_q conv_flat[p*64+q]*w[q] )
    for (int p = warp; p < 512; p += 8) {
        float a = conv_s[p * 64 + lane] * w_s[lane]
                + conv_s[p * 64 + 32 + lane] * w_s[32 + lane];
#pragma unroll
        for (int o = 16; o; o >>= 1) a += __shfl_xor_sync(0xffffffffu, a, o);
        if (lane == 0) alpha_s[p] = 1.f / (1.f + expf(-a));
    }
    __syncthreads();

    // v[q] = sum_p alpha[p]*conv_flat[p*64+q]
    {
        int qn = tid & 63, part = tid >> 6;
        float a = 0.f;
        for (int p = part; p < 512; p += 4) a += alpha_s[p] * conv_s[p * 64 + qn];
        red_s[tid] = a;
    }
    __syncthreads();
    if (tid < 64) v_s[tid] = red_s[tid] + red_s[64 + tid] + red_s[128 + tid] + red_s[192 + tid];
    __syncthreads();

    // ypred[b] = dot([htt, v], effw) + effb
    float a = 0.f;
    for (int k = tid; k < HD_; k += 256) a += htt_s[k] * g_effw[k];
    if (tid < 64) a += v_s[tid] * g_effw[HD_ + tid];
#pragma unroll
    for (int o = 16; o; o >>= 1) a += __shfl_xor_sync(0xffffffffu, a, o);
    if (lane == 0) red_s[warp] = a;
    __syncthreads();
    if (tid == 0) {
        float tot = g_effw[576];
        for (int i = 0; i < 8; i++) tot += red_s[i];
        out[b] = tot;
    }
}

// ---------------- launch ----------------------------------------------------
extern "C" void kernel_launch(void* const* d_in, const int* in_sizes, int n_in,
                              void* d_out, int out_size) {
    const float* x      = (const float*)d_in[0];
    const float* W_ih   = (const float*)d_in[1];
    const float* W_hh   = (const float*)d_in[2];
    const float* b_ih   = (const float*)d_in[3];
    const float* b_hh   = (const float*)d_in[4];
    const float* conv_W = (const float*)d_in[5];
    const float* conv_b = (const float*)d_in[6];
    const float* lin1_W = (const float*)d_in[7];
    const float* lin1_b = (const float*)d_in[8];
    const float* lin2_W = (const float*)d_in[9];
    const float* lin2_b = (const float*)d_in[10];
    const float* out_W  = (const float*)d_in[11];
    const float* out_b  = (const float*)d_in[12];
    float* out = (float*)d_out;

    {   // prep (2 launches)
        size_t tw = (size_t)L_ * NG * KK;
        prep_w_kernel<<<(unsigned)((tw + 255) / 256), 256>>>(W_ih, W_hh, b_ih, b_hh);
        size_t tx = (size_t)T_ * B_ * D_;
        prep_misc_kernel<<<(unsigned)((tx + 255) / 256), 256>>>(x, lin2_W, lin2_b, out_W, out_b);
    }

    // persistent dataflow wavefront (single launch for all 192 cells)
    cudaFuncSetAttribute(lstm_persist, cudaFuncAttributeMaxDynamicSharedMemorySize, DYN_SMEM);
    lstm_persist<<<NPERS, NTHR, DYN_SMEM>>>();

    // head
    cudaFuncSetAttribute(head_kernel, cudaFuncAttributeMaxDynamicSharedMemorySize,
                         HEAD_SMEM_FLOATS * (int)sizeof(float));
    head_kernel<<<B_, 256, HEAD_SMEM_FLOATS * (int)sizeof(float)>>>(
        conv_W, conv_b, lin1_W, lin1_b, out);
}

// round 12
// speedup vs baseline: 1.4222x; 1.0243x over previous
#include <cuda_runtime.h>
#include <cuda_bf16.h>
#include <math.h>
#include <stdint.h>

// ---------------- problem constants ----------------------------------------
#define B_ 1024
#define T_ 64
#define D_ 512
#define HD_ 512
#define L_ 3
#define NG 2048          // 4*HD gate columns (gate-interleaved)
#define KK 1024          // D + HD fused K
#define FN_ 64
#define ATT 63
#define NCELL (T_ * L_)          // 192
#define NITEM (NCELL * 128)      // 24576 tiles

// ---------------- device scratch -------------------------------------------
__device__ __align__(16) __nv_bfloat16 g_Whi[(size_t)L_ * NG * KK];   // [l][n][k]
__device__ __align__(16) __nv_bfloat16 g_Wlo[(size_t)L_ * NG * KK];
__device__ __align__(16) __nv_bfloat16 g_xhi[(size_t)T_ * B_ * D_];   // [t][b][d]
__device__ __align__(16) __nv_bfloat16 g_xlo[(size_t)T_ * B_ * D_];
// write-once hidden state: slot s = t+1 holds h(t,l); slot 0 = zeros
__device__ __align__(16) __nv_bfloat16 g_Hhi[(size_t)(T_ + 1) * L_ * B_ * HD_];
__device__ __align__(16) __nv_bfloat16 g_Hlo[(size_t)(T_ + 1) * L_ * B_ * HD_];
__device__ float g_c[(size_t)L_ * B_ * HD_];
__device__ __align__(16) float g_bias[L_ * NG];
__device__ __align__(16) float g_ys[(size_t)T_ * B_ * HD_];
__device__ float g_effw[577];
// dataflow scheduling state
__device__ int g_next;
__device__ int g_cnt[T_ * L_ * 8];     // [t][l][mBi] -> arrives 0..16
__device__ int g_cell_tl[NCELL];       // diagonal-major (t<<2)|l

// ---------------- small asm helpers ----------------------------------------
__device__ __forceinline__ uint32_t smem_u32(const void* p) {
    uint32_t a;
    asm("{ .reg .u64 t; cvta.to.shared.u64 t, %1; cvt.u32.u64 %0, t; }" : "=r"(a) : "l"(p));
    return a;
}
__device__ __forceinline__ void cp16(uint32_t dst, const void* src) {
    asm volatile("cp.async.cg.shared.global [%0], [%1], 16;" :: "r"(dst), "l"(src));
}
__device__ __forceinline__ void cp_mbar_arrive(uint32_t mbar) {
    asm volatile("cp.async.mbarrier.arrive.noinc.shared.b64 [%0];" :: "r"(mbar) : "memory");
}
#define MBARRIER_INIT(addr, cnt) \
    asm volatile("mbarrier.init.shared.b64 [%0], %1;" :: "r"((uint32_t)(addr)), "r"((uint32_t)(cnt)) : "memory")
#define MBARRIER_ARRIVE(addr) \
    asm volatile("mbarrier.arrive.shared.b64 _, [%0];" :: "r"((uint32_t)(addr)) : "memory")
#define MBARRIER_WAIT_PARITY(addr, par) do { \
    uint32_t _m = (uint32_t)(addr); uint32_t _p = (uint32_t)(par); uint32_t _d; \
    asm volatile("{ .reg .pred p; mbarrier.try_wait.parity.acquire.cta.shared::cta.b64 p, [%1], %2; selp.b32 %0,1,0,p; }" \
        : "=r"(_d) : "r"(_m), "r"(_p) : "memory"); \
    if (!_d) { \
        asm volatile("{ .reg .pred P1; WL%=: mbarrier.try_wait.parity.acquire.cta.shared::cta.b64 P1, [%0], %1, 0x989680; @P1 bra.uni WD%=; bra.uni WL%=; WD%=: }" \
            :: "r"(_m), "r"(_p) : "memory"); \
    } } while (0)

__device__ __forceinline__ int ld_acq(const int* p) {
    int v;
    asm volatile("ld.acquire.gpu.global.s32 %0, [%1];" : "=r"(v) : "l"(p) : "memory");
    return v;
}
__device__ __forceinline__ void red_rel_add1(int* p) {
    asm volatile("red.release.gpu.global.add.s32 [%0], %1;" :: "l"(p), "r"(1) : "memory");
}

__device__ __forceinline__ void ldsm4(uint32_t* r, uint32_t addr) {
    asm volatile("ldmatrix.sync.aligned.m8n8.x4.shared.b16 {%0,%1,%2,%3}, [%4];"
                 : "=r"(r[0]), "=r"(r[1]), "=r"(r[2]), "=r"(r[3]) : "r"(addr));
}
__device__ __forceinline__ void mma16816(float* c, const uint32_t* a, const uint32_t* b) {
    asm volatile("mma.sync.aligned.m16n8k16.row.col.f32.bf16.bf16.f32 "
                 "{%0,%1,%2,%3}, {%4,%5,%6,%7}, {%8,%9}, {%0,%1,%2,%3};"
                 : "+f"(c[0]), "+f"(c[1]), "+f"(c[2]), "+f"(c[3])
                 : "r"(a[0]), "r"(a[1]), "r"(a[2]), "r"(a[3]), "r"(b[0]), "r"(b[1]));
}
__device__ __forceinline__ float sigf(float x) { return 1.f / (1.f + expf(-x)); }

// ---------------- prep kernels ---------------------------------------------
__global__ void prep_w_kernel(const float* __restrict__ W_ih, const float* __restrict__ W_hh,
                              const float* __restrict__ b_ih, const float* __restrict__ b_hh) {
    size_t idx = (size_t)blockIdx.x * blockDim.x + threadIdx.x;
    const size_t total = (size_t)L_ * NG * KK;
    if (idx < total) {
        int l = (int)(idx / ((size_t)NG * KK));
        size_t r = idx % ((size_t)NG * KK);
        int n = (int)(r / KK), k = (int)(r % KK);
        int oc = (n & 3) * HD_ + (n >> 2);
        float v = (k < D_) ? W_ih[((size_t)l * NG + oc) * D_ + k]
                           : W_hh[((size_t)l * NG + oc) * HD_ + (k - D_)];
        __nv_bfloat16 hi = __float2bfloat16(v);
        g_Whi[idx] = hi;
        g_Wlo[idx] = __float2bfloat16(v - __bfloat162float(hi));
    }
    if (idx < (size_t)L_ * NG) {
        int l = (int)(idx / NG), n = (int)(idx % NG);
        int oc = (n & 3) * HD_ + (n >> 2);
        g_bias[idx] = b_ih[(size_t)l * NG + oc] + b_hh[(size_t)l * NG + oc];
    }
}

// merged: x split + h-slot0/c zero + scheduler reset + folded output vector
__global__ void prep_misc_kernel(const float* __restrict__ x,
                                 const float* __restrict__ lin2_W, const float* __restrict__ lin2_b,
                                 const float* __restrict__ out_W, const float* __restrict__ out_b) {
    size_t idx = (size_t)blockIdx.x * blockDim.x + threadIdx.x;
    const size_t totx = (size_t)T_ * B_ * D_;
    if (idx < totx) {
        int t = (int)(idx / ((size_t)B_ * D_));
        size_t r = idx % ((size_t)B_ * D_);
        int b = (int)(r / D_), d = (int)(r % D_);
        float v = x[((size_t)b * T_ + t) * D_ + d];
        __nv_bfloat16 hi = __float2bfloat16(v);
        g_xhi[idx] = hi;
        g_xlo[idx] = __float2bfloat16(v - __bfloat162float(hi));
    }
    const size_t slot0 = (size_t)L_ * B_ * HD_;
    if (idx < slot0) { g_Hhi[idx] = __float2bfloat16(0.f); g_Hlo[idx] = __float2bfloat16(0.f); g_c[idx] = 0.f; }
    if (idx < (size_t)(T_ * L_ * 8)) g_cnt[idx] = 0;
    if (idx == 0) {
        g_next = 0;
        int i = 0;
        for (int d = 0; d < T_ + L_ - 1; d++) {
            int lmin = d - (T_ - 1); if (lmin < 0) lmin = 0;
            int lmax = (d < L_ - 1) ? d : (L_ - 1);
            for (int l = lmin; l <= lmax; l++) g_cell_tl[i++] = ((d - l) << 2) | l;
        }
    }
    if (idx < 576) {
        float a = 0.f;
        for (int j = 0; j < HD_; j++) a += out_W[j] * lin2_W[(size_t)j * 576 + idx];
        g_effw[idx] = a;
    } else if (idx == 576) {
        float a = out_b[0];
        for (int j = 0; j < HD_; j++) a += out_W[j] * lin2_b[j];
        g_effw[576] = a;
    }
}

// ---------------- persistent dataflow LSTM ----------------------------------
// 148 persistent CTAs; work item = (cell, mB-tile, nB-tile); deps via
// release/acquire counters. Loader: hoisted per-thread pointers; dep spins
// moved per-operand into the pipeline (B/weights never wait; the t-1 dep only
// gates chunk 8's A-half, overlapping the spin with 6 chunks of compute).
#define KCH 64
#define NCH (KK / KCH)            // 16 chunks
#define ROWB 144
#define TILE_BYTES (128 * ROWB)   // 18432
#define AH_OFF 0
#define AL_OFF (TILE_BYTES)
#define BH_OFF (2 * TILE_BYTES)
#define BL_OFF (3 * TILE_BYTES)
#define STAGE_BYTES (4 * TILE_BYTES)   // 73728
#define NSTAGE 3
#define DYN_SMEM (NSTAGE * STAGE_BYTES)  // 221184 (1 CTA/SM)
#define NTHR 512
#define NPERS 148

__global__ __launch_bounds__(NTHR, 1)
void lstm_persist() {
    extern __shared__ __align__(128) char dynsm[];
    __shared__ __align__(8) unsigned long long s_full[NSTAGE], s_empty[NSTAGE];
    __shared__ int s_item;
    const uint32_t smb = smem_u32(dynsm);
    const uint32_t mb_full = smem_u32(s_full);
    const uint32_t mb_empty = smem_u32(s_empty);

    const int tid  = threadIdx.x;
    const int lane = tid & 31;
    const int wid  = tid >> 5;               // 0..15
    const int wm   = (wid & 3) * 32;
    const int wn   = (wid >> 2) * 32;

    const uint32_t a_off = (uint32_t)((wm + (lane & 15)) * ROWB + (lane >> 4) * 16);
    const uint32_t b_row = (uint32_t)(wn + (lane & 7) + ((lane >> 4) << 3));
    const uint32_t b_off = b_row * ROWB + (((lane >> 3) & 1) << 4);

    // loader per-thread constants
    const int row0 = tid >> 3;               // 0..63 (iter 1 handles row0+64)
    const int ch   = tid & 7;
    const uint32_t so0 = (uint32_t)(row0 * ROWB + ch * 16);
    const uint32_t so1 = so0 + (uint32_t)(64 * ROWB);
    const ptrdiff_t dW  = g_Wlo - g_Whi;     // hi->lo array delta (constant)
    const ptrdiff_t dH  = g_Hlo - g_Hhi;
    const ptrdiff_t dX  = g_xlo - g_xhi;

    for (;;) {
        // ---- grab next item; init barriers ---------------------------------
        if (tid == 0) s_item = atomicAdd(&g_next, 1);
        __syncthreads();
        const int item = s_item;
        if (item >= NITEM) break;

        const int cell = item >> 7;
        const int tl = g_cell_tl[cell];
        const int t = tl >> 2, l = tl & 3;
        const int tile = item & 127;
        const int mBi = tile & 7, nBi = tile >> 3;
        const int mBase = mBi * 128, nBase = nBi * 128;

        if (tid == 0) {
#pragma unroll
            for (int s = 0; s < NSTAGE; s++) {
                MBARRIER_INIT(mb_full + s * 8, NTHR);
                MBARRIER_INIT(mb_empty + s * 8, NTHR);
            }
        }
        __syncthreads();

        // ---- hoisted operand pointers (per thread) --------------------------
        const __nv_bfloat16 *pA0, *pA1, *pW;
        ptrdiff_t dA0;
        if (l == 0) {
            pA0 = g_xhi + (size_t)t * B_ * D_ + (size_t)(mBase + row0) * 512 + ch * 8;
            dA0 = dX;
        } else {
            pA0 = g_Hhi + ((size_t)(t + 1) * L_ + (l - 1)) * B_ * HD_
                        + (size_t)(mBase + row0) * 512 + ch * 8;   // h(t, l-1)
            dA0 = dH;
        }
        pA1 = g_Hhi + ((size_t)t * L_ + l) * B_ * HD_
                    + (size_t)(mBase + row0) * 512 + ch * 8;       // h(t-1, l)
        pW  = g_Whi + (size_t)l * NG * KK
                    + (size_t)(nBase + row0) * (size_t)KK + ch * 8;

        auto load_chunk = [&](int c) {
            const int k0 = c * KCH;
            const int s = c % NSTAGE;
            const uint32_t sb = smb + s * STAGE_BYTES;
            // B (weights) never has a dependency -> issue first
            const __nv_bfloat16* w0 = pW + k0;
            cp16(sb + BH_OFF + so0, w0);
            cp16(sb + BH_OFF + so1, w0 + 64 * KK);
            cp16(sb + BL_OFF + so0, w0 + dW);
            cp16(sb + BL_OFF + so1, w0 + dW + 64 * KK);
            // A: per-operand dep gate at the boundary chunk only
            const __nv_bfloat16* a0;
            ptrdiff_t da;
            if (k0 < D_) {
                if (k0 == 0 && l > 0) {
                    const int* p = &g_cnt[(t * L_ + (l - 1)) * 8 + mBi];
                    while (ld_acq(p) < 16) __nanosleep(32);
                }
                a0 = pA0 + k0; da = dA0;
            } else {
                if (k0 == D_ && t > 0) {
                    const int* p = &g_cnt[((t - 1) * L_ + l) * 8 + mBi];
                    while (ld_acq(p) < 16) __nanosleep(32);
                }
                a0 = pA1 + (k0 - D_); da = dH;
            }
            cp16(sb + AH_OFF + so0, a0);
            cp16(sb + AH_OFF + so1, a0 + 64 * 512);
            cp16(sb + AL_OFF + so0, a0 + da);
            cp16(sb + AL_OFF + so1, a0 + da + 64 * 512);
            cp_mbar_arrive(mb_full + s * 8);
        };

        float acc[2][4][4];
#pragma unroll
        for (int i = 0; i < 2; i++)
#pragma unroll
            for (int j = 0; j < 4; j++)
#pragma unroll
                for (int q = 0; q < 4; q++) acc[i][j][q] = 0.f;

        load_chunk(0);
        load_chunk(1);

        for (int c = 0; c < NCH; c++) {
            const int s = c % NSTAGE;
            const int k = c / NSTAGE;
            MBARRIER_WAIT_PARITY(mb_full + s * 8, k & 1);
            const uint32_t sb = smb + s * STAGE_BYTES;

#pragma unroll
            for (int kk = 0; kk < 4; kk++) {
                const uint32_t kofs = (uint32_t)(kk * 32);
                uint32_t a_hi[2][4], a_lo[2][4];
#pragma unroll
                for (int mt = 0; mt < 2; mt++) {
                    uint32_t ad = sb + a_off + (uint32_t)(mt * 16 * ROWB) + kofs;
                    ldsm4(a_hi[mt], ad + AH_OFF);
                    ldsm4(a_lo[mt], ad + AL_OFF);
                }
                uint32_t b_hi[4][2], b_lo[4][2];
#pragma unroll
                for (int g = 0; g < 2; g++) {
                    uint32_t bd = sb + b_off + (uint32_t)(g * 16 * ROWB) + kofs;
                    uint32_t r[4];
                    ldsm4(r, bd + BH_OFF);
                    b_hi[2 * g][0] = r[0]; b_hi[2 * g][1] = r[1];
                    b_hi[2 * g + 1][0] = r[2]; b_hi[2 * g + 1][1] = r[3];
                    ldsm4(r, bd + BL_OFF);
                    b_lo[2 * g][0] = r[0]; b_lo[2 * g][1] = r[1];
                    b_lo[2 * g + 1][0] = r[2]; b_lo[2 * g + 1][1] = r[3];
                }
#pragma unroll
                for (int mt = 0; mt < 2; mt++)
#pragma unroll
                    for (int nt = 0; nt < 4; nt++) mma16816(acc[mt][nt], a_hi[mt], b_hi[nt]);
#pragma unroll
                for (int mt = 0; mt < 2; mt++)
#pragma unroll
                    for (int nt = 0; nt < 4; nt++) mma16816(acc[mt][nt], a_lo[mt], b_hi[nt]);
#pragma unroll
                for (int mt = 0; mt < 2; mt++)
#pragma unroll
                    for (int nt = 0; nt < 4; nt++) mma16816(acc[mt][nt], a_hi[mt], b_lo[nt]);
            }
            MBARRIER_ARRIVE(mb_empty + s * 8);

            const int c2 = c + 2;
            if (c2 < NCH) {
                const int s2 = c2 % NSTAGE;
                const int k2 = c2 / NSTAGE;
                if (k2 >= 1) MBARRIER_WAIT_PARITY(mb_empty + s2 * 8, (k2 - 1) & 1);
                load_chunk(c2);
            }
        }

        // ---- fused LSTM-cell epilogue ---------------------------------------
        {
            const int q = lane & 3;
            const bool active = (q & 1) == 0;
            float* cbase = g_c + (size_t)l * B_ * HD_;
            __nv_bfloat16* hh = g_Hhi + ((size_t)(t + 1) * L_ + l) * B_ * HD_;
            __nv_bfloat16* hl = g_Hlo + ((size_t)(t + 1) * L_ + l) * B_ * HD_;
            float* ys = (l == 2) ? (g_ys + (size_t)t * B_ * HD_) : nullptr;

#pragma unroll
            for (int mt = 0; mt < 2; mt++) {
#pragma unroll
                for (int nt = 0; nt < 4; nt++) {
                    float* cc = acc[mt][nt];
                    float p0 = __shfl_xor_sync(0xffffffffu, cc[0], 1);
                    float p1 = __shfl_xor_sync(0xffffffffu, cc[1], 1);
                    float p2 = __shfl_xor_sync(0xffffffffu, cc[2], 1);
                    float p3 = __shfl_xor_sync(0xffffffffu, cc[3], 1);
                    if (active) {
                        int n0 = nBase + wn + nt * 8 + q * 2;
                        int j = n0 >> 2;
                        const float4 bs = *(const float4*)&g_bias[l * NG + n0];
                        int r0 = mBase + wm + mt * 16 + (lane >> 2);
#pragma unroll
                        for (int rg = 0; rg < 2; rg++) {
                            int row = r0 + rg * 8;
                            float gi = (rg ? cc[2] : cc[0]) + bs.x;
                            float gf = (rg ? cc[3] : cc[1]) + bs.y;
                            float gg = (rg ? p2 : p0) + bs.z;
                            float go = (rg ? p3 : p1) + bs.w;
                            size_t off = (size_t)row * HD_ + j;
                            float cold = cbase[off];
                            float cn = sigf(gf) * cold + sigf(gi) * tanhf(gg);
                            float hn = sigf(go) * tanhf(cn);
                            cbase[off] = cn;
                            __nv_bfloat16 hi = __float2bfloat16(hn);
                            hh[off] = hi;
                            hl[off] = __float2bfloat16(hn - __bfloat162float(hi));
                            if (ys) ys[off] = hn;
                        }
                    }
                }
            }
        }

        // publish: all threads' stores -> cta barrier -> release increment
        __threadfence();
        __syncthreads();
        if (tid == 0) red_rel_add1(&g_cnt[(t * L_ + l) * 8 + mBi]);
    }
}

// ---------------- attention / TPA head --------------------------------------
// conv phase register-blocked: thread = (float4 of features) x (8 channels).
#define HEAD_SMEM_FLOATS (32768 + 8064 + 4032 + 512 + 64 + 512 + 64 + 256)

__global__ __launch_bounds__(256)
void head_kernel(const float* __restrict__ conv_W, const float* __restrict__ conv_b,
                 const float* __restrict__ lin1_W, const float* __restrict__ lin1_b,
                 float* __restrict__ out) {
    extern __shared__ float sm[];
    float* conv_s  = sm;                 // [64][512] flat c*512+f
    float* Hblk    = conv_s + 32768;     // [63][128] as float4[63][32]
    float* kW_s    = Hblk + 8064;        // [64][63]
    float* htt_s   = kW_s + 4032;
    float* w_s     = htt_s + 512;
    float* alpha_s = w_s + 64;
    float* v_s     = alpha_s + 512;
    float* red_s   = v_s + 64;

    const int b = blockIdx.x;
    const int tid = threadIdx.x;
    const int lane = tid & 31;
    const int warp = tid >> 5;

    for (int i = tid; i < FN_ * ATT; i += 256) kW_s[i] = conv_W[i];
    for (int i = tid; i < HD_; i += 256)
        htt_s[i] = g_ys[(size_t)(T_ - 1) * B_ * HD_ + (size_t)b * HD_ + i];
    __syncthreads();

    for (int qq = 0; qq < 8; qq++) {
        int qi = warp * 8 + qq;
        float p = 0.f;
        for (int k = lane; k < HD_; k += 32) p += htt_s[k] * lin1_W[(size_t)qi * HD_ + k];
#pragma unroll
        for (int o = 16; o; o >>= 1) p += __shfl_xor_sync(0xffffffffu, p, o);
        if (lane == 0) w_s[qi] = p + lin1_b[qi];
    }

    float4* Hblk4 = (float4*)Hblk;
    float4* conv_s4 = (float4*)conv_s;
    const int fi4 = tid & 31;
    const int cgrp = tid >> 5;
    for (int fb = 0; fb < 4; fb++) {
        int f0 = fb * 128;
        for (int i = tid; i < ATT * 32; i += 256) {
            int tt = i >> 5, f4 = i & 31;
            float4 v = *(const float4*)&g_ys[(size_t)tt * B_ * HD_ + (size_t)b * HD_ + f0 + f4 * 4];
            v.x = fmaxf(v.x, 0.f); v.y = fmaxf(v.y, 0.f);
            v.z = fmaxf(v.z, 0.f); v.w = fmaxf(v.w, 0.f);
            Hblk4[i] = v;
        }
        __syncthreads();

        float4 acc[8];
#pragma unroll
        for (int k = 0; k < 8; k++) {
            float bb = conv_b[cgrp + 8 * k];
            acc[k] = make_float4(bb, bb, bb, bb);
        }
        for (int t = 0; t < ATT; t++) {
            float4 h = Hblk4[t * 32 + fi4];
#pragma unroll
            for (int k = 0; k < 8; k++) {
                float w = kW_s[(cgrp + 8 * k) * ATT + t];
                acc[k].x += w * h.x; acc[k].y += w * h.y;
                acc[k].z += w * h.z; acc[k].w += w * h.w;
            }
        }
#pragma unroll
        for (int k = 0; k < 8; k++) {
            int c = cgrp + 8 * k;
            float4 v = acc[k];
            v.x = fmaxf(v.x, 0.f); v.y = fmaxf(v.y, 0.f);
            v.z = fmaxf(v.z, 0.f); v.w = fmaxf(v.w, 0.f);
            conv_s4[(c << 7) + (f0 >> 2) + fi4] = v;
        }
        __syncthreads();
    }

    for (int p = warp; p < 512; p += 8) {
        float a = conv_s[p * 64 + lane] * w_s[lane]
                + conv_s[p * 64 + 32 + lane] * w_s[32 + lane];
#pragma unroll
        for (int o = 16; o; o >>= 1) a += __shfl_xor_sync(0xffffffffu, a, o);
        if (lane == 0) alpha_s[p] = 1.f / (1.f + expf(-a));
    }
    __syncthreads();

    {
        int qn = tid & 63, part = tid >> 6;
        float a = 0.f;
        for (int p = part; p < 512; p += 4) a += alpha_s[p] * conv_s[p * 64 + qn];
        red_s[tid] = a;
    }
    __syncthreads();
    if (tid < 64) v_s[tid] = red_s[tid] + red_s[64 + tid] + red_s[128 + tid] + red_s[192 + tid];
    __syncthreads();

    float a = 0.f;
    for (int k = tid; k < HD_; k += 256) a += htt_s[k] * g_effw[k];
    if (tid < 64) a += v_s[tid] * g_effw[HD_ + tid];
#pragma unroll
    for (int o = 16; o; o >>= 1) a += __shfl_xor_sync(0xffffffffu, a, o);
    if (lane == 0) red_s[warp] = a;
    __syncthreads();
    if (tid == 0) {
        float tot = g_effw[576];
        for (int i = 0; i < 8; i++) tot += red_s[i];
        out[b] = tot;
    }
}

// ---------------- launch ----------------------------------------------------
extern "C" void kernel_launch(void* const* d_in, const int* in_sizes, int n_in,
                              void* d_out, int out_size) {
    const float* x      = (const float*)d_in[0];
    const float* W_ih   = (const float*)d_in[1];
    const float* W_hh   = (const float*)d_in[2];
    const float* b_ih   = (const float*)d_in[3];
    const float* b_hh   = (const float*)d_in[4];
    const float* conv_W = (const float*)d_in[5];
    const float* conv_b = (const float*)d_in[6];
    const float* lin1_W = (const float*)d_in[7];
    const float* lin1_b = (const float*)d_in[8];
    const float* lin2_W = (const float*)d_in[9];
    const float* lin2_b = (const float*)d_in[10];
    const float* out_W  = (const float*)d_in[11];
    const float* out_b  = (const float*)d_in[12];
    float* out = (float*)d_out;

    {   // prep (2 launches)
        size_t tw = (size_t)L_ * NG * KK;
        prep_w_kernel<<<(unsigned)((tw + 255) / 256), 256>>>(W_ih, W_hh, b_ih, b_hh);
        size_t tx = (size_t)T_ * B_ * D_;
        prep_misc_kernel<<<(unsigned)((tx + 255) / 256), 256>>>(x, lin2_W, lin2_b, out_W, out_b);
    }

    // persistent dataflow wavefront (single launch for all 192 cells)
    cudaFuncSetAttribute(lstm_persist, cudaFuncAttributeMaxDynamicSharedMemorySize, DYN_SMEM);
    lstm_persist<<<NPERS, NTHR, DYN_SMEM>>>();

    // head
    cudaFuncSetAttribute(head_kernel, cudaFuncAttributeMaxDynamicSharedMemorySize,
                         HEAD_SMEM_FLOATS * (int)sizeof(float));
    head_kernel<<<B_, 256, HEAD_SMEM_FLOATS * (int)sizeof(float)>>>(
        conv_W, conv_b, lin1_W, lin1_b, out);
}

// round 13
// speedup vs baseline: 1.5197x; 1.0685x over previous
#include <cuda_runtime.h>
#include <cuda_bf16.h>
#include <math.h>
#include <stdint.h>

// ---------------- problem constants ----------------------------------------
#define B_ 1024
#define T_ 64
#define D_ 512
#define HD_ 512
#define L_ 3
#define NG 2048          // 4*HD gate columns (gate-interleaved)
#define KK 1024          // D + HD fused K
#define FN_ 64
#define ATT 63
#define NCELL (T_ * L_)          // 192
#define NITEM (NCELL * 128)      // 24576 tiles

// tile geometry (global layout == smem stage image)
#define KCH 64
#define NCH (KK / KCH)            // 16 chunks
#define ROWB 144                  // 128B payload + 16B pad (conflict-free ldmatrix)
#define TB 18432                  // one 128-row tile (128*ROWB)
#define BLK (2 * TB)              // hi tile + lo tile, adjacent = 36864
#define AH_OFF 0
#define AL_OFF (TB)
#define BH_OFF (2 * TB)
#define BL_OFF (3 * TB)
#define STAGE_BYTES (4 * TB)      // 73728
#define NSTAGE 3
#define DYN_SMEM (NSTAGE * STAGE_BYTES)  // 221184 (1 CTA/SM)
#define NTHR 512
#define NPERS 148

// ---------------- device scratch (tiled operand storage) --------------------
// W tiled: [l][nBi(16)][chunk(16)] x BLK (hi tile | lo tile)
__device__ __align__(128) uint8_t g_Wt[(size_t)L_ * 16 * 16 * BLK];
// x tiled: [t][mBi(8)][chunk(8)] x BLK
__device__ __align__(128) uint8_t g_xt[(size_t)T_ * 64 * BLK];
// h tiled, write-once: slot s = t+1 holds h(t,l); slot indices [s*L+l][mBi(8)][chunk(8)]
__device__ __align__(128) uint8_t g_Ht[(size_t)(T_ + 1) * L_ * 64 * BLK];
__device__ float g_c[(size_t)L_ * B_ * HD_];
__device__ __align__(16) float g_bias[L_ * NG];
__device__ __align__(16) float g_ys[(size_t)T_ * B_ * HD_];
__device__ float g_effw[577];
// dataflow scheduling state
__device__ int g_next;
__device__ int g_cnt[T_ * L_ * 8];     // [t][l][mBi] -> arrives 0..16
__device__ int g_cell_tl[NCELL];       // diagonal-major (t<<2)|l

// ---------------- small asm helpers ----------------------------------------
__device__ __forceinline__ uint32_t smem_u32(const void* p) {
    uint32_t a;
    asm("{ .reg .u64 t; cvta.to.shared.u64 t, %1; cvt.u32.u64 %0, t; }" : "=r"(a) : "l"(p));
    return a;
}
// bulk async copy global->shared, completion via mbarrier complete_tx
__device__ __forceinline__ void cp_bulk(uint32_t dst, const void* src, uint32_t bytes, uint32_t mbar) {
    asm volatile("cp.async.bulk.shared::cluster.global.mbarrier::complete_tx::bytes [%0], [%1], %2, [%3];"
                 :: "r"(dst), "l"(src), "r"(bytes), "r"(mbar) : "memory");
}
#define MBARRIER_INIT(addr, cnt) \
    asm volatile("mbarrier.init.shared.b64 [%0], %1;" :: "r"((uint32_t)(addr)), "r"((uint32_t)(cnt)) : "memory")
#define MBARRIER_ARRIVE(addr) \
    asm volatile("mbarrier.arrive.shared.b64 _, [%0];" :: "r"((uint32_t)(addr)) : "memory")
#define MBARRIER_EXPECT_TX(addr, tx) \
    asm volatile("mbarrier.arrive.expect_tx.shared.b64 _, [%0], %1;" :: "r"((uint32_t)(addr)), "r"((uint32_t)(tx)) : "memory")
#define MBARRIER_WAIT_PARITY(addr, par) do { \
    uint32_t _m = (uint32_t)(addr); uint32_t _p = (uint32_t)(par); uint32_t _d; \
    asm volatile("{ .reg .pred p; mbarrier.try_wait.parity.acquire.cta.shared::cta.b64 p, [%1], %2; selp.b32 %0,1,0,p; }" \
        : "=r"(_d) : "r"(_m), "r"(_p) : "memory"); \
    if (!_d) { \
        asm volatile("{ .reg .pred P1; WL%=: mbarrier.try_wait.parity.acquire.cta.shared::cta.b64 P1, [%0], %1, 0x989680; @P1 bra.uni WD%=; bra.uni WL%=; WD%=: }" \
            :: "r"(_m), "r"(_p) : "memory"); \
    } } while (0)

__device__ __forceinline__ int ld_acq(const int* p) {
    int v;
    asm volatile("ld.acquire.gpu.global.s32 %0, [%1];" : "=r"(v) : "l"(p) : "memory");
    return v;
}
__device__ __forceinline__ void red_rel_add1(int* p) {
    asm volatile("red.release.gpu.global.add.s32 [%0], %1;" :: "l"(p), "r"(1) : "memory");
}

__device__ __forceinline__ void ldsm4(uint32_t* r, uint32_t addr) {
    asm volatile("ldmatrix.sync.aligned.m8n8.x4.shared.b16 {%0,%1,%2,%3}, [%4];"
                 : "=r"(r[0]), "=r"(r[1]), "=r"(r[2]), "=r"(r[3]) : "r"(addr));
}
__device__ __forceinline__ void mma16816(float* c, const uint32_t* a, const uint32_t* b) {
    asm volatile("mma.sync.aligned.m16n8k16.row.col.f32.bf16.bf16.f32 "
                 "{%0,%1,%2,%3}, {%4,%5,%6,%7}, {%8,%9}, {%0,%1,%2,%3};"
                 : "+f"(c[0]), "+f"(c[1]), "+f"(c[2]), "+f"(c[3])
                 : "r"(a[0]), "r"(a[1]), "r"(a[2]), "r"(a[3]), "r"(b[0]), "r"(b[1]));
}
__device__ __forceinline__ float sigf(float x) { return 1.f / (1.f + expf(-x)); }

// ---------------- prep kernels ---------------------------------------------
__global__ void prep_w_kernel(const float* __restrict__ W_ih, const float* __restrict__ W_hh,
                              const float* __restrict__ b_ih, const float* __restrict__ b_hh) {
    size_t idx = (size_t)blockIdx.x * blockDim.x + threadIdx.x;
    const size_t total = (size_t)L_ * NG * KK;
    if (idx < total) {
        int l = (int)(idx / ((size_t)NG * KK));
        size_t r = idx % ((size_t)NG * KK);
        int n = (int)(r / KK), k = (int)(r % KK);
        int oc = (n & 3) * HD_ + (n >> 2);
        float v = (k < D_) ? W_ih[((size_t)l * NG + oc) * D_ + k]
                           : W_hh[((size_t)l * NG + oc) * HD_ + (k - D_)];
        __nv_bfloat16 hi = __float2bfloat16(v);
        __nv_bfloat16 lo = __float2bfloat16(v - __bfloat162float(hi));
        size_t blk = ((size_t)l * 16 + (n >> 7)) * 16 + (k >> 6);
        uint8_t* p = g_Wt + blk * BLK + (uint32_t)(n & 127) * ROWB + (uint32_t)(k & 63) * 2;
        *(__nv_bfloat16*)p = hi;
        *(__nv_bfloat16*)(p + TB) = lo;
    }
    if (idx < (size_t)L_ * NG) {
        int l = (int)(idx / NG), n = (int)(idx % NG);
        int oc = (n & 3) * HD_ + (n >> 2);
        g_bias[idx] = b_ih[(size_t)l * NG + oc] + b_hh[(size_t)l * NG + oc];
    }
}

// merged: x tile-split + h-slot(0..L-1)/c zero + scheduler reset + folded output vec
__global__ void prep_misc_kernel(const float* __restrict__ x,
                                 const float* __restrict__ lin2_W, const float* __restrict__ lin2_b,
                                 const float* __restrict__ out_W, const float* __restrict__ out_b) {
    size_t idx = (size_t)blockIdx.x * blockDim.x + threadIdx.x;
    const size_t totx = (size_t)T_ * B_ * D_;
    if (idx < totx) {
        int t = (int)(idx / ((size_t)B_ * D_));
        size_t r = idx % ((size_t)B_ * D_);
        int b = (int)(r / D_), d = (int)(r % D_);
        float v = x[((size_t)b * T_ + t) * D_ + d];
        __nv_bfloat16 hi = __float2bfloat16(v);
        __nv_bfloat16 lo = __float2bfloat16(v - __bfloat162float(hi));
        size_t blk = (size_t)t * 64 + (size_t)(b >> 7) * 8 + (d >> 6);
        uint8_t* p = g_xt + blk * BLK + (uint32_t)(b & 127) * ROWB + (uint32_t)(d & 63) * 2;
        *(__nv_bfloat16*)p = hi;
        *(__nv_bfloat16*)(p + TB) = lo;
    }
    // zero h slots 0..L-1 (t=0 recurrent input) incl. padding: L*64*BLK bytes
    const size_t hz = (size_t)L_ * 64 * BLK / 4;
    if (idx < hz) ((uint32_t*)g_Ht)[idx] = 0;
    if (idx < (size_t)L_ * B_ * HD_) g_c[idx] = 0.f;
    if (idx < (size_t)(T_ * L_ * 8)) g_cnt[idx] = 0;
    if (idx == 0) {
        g_next = 0;
        int i = 0;
        for (int d = 0; d < T_ + L_ - 1; d++) {
            int lmin = d - (T_ - 1); if (lmin < 0) lmin = 0;
            int lmax = (d < L_ - 1) ? d : (L_ - 1);
            for (int l = lmin; l <= lmax; l++) g_cell_tl[i++] = ((d - l) << 2) | l;
        }
    }
    if (idx < 576) {
        float a = 0.f;
        for (int j = 0; j < HD_; j++) a += out_W[j] * lin2_W[(size_t)j * 576 + idx];
        g_effw[idx] = a;
    } else if (idx == 576) {
        float a = out_b[0];
        for (int j = 0; j < HD_; j++) a += out_W[j] * lin2_b[j];
        g_effw[576] = a;
    }
}

// ---------------- persistent dataflow LSTM ----------------------------------
// 148 persistent CTAs; item = (cell, mBi, nBi). Loads: 2 cp.async.bulk per
// chunk (A block, B block) issued by tid0 into a 3-stage ring; full barrier =
// 1 arrive + expect_tx(73728). Compute: 16-warp mma.sync, desynced consumers.
__global__ __launch_bounds__(NTHR, 1)
void lstm_persist() {
    extern __shared__ __align__(128) char dynsm[];
    __shared__ __align__(8) unsigned long long s_full[NSTAGE], s_empty[NSTAGE];
    __shared__ int s_item;
    const uint32_t smb = smem_u32(dynsm);
    const uint32_t mb_full = smem_u32(s_full);
    const uint32_t mb_empty = smem_u32(s_empty);

    const int tid  = threadIdx.x;
    const int lane = tid & 31;
    const int wid  = tid >> 5;               // 0..15
    const int wm   = (wid & 3) * 32;
    const int wn   = (wid >> 2) * 32;

    const uint32_t a_off = (uint32_t)((wm + (lane & 15)) * ROWB + (lane >> 4) * 16);
    const uint32_t b_row = (uint32_t)(wn + (lane & 7) + ((lane >> 4) << 3));
    const uint32_t b_off = b_row * ROWB + (((lane >> 3) & 1) << 4);

    for (;;) {
        // ---- grab next item; init barriers ---------------------------------
        if (tid == 0) s_item = atomicAdd(&g_next, 1);
        __syncthreads();
        const int item = s_item;
        if (item >= NITEM) break;

        const int cell = item >> 7;
        const int tl = g_cell_tl[cell];
        const int t = tl >> 2, l = tl & 3;
        const int tile = item & 127;
        const int mBi = tile & 7, nBi = tile >> 3;
        const int nBase = nBi * 128;

        if (tid == 0) {
#pragma unroll
            for (int s = 0; s < NSTAGE; s++) {
                MBARRIER_INIT(mb_full + s * 8, 1);       // expect_tx arriver
                MBARRIER_INIT(mb_empty + s * 8, NTHR);   // consumer done-reads
            }
        }
        __syncthreads();

        // block bases for this item
        const uint8_t* wbase = g_Wt + (((size_t)l * 16 + nBi) * 16) * BLK;
        const uint8_t* a0base = (l == 0)
            ? g_xt + ((size_t)t * 64 + (size_t)mBi * 8) * BLK
            : g_Ht + (((size_t)(t + 1) * L_ + (l - 1)) * 64 + (size_t)mBi * 8) * BLK;  // h(t,l-1)
        const uint8_t* a1base = g_Ht + (((size_t)t * L_ + l) * 64 + (size_t)mBi * 8) * BLK;  // h(t-1,l)

        auto issue_chunk = [&](int c) {      // tid==0 only
            const int s = c % NSTAGE;
            const uint32_t sb = smb + s * STAGE_BYTES;
            MBARRIER_EXPECT_TX(mb_full + s * 8, (uint32_t)STAGE_BYTES);
            cp_bulk(sb + BH_OFF, wbase + (size_t)c * BLK, BLK, mb_full + s * 8);
            const uint8_t* asrc;
            if (c < 8) {
                if (c == 0 && l > 0) {
                    const int* p = &g_cnt[(t * L_ + (l - 1)) * 8 + mBi];
                    while (ld_acq(p) < 16) __nanosleep(32);
                }
                asrc = a0base + (size_t)c * BLK;
            } else {
                if (c == 8 && t > 0) {
                    const int* p = &g_cnt[((t - 1) * L_ + l) * 8 + mBi];
                    while (ld_acq(p) < 16) __nanosleep(32);
                }
                asrc = a1base + (size_t)(c - 8) * BLK;
            }
            cp_bulk(sb + AH_OFF, asrc, BLK, mb_full + s * 8);
        };

        float acc[2][4][4];
#pragma unroll
        for (int i = 0; i < 2; i++)
#pragma unroll
            for (int j = 0; j < 4; j++)
#pragma unroll
                for (int q = 0; q < 4; q++) acc[i][j][q] = 0.f;

        if (tid == 0) { issue_chunk(0); issue_chunk(1); }

        for (int c = 0; c < NCH; c++) {
            const int s = c % NSTAGE;
            const int k = c / NSTAGE;
            MBARRIER_WAIT_PARITY(mb_full + s * 8, k & 1);
            const uint32_t sb = smb + s * STAGE_BYTES;

#pragma unroll
            for (int kk = 0; kk < 4; kk++) {
                const uint32_t kofs = (uint32_t)(kk * 32);
                uint32_t a_hi[2][4], a_lo[2][4];
#pragma unroll
                for (int mt = 0; mt < 2; mt++) {
                    uint32_t ad = sb + a_off + (uint32_t)(mt * 16 * ROWB) + kofs;
                    ldsm4(a_hi[mt], ad + AH_OFF);
                    ldsm4(a_lo[mt], ad + AL_OFF);
                }
                uint32_t b_hi[4][2], b_lo[4][2];
#pragma unroll
                for (int g = 0; g < 2; g++) {
                    uint32_t bd = sb + b_off + (uint32_t)(g * 16 * ROWB) + kofs;
                    uint32_t r[4];
                    ldsm4(r, bd + BH_OFF);
                    b_hi[2 * g][0] = r[0]; b_hi[2 * g][1] = r[1];
                    b_hi[2 * g + 1][0] = r[2]; b_hi[2 * g + 1][1] = r[3];
                    ldsm4(r, bd + BL_OFF);
                    b_lo[2 * g][0] = r[0]; b_lo[2 * g][1] = r[1];
                    b_lo[2 * g + 1][0] = r[2]; b_lo[2 * g + 1][1] = r[3];
                }
#pragma unroll
                for (int mt = 0; mt < 2; mt++)
#pragma unroll
                    for (int nt = 0; nt < 4; nt++) mma16816(acc[mt][nt], a_hi[mt], b_hi[nt]);
#pragma unroll
                for (int mt = 0; mt < 2; mt++)
#pragma unroll
                    for (int nt = 0; nt < 4; nt++) mma16816(acc[mt][nt], a_lo[mt], b_hi[nt]);
#pragma unroll
                for (int mt = 0; mt < 2; mt++)
#pragma unroll
                    for (int nt = 0; nt < 4; nt++) mma16816(acc[mt][nt], a_hi[mt], b_lo[nt]);
            }
            MBARRIER_ARRIVE(mb_empty + s * 8);

            const int c2 = c + 2;
            if (tid == 0 && c2 < NCH) {
                const int s2 = c2 % NSTAGE;
                const int k2 = c2 / NSTAGE;
                if (k2 >= 1) MBARRIER_WAIT_PARITY(mb_empty + s2 * 8, (k2 - 1) & 1);
                issue_chunk(c2);
            }
        }

        // ---- fused LSTM-cell epilogue (h written in tiled layout) ------------
        {
            const int q = lane & 3;
            const bool active = (q & 1) == 0;
            float* cbase = g_c + (size_t)l * B_ * HD_;
            uint8_t* hb = g_Ht + (((size_t)(t + 1) * L_ + l) * 64 + (size_t)mBi * 8) * BLK;
            float* ys = (l == 2) ? (g_ys + (size_t)t * B_ * HD_) : nullptr;
            const int mBase = mBi * 128;

#pragma unroll
            for (int mt = 0; mt < 2; mt++) {
#pragma unroll
                for (int nt = 0; nt < 4; nt++) {
                    float* cc = acc[mt][nt];
                    float p0 = __shfl_xor_sync(0xffffffffu, cc[0], 1);
                    float p1 = __shfl_xor_sync(0xffffffffu, cc[1], 1);
                    float p2 = __shfl_xor_sync(0xffffffffu, cc[2], 1);
                    float p3 = __shfl_xor_sync(0xffffffffu, cc[3], 1);
                    if (active) {
                        int n0 = nBase + wn + nt * 8 + q * 2;
                        int j = n0 >> 2;
                        const float4 bs = *(const float4*)&g_bias[l * NG + n0];
                        int r0 = wm + mt * 16 + (lane >> 2);    // row within 128-tile
                        uint8_t* hj = hb + (size_t)(j >> 6) * BLK + (uint32_t)(j & 63) * 2;
#pragma unroll
                        for (int rg = 0; rg < 2; rg++) {
                            int rowin = r0 + rg * 8;
                            float gi = (rg ? cc[2] : cc[0]) + bs.x;
                            float gf = (rg ? cc[3] : cc[1]) + bs.y;
                            float gg = (rg ? p2 : p0) + bs.z;
                            float go = (rg ? p3 : p1) + bs.w;
                            size_t off = (size_t)(mBase + rowin) * HD_ + j;
                            float cold = cbase[off];
                            float cn = sigf(gf) * cold + sigf(gi) * tanhf(gg);
                            float hn = sigf(go) * tanhf(cn);
                            cbase[off] = cn;
                            __nv_bfloat16 hi = __float2bfloat16(hn);
                            uint8_t* p = hj + (uint32_t)rowin * ROWB;
                            *(__nv_bfloat16*)p = hi;
                            *(__nv_bfloat16*)(p + TB) = __float2bfloat16(hn - __bfloat162float(hi));
                            if (ys) ys[off] = hn;
                        }
                    }
                }
            }
        }

        // publish: stores visible (incl. to async proxy) -> barrier -> release
        __threadfence();
        asm volatile("fence.proxy.async;" ::: "memory");
        __syncthreads();
        if (tid == 0) red_rel_add1(&g_cnt[(t * L_ + l) * 8 + mBi]);
    }
}

// ---------------- attention / TPA head --------------------------------------
#define HEAD_SMEM_FLOATS (32768 + 8064 + 4032 + 512 + 64 + 512 + 64 + 256)

__global__ __launch_bounds__(256)
void head_kernel(const float* __restrict__ conv_W, const float* __restrict__ conv_b,
                 const float* __restrict__ lin1_W, const float* __restrict__ lin1_b,
                 float* __restrict__ out) {
    extern __shared__ float sm[];
    float* conv_s  = sm;                 // [64][512] flat c*512+f
    float* Hblk    = conv_s + 32768;     // [63][128] as float4[63][32]
    float* kW_s    = Hblk + 8064;        // [64][63]
    float* htt_s   = kW_s + 4032;
    float* w_s     = htt_s + 512;
    float* alpha_s = w_s + 64;
    float* v_s     = alpha_s + 512;
    float* red_s   = v_s + 64;

    const int b = blockIdx.x;
    const int tid = threadIdx.x;
    const int lane = tid & 31;
    const int warp = tid >> 5;

    for (int i = tid; i < FN_ * ATT; i += 256) kW_s[i] = conv_W[i];
    for (int i = tid; i < HD_; i += 256)
        htt_s[i] = g_ys[(size_t)(T_ - 1) * B_ * HD_ + (size_t)b * HD_ + i];
    __syncthreads();

    for (int qq = 0; qq < 8; qq++) {
        int qi = warp * 8 + qq;
        float p = 0.f;
        for (int k = lane; k < HD_; k += 32) p += htt_s[k] * lin1_W[(size_t)qi * HD_ + k];
#pragma unroll
        for (int o = 16; o; o >>= 1) p += __shfl_xor_sync(0xffffffffu, p, o);
        if (lane == 0) w_s[qi] = p + lin1_b[qi];
    }

    float4* Hblk4 = (float4*)Hblk;
    float4* conv_s4 = (float4*)conv_s;
    const int fi4 = tid & 31;
    const int cgrp = tid >> 5;
    for (int fb = 0; fb < 4; fb++) {
        int f0 = fb * 128;
        for (int i = tid; i < ATT * 32; i += 256) {
            int tt = i >> 5, f4 = i & 31;
            float4 v = *(const float4*)&g_ys[(size_t)tt * B_ * HD_ + (size_t)b * HD_ + f0 + f4 * 4];
            v.x = fmaxf(v.x, 0.f); v.y = fmaxf(v.y, 0.f);
            v.z = fmaxf(v.z, 0.f); v.w = fmaxf(v.w, 0.f);
            Hblk4[i] = v;
        }
        __syncthreads();

        float4 acc[8];
#pragma unroll
        for (int k = 0; k < 8; k++) {
            float bb = conv_b[cgrp + 8 * k];
            acc[k] = make_float4(bb, bb, bb, bb);
        }
        for (int t = 0; t < ATT; t++) {
            float4 h = Hblk4[t * 32 + fi4];
#pragma unroll
            for (int k = 0; k < 8; k++) {
                float w = kW_s[(cgrp + 8 * k) * ATT + t];
                acc[k].x += w * h.x; acc[k].y += w * h.y;
                acc[k].z += w * h.z; acc[k].w += w * h.w;
            }
        }
#pragma unroll
        for (int k = 0; k < 8; k++) {
            int c = cgrp + 8 * k;
            float4 v = acc[k];
            v.x = fmaxf(v.x, 0.f); v.y = fmaxf(v.y, 0.f);
            v.z = fmaxf(v.z, 0.f); v.w = fmaxf(v.w, 0.f);
            conv_s4[(c << 7) + (f0 >> 2) + fi4] = v;
        }
        __syncthreads();
    }

    for (int p = warp; p < 512; p += 8) {
        float a = conv_s[p * 64 + lane] * w_s[lane]
                + conv_s[p * 64 + 32 + lane] * w_s[32 + lane];
#pragma unroll
        for (int o = 16; o; o >>= 1) a += __shfl_xor_sync(0xffffffffu, a, o);
        if (lane == 0) alpha_s[p] = 1.f / (1.f + expf(-a));
    }
    __syncthreads();

    {
        int qn = tid & 63, part = tid >> 6;
        float a = 0.f;
        for (int p = part; p < 512; p += 4) a += alpha_s[p] * conv_s[p * 64 + qn];
        red_s[tid] = a;
    }
    __syncthreads();
    if (tid < 64) v_s[tid] = red_s[tid] + red_s[64 + tid] + red_s[128 + tid] + red_s[192 + tid];
    __syncthreads();

    float a = 0.f;
    for (int k = tid; k < HD_; k += 256) a += htt_s[k] * g_effw[k];
    if (tid < 64) a += v_s[tid] * g_effw[HD_ + tid];
#pragma unroll
    for (int o = 16; o; o >>= 1) a += __shfl_xor_sync(0xffffffffu, a, o);
    if (lane == 0) red_s[warp] = a;
    __syncthreads();
    if (tid == 0) {
        float tot = g_effw[576];
        for (int i = 0; i < 8; i++) tot += red_s[i];
        out[b] = tot;
    }
}

// ---------------- launch ----------------------------------------------------
extern "C" void kernel_launch(void* const* d_in, const int* in_sizes, int n_in,
                              void* d_out, int out_size) {
    const float* x      = (const float*)d_in[0];
    const float* W_ih   = (const float*)d_in[1];
    const float* W_hh   = (const float*)d_in[2];
    const float* b_ih   = (const float*)d_in[3];
    const float* b_hh   = (const float*)d_in[4];
    const float* conv_W = (const float*)d_in[5];
    const float* conv_b = (const float*)d_in[6];
    const float* lin1_W = (const float*)d_in[7];
    const float* lin1_b = (const float*)d_in[8];
    const float* lin2_W = (const float*)d_in[9];
    const float* lin2_b = (const float*)d_in[10];
    const float* out_W  = (const float*)d_in[11];
    const float* out_b  = (const float*)d_in[12];
    float* out = (float*)d_out;

    {   // prep (2 launches)
        size_t tw = (size_t)L_ * NG * KK;
        prep_w_kernel<<<(unsigned)((tw + 255) / 256), 256>>>(W_ih, W_hh, b_ih, b_hh);
        size_t tx = (size_t)T_ * B_ * D_;
        prep_misc_kernel<<<(unsigned)((tx + 255) / 256), 256>>>(x, lin2_W, lin2_b, out_W, out_b);
    }

    // persistent dataflow wavefront (single launch for all 192 cells)
    cudaFuncSetAttribute(lstm_persist, cudaFuncAttributeMaxDynamicSharedMemorySize, DYN_SMEM);
    lstm_persist<<<NPERS, NTHR, DYN_SMEM>>>();

    // head
    cudaFuncSetAttribute(head_kernel, cudaFuncAttributeMaxDynamicSharedMemorySize,
                         HEAD_SMEM_FLOATS * (int)sizeof(float));
    head_kernel<<<B_, 256, HEAD_SMEM_FLOATS * (int)sizeof(float)>>>(
        conv_W, conv_b, lin1_W, lin1_b, out);
}

// round 14
// speedup vs baseline: 1.9200x; 1.2634x over previous
#include <cuda_runtime.h>
#include <cuda_bf16.h>
#include <cuda_fp16.h>
#include <math.h>
#include <stdint.h>

// ---------------- problem constants ----------------------------------------
#define B_ 1024
#define T_ 64
#define D_ 512
#define HD_ 512
#define L_ 3
#define NG 2048          // 4*HD gate columns (gate-interleaved)
#define KK 1024          // D + HD fused K
#define FN_ 64
#define ATT 63
#define NCELL (T_ * L_)          // 192
#define NITEM (NCELL * 128)      // 24576 tiles

// tile geometry (global layout == smem stage image)
#define KCH 64
#define NCH (KK / KCH)            // 16 chunks
#define ROWB 144                  // 128B payload + 16B pad (conflict-free ldmatrix)
#define TB 18432                  // one 128-row tile (128*ROWB)
#define BLKA (2 * TB)             // A block: hi tile | lo tile = 36864
#define AH_OFF 0
#define AL_OFF (TB)
#define B_OFF (2 * TB)
#define STAGE_BYTES (3 * TB)      // 55296
#define NSTAGE 4
#define DYN_SMEM (NSTAGE * STAGE_BYTES)  // 221184 (1 CTA/SM)
#define NTHR 512
#define NPERS 148

// ---------------- device scratch (tiled operand storage) --------------------
// W tiled (single fp16): [l][nBi(16)][chunk(16)] x TB
__device__ __align__(128) uint8_t g_Wt[(size_t)L_ * 16 * 16 * TB];
// x tiled (fp16 hi|lo): [t][mBi(8)][chunk(8)] x BLKA
__device__ __align__(128) uint8_t g_xt[(size_t)T_ * 64 * BLKA];
// h tiled (fp16 hi|lo), write-once: slot s = t+1 holds h(t,l)
__device__ __align__(128) uint8_t g_Ht[(size_t)(T_ + 1) * L_ * 64 * BLKA];
__device__ float g_c[(size_t)L_ * B_ * HD_];
__device__ __align__(16) float g_bias[L_ * NG];
__device__ __align__(16) float g_ys[(size_t)T_ * B_ * HD_];
__device__ float g_effw[577];
// dataflow scheduling state
__device__ int g_next;
__device__ int g_cnt[T_ * L_ * 8];     // [t][l][mBi] -> arrives 0..16
__device__ int g_cell_tl[NCELL];       // diagonal-major (t<<2)|l

// ---------------- small asm helpers ----------------------------------------
__device__ __forceinline__ uint32_t smem_u32(const void* p) {
    uint32_t a;
    asm("{ .reg .u64 t; cvta.to.shared.u64 t, %1; cvt.u32.u64 %0, t; }" : "=r"(a) : "l"(p));
    return a;
}
__device__ __forceinline__ void cp_bulk(uint32_t dst, const void* src, uint32_t bytes, uint32_t mbar) {
    asm volatile("cp.async.bulk.shared::cluster.global.mbarrier::complete_tx::bytes [%0], [%1], %2, [%3];"
                 :: "r"(dst), "l"(src), "r"(bytes), "r"(mbar) : "memory");
}
#define MBARRIER_INIT(addr, cnt) \
    asm volatile("mbarrier.init.shared.b64 [%0], %1;" :: "r"((uint32_t)(addr)), "r"((uint32_t)(cnt)) : "memory")
#define MBARRIER_ARRIVE(addr) \
    asm volatile("mbarrier.arrive.shared.b64 _, [%0];" :: "r"((uint32_t)(addr)) : "memory")
#define MBARRIER_EXPECT_TX(addr, tx) \
    asm volatile("mbarrier.arrive.expect_tx.shared.b64 _, [%0], %1;" :: "r"((uint32_t)(addr)), "r"((uint32_t)(tx)) : "memory")
#define MBARRIER_WAIT_PARITY(addr, par) do { \
    uint32_t _m = (uint32_t)(addr); uint32_t _p = (uint32_t)(par); uint32_t _d; \
    asm volatile("{ .reg .pred p; mbarrier.try_wait.parity.acquire.cta.shared::cta.b64 p, [%1], %2; selp.b32 %0,1,0,p; }" \
        : "=r"(_d) : "r"(_m), "r"(_p) : "memory"); \
    if (!_d) { \
        asm volatile("{ .reg .pred P1; WL%=: mbarrier.try_wait.parity.acquire.cta.shared::cta.b64 P1, [%0], %1, 0x989680; @P1 bra.uni WD%=; bra.uni WL%=; WD%=: }" \
            :: "r"(_m), "r"(_p) : "memory"); \
    } } while (0)

__device__ __forceinline__ int ld_acq(const int* p) {
    int v;
    asm volatile("ld.acquire.gpu.global.s32 %0, [%1];" : "=r"(v) : "l"(p) : "memory");
    return v;
}
__device__ __forceinline__ void red_rel_add1(int* p) {
    asm volatile("red.release.gpu.global.add.s32 [%0], %1;" :: "l"(p), "r"(1) : "memory");
}

__device__ __forceinline__ void ldsm4(uint32_t* r, uint32_t addr) {
    asm volatile("ldmatrix.sync.aligned.m8n8.x4.shared.b16 {%0,%1,%2,%3}, [%4];"
                 : "=r"(r[0]), "=r"(r[1]), "=r"(r[2]), "=r"(r[3]) : "r"(addr));
}
__device__ __forceinline__ void mma_f16(float* c, const uint32_t* a, const uint32_t* b) {
    asm volatile("mma.sync.aligned.m16n8k16.row.col.f32.f16.f16.f32 "
                 "{%0,%1,%2,%3}, {%4,%5,%6,%7}, {%8,%9}, {%0,%1,%2,%3};"
                 : "+f"(c[0]), "+f"(c[1]), "+f"(c[2]), "+f"(c[3])
                 : "r"(a[0]), "r"(a[1]), "r"(a[2]), "r"(a[3]), "r"(b[0]), "r"(b[1]));
}
__device__ __forceinline__ float sigf(float x) { return 1.f / (1.f + expf(-x)); }

// ---------------- prep kernels ---------------------------------------------
__global__ void prep_w_kernel(const float* __restrict__ W_ih, const float* __restrict__ W_hh,
                              const float* __restrict__ b_ih, const float* __restrict__ b_hh) {
    size_t idx = (size_t)blockIdx.x * blockDim.x + threadIdx.x;
    const size_t total = (size_t)L_ * NG * KK;
    if (idx < total) {
        int l = (int)(idx / ((size_t)NG * KK));
        size_t r = idx % ((size_t)NG * KK);
        int n = (int)(r / KK), k = (int)(r % KK);
        int oc = (n & 3) * HD_ + (n >> 2);
        float v = (k < D_) ? W_ih[((size_t)l * NG + oc) * D_ + k]
                           : W_hh[((size_t)l * NG + oc) * HD_ + (k - D_)];
        size_t blk = ((size_t)l * 16 + (n >> 7)) * 16 + (k >> 6);
        uint8_t* p = g_Wt + blk * TB + (uint32_t)(n & 127) * ROWB + (uint32_t)(k & 63) * 2;
        *(__half*)p = __float2half(v);
    }
    if (idx < (size_t)L_ * NG) {
        int l = (int)(idx / NG), n = (int)(idx % NG);
        int oc = (n & 3) * HD_ + (n >> 2);
        g_bias[idx] = b_ih[(size_t)l * NG + oc] + b_hh[(size_t)l * NG + oc];
    }
}

// merged: x tile-split + h-slot(0..L-1)/c zero + scheduler reset + folded output vec
__global__ void prep_misc_kernel(const float* __restrict__ x,
                                 const float* __restrict__ lin2_W, const float* __restrict__ lin2_b,
                                 const float* __restrict__ out_W, const float* __restrict__ out_b) {
    size_t idx = (size_t)blockIdx.x * blockDim.x + threadIdx.x;
    const size_t totx = (size_t)T_ * B_ * D_;
    if (idx < totx) {
        int t = (int)(idx / ((size_t)B_ * D_));
        size_t r = idx % ((size_t)B_ * D_);
        int b = (int)(r / D_), d = (int)(r % D_);
        float v = x[((size_t)b * T_ + t) * D_ + d];
        __half hi = __float2half(v);
        __half lo = __float2half(v - __half2float(hi));
        size_t blk = (size_t)t * 64 + (size_t)(b >> 7) * 8 + (d >> 6);
        uint8_t* p = g_xt + blk * BLKA + (uint32_t)(b & 127) * ROWB + (uint32_t)(d & 63) * 2;
        *(__half*)p = hi;
        *(__half*)(p + TB) = lo;
    }
    // zero h slots 0..L-1 (t=0 recurrent input) incl. padding
    const size_t hz = (size_t)L_ * 64 * BLKA / 4;
    if (idx < hz) ((uint32_t*)g_Ht)[idx] = 0;
    if (idx < (size_t)L_ * B_ * HD_) g_c[idx] = 0.f;
    if (idx < (size_t)(T_ * L_ * 8)) g_cnt[idx] = 0;
    if (idx == 0) {
        g_next = 0;
        int i = 0;
        for (int d = 0; d < T_ + L_ - 1; d++) {
            int lmin = d - (T_ - 1); if (lmin < 0) lmin = 0;
            int lmax = (d < L_ - 1) ? d : (L_ - 1);
            for (int l = lmin; l <= lmax; l++) g_cell_tl[i++] = ((d - l) << 2) | l;
        }
    }
    if (idx < 576) {
        float a = 0.f;
        for (int j = 0; j < HD_; j++) a += out_W[j] * lin2_W[(size_t)j * 576 + idx];
        g_effw[idx] = a;
    } else if (idx == 576) {
        float a = out_b[0];
        for (int j = 0; j < HD_; j++) a += out_W[j] * lin2_b[j];
        g_effw[576] = a;
    }
}

// ---------------- persistent dataflow LSTM ----------------------------------
// fp16 2-pass: A (x/h) split hi/lo fp16, W single fp16. 4-stage bulk-DMA ring.
__global__ __launch_bounds__(NTHR, 1)
void lstm_persist() {
    extern __shared__ __align__(128) char dynsm[];
    __shared__ __align__(8) unsigned long long s_full[NSTAGE], s_empty[NSTAGE];
    __shared__ int s_item;
    const uint32_t smb = smem_u32(dynsm);
    const uint32_t mb_full = smem_u32(s_full);
    const uint32_t mb_empty = smem_u32(s_empty);

    const int tid  = threadIdx.x;
    const int lane = tid & 31;
    const int wid  = tid >> 5;               // 0..15
    const int wm   = (wid & 3) * 32;
    const int wn   = (wid >> 2) * 32;

    const uint32_t a_off = (uint32_t)((wm + (lane & 15)) * ROWB + (lane >> 4) * 16);
    const uint32_t b_row = (uint32_t)(wn + (lane & 7) + ((lane >> 4) << 3));
    const uint32_t b_off = b_row * ROWB + (((lane >> 3) & 1) << 4);

    for (;;) {
        // ---- grab next item; init barriers ---------------------------------
        if (tid == 0) s_item = atomicAdd(&g_next, 1);
        __syncthreads();
        const int item = s_item;
        if (item >= NITEM) break;

        const int cell = item >> 7;
        const int tl = g_cell_tl[cell];
        const int t = tl >> 2, l = tl & 3;
        const int tile = item & 127;
        const int mBi = tile & 7, nBi = tile >> 3;
        const int nBase = nBi * 128;

        if (tid == 0) {
#pragma unroll
            for (int s = 0; s < NSTAGE; s++) {
                MBARRIER_INIT(mb_full + s * 8, 1);       // expect_tx arriver
                MBARRIER_INIT(mb_empty + s * 8, NTHR);   // consumer done-reads
            }
        }
        __syncthreads();

        // block bases for this item
        const uint8_t* wbase = g_Wt + (((size_t)l * 16 + nBi) * 16) * TB;
        const uint8_t* a0base = (l == 0)
            ? g_xt + ((size_t)t * 64 + (size_t)mBi * 8) * BLKA
            : g_Ht + (((size_t)(t + 1) * L_ + (l - 1)) * 64 + (size_t)mBi * 8) * BLKA;  // h(t,l-1)
        const uint8_t* a1base = g_Ht + (((size_t)t * L_ + l) * 64 + (size_t)mBi * 8) * BLKA;  // h(t-1,l)

        auto issue_chunk = [&](int c) {      // tid==0 only
            const int s = c % NSTAGE;
            const uint32_t sb = smb + s * STAGE_BYTES;
            MBARRIER_EXPECT_TX(mb_full + s * 8, (uint32_t)STAGE_BYTES);
            cp_bulk(sb + B_OFF, wbase + (size_t)c * TB, TB, mb_full + s * 8);
            const uint8_t* asrc;
            if (c < 8) {
                if (c == 0 && l > 0) {
                    const int* p = &g_cnt[(t * L_ + (l - 1)) * 8 + mBi];
                    while (ld_acq(p) < 16) __nanosleep(32);
                }
                asrc = a0base + (size_t)c * BLKA;
            } else {
                if (c == 8 && t > 0) {
                    const int* p = &g_cnt[((t - 1) * L_ + l) * 8 + mBi];
                    while (ld_acq(p) < 16) __nanosleep(32);
                }
                asrc = a1base + (size_t)(c - 8) * BLKA;
            }
            cp_bulk(sb + AH_OFF, asrc, BLKA, mb_full + s * 8);
        };

        float acc[2][4][4];
#pragma unroll
        for (int i = 0; i < 2; i++)
#pragma unroll
            for (int j = 0; j < 4; j++)
#pragma unroll
                for (int q = 0; q < 4; q++) acc[i][j][q] = 0.f;

        if (tid == 0) { issue_chunk(0); issue_chunk(1); issue_chunk(2); }

        for (int c = 0; c < NCH; c++) {
            const int s = c % NSTAGE;
            const int k = c / NSTAGE;
            MBARRIER_WAIT_PARITY(mb_full + s * 8, k & 1);
            const uint32_t sb = smb + s * STAGE_BYTES;

#pragma unroll
            for (int kk = 0; kk < 4; kk++) {
                const uint32_t kofs = (uint32_t)(kk * 32);
                uint32_t a_hi[2][4], a_lo[2][4];
#pragma unroll
                for (int mt = 0; mt < 2; mt++) {
                    uint32_t ad = sb + a_off + (uint32_t)(mt * 16 * ROWB) + kofs;
                    ldsm4(a_hi[mt], ad + AH_OFF);
                    ldsm4(a_lo[mt], ad + AL_OFF);
                }
                uint32_t bfr[4][2];
#pragma unroll
                for (int g = 0; g < 2; g++) {
                    uint32_t bd = sb + b_off + (uint32_t)(g * 16 * ROWB) + kofs + B_OFF;
                    uint32_t r[4];
                    ldsm4(r, bd);
                    bfr[2 * g][0] = r[0]; bfr[2 * g][1] = r[1];
                    bfr[2 * g + 1][0] = r[2]; bfr[2 * g + 1][1] = r[3];
                }
#pragma unroll
                for (int mt = 0; mt < 2; mt++)
#pragma unroll
                    for (int nt = 0; nt < 4; nt++) mma_f16(acc[mt][nt], a_hi[mt], bfr[nt]);
#pragma unroll
                for (int mt = 0; mt < 2; mt++)
#pragma unroll
                    for (int nt = 0; nt < 4; nt++) mma_f16(acc[mt][nt], a_lo[mt], bfr[nt]);
            }
            MBARRIER_ARRIVE(mb_empty + s * 8);

            const int c3 = c + 3;
            if (tid == 0 && c3 < NCH) {
                const int s3 = c3 % NSTAGE;
                const int k3 = c3 / NSTAGE;
                if (k3 >= 1) MBARRIER_WAIT_PARITY(mb_empty + s3 * 8, (k3 - 1) & 1);
                issue_chunk(c3);
            }
        }

        // ---- fused LSTM-cell epilogue (h written fp16 hi/lo, tiled) ----------
        {
            const int q = lane & 3;
            const bool active = (q & 1) == 0;
            float* cbase = g_c + (size_t)l * B_ * HD_;
            uint8_t* hb = g_Ht + (((size_t)(t + 1) * L_ + l) * 64 + (size_t)mBi * 8) * BLKA;
            float* ys = (l == 2) ? (g_ys + (size_t)t * B_ * HD_) : nullptr;
            const int mBase = mBi * 128;

#pragma unroll
            for (int mt = 0; mt < 2; mt++) {
#pragma unroll
                for (int nt = 0; nt < 4; nt++) {
                    float* cc = acc[mt][nt];
                    float p0 = __shfl_xor_sync(0xffffffffu, cc[0], 1);
                    float p1 = __shfl_xor_sync(0xffffffffu, cc[1], 1);
                    float p2 = __shfl_xor_sync(0xffffffffu, cc[2], 1);
                    float p3 = __shfl_xor_sync(0xffffffffu, cc[3], 1);
                    if (active) {
                        int n0 = nBase + wn + nt * 8 + q * 2;
                        int j = n0 >> 2;
                        const float4 bs = *(const float4*)&g_bias[l * NG + n0];
                        int r0 = wm + mt * 16 + (lane >> 2);    // row within 128-tile
                        uint8_t* hj = hb + (size_t)(j >> 6) * BLKA + (uint32_t)(j & 63) * 2;
#pragma unroll
                        for (int rg = 0; rg < 2; rg++) {
                            int rowin = r0 + rg * 8;
                            float gi = (rg ? cc[2] : cc[0]) + bs.x;
                            float gf = (rg ? cc[3] : cc[1]) + bs.y;
                            float gg = (rg ? p2 : p0) + bs.z;
                            float go = (rg ? p3 : p1) + bs.w;
                            size_t off = (size_t)(mBase + rowin) * HD_ + j;
                            float cold = cbase[off];
                            float cn = sigf(gf) * cold + sigf(gi) * tanhf(gg);
                            float hn = sigf(go) * tanhf(cn);
                            cbase[off] = cn;
                            __half hi = __float2half(hn);
                            uint8_t* p = hj + (uint32_t)rowin * ROWB;
                            *(__half*)p = hi;
                            *(__half*)(p + TB) = __float2half(hn - __half2float(hi));
                            if (ys) ys[off] = hn;
                        }
                    }
                }
            }
        }

        // publish: stores visible (incl. to async proxy) -> barrier -> release
        __threadfence();
        asm volatile("fence.proxy.async;" ::: "memory");
        __syncthreads();
        if (tid == 0) red_rel_add1(&g_cnt[(t * L_ + l) * 8 + mBi]);
    }
}

// ---------------- attention / TPA head --------------------------------------
#define HEAD_SMEM_FLOATS (32768 + 8064 + 4032 + 512 + 64 + 512 + 64 + 256)

__global__ __launch_bounds__(256)
void head_kernel(const float* __restrict__ conv_W, const float* __restrict__ conv_b,
                 const float* __restrict__ lin1_W, const float* __restrict__ lin1_b,
                 float* __restrict__ out) {
    extern __shared__ float sm[];
    float* conv_s  = sm;                 // [64][512] flat c*512+f
    float* Hblk    = conv_s + 32768;     // [63][128] as float4[63][32]
    float* kW_s    = Hblk + 8064;        // [64][63]
    float* htt_s   = kW_s + 4032;
    float* w_s     = htt_s + 512;
    float* alpha_s = w_s + 64;
    float* v_s     = alpha_s + 512;
    float* red_s   = v_s + 64;

    const int b = blockIdx.x;
    const int tid = threadIdx.x;
    const int lane = tid & 31;
    const int warp = tid >> 5;

    for (int i = tid; i < FN_ * ATT; i += 256) kW_s[i] = conv_W[i];
    for (int i = tid; i < HD_; i += 256)
        htt_s[i] = g_ys[(size_t)(T_ - 1) * B_ * HD_ + (size_t)b * HD_ + i];
    __syncthreads();

    for (int qq = 0; qq < 8; qq++) {
        int qi = warp * 8 + qq;
        float p = 0.f;
        for (int k = lane; k < HD_; k += 32) p += htt_s[k] * lin1_W[(size_t)qi * HD_ + k];
#pragma unroll
        for (int o = 16; o; o >>= 1) p += __shfl_xor_sync(0xffffffffu, p, o);
        if (lane == 0) w_s[qi] = p + lin1_b[qi];
    }

    float4* Hblk4 = (float4*)Hblk;
    float4* conv_s4 = (float4*)conv_s;
    const int fi4 = tid & 31;
    const int cgrp = tid >> 5;
    for (int fb = 0; fb < 4; fb++) {
        int f0 = fb * 128;
        for (int i = tid; i < ATT * 32; i += 256) {
            int tt = i >> 5, f4 = i & 31;
            float4 v = *(const float4*)&g_ys[(size_t)tt * B_ * HD_ + (size_t)b * HD_ + f0 + f4 * 4];
            v.x = fmaxf(v.x, 0.f); v.y = fmaxf(v.y, 0.f);
            v.z = fmaxf(v.z, 0.f); v.w = fmaxf(v.w, 0.f);
            Hblk4[i] = v;
        }
        __syncthreads();

        float4 acc[8];
#pragma unroll
        for (int k = 0; k < 8; k++) {
            float bb = conv_b[cgrp + 8 * k];
            acc[k] = make_float4(bb, bb, bb, bb);
        }
        for (int t = 0; t < ATT; t++) {
            float4 h = Hblk4[t * 32 + fi4];
#pragma unroll
            for (int k = 0; k < 8; k++) {
                float w = kW_s[(cgrp + 8 * k) * ATT + t];
                acc[k].x += w * h.x; acc[k].y += w * h.y;
                acc[k].z += w * h.z; acc[k].w += w * h.w;
            }
        }
#pragma unroll
        for (int k = 0; k < 8; k++) {
            int c = cgrp + 8 * k;
            float4 v = acc[k];
            v.x = fmaxf(v.x, 0.f); v.y = fmaxf(v.y, 0.f);
            v.z = fmaxf(v.z, 0.f); v.w = fmaxf(v.w, 0.f);
            conv_s4[(c << 7) + (f0 >> 2) + fi4] = v;
        }
        __syncthreads();
    }

    for (int p = warp; p < 512; p += 8) {
        float a = conv_s[p * 64 + lane] * w_s[lane]
                + conv_s[p * 64 + 32 + lane] * w_s[32 + lane];
#pragma unroll
        for (int o = 16; o; o >>= 1) a += __shfl_xor_sync(0xffffffffu, a, o);
        if (lane == 0) alpha_s[p] = 1.f / (1.f + expf(-a));
    }
    __syncthreads();

    {
        int qn = tid & 63, part = tid >> 6;
        float a = 0.f;
        for (int p = part; p < 512; p += 4) a += alpha_s[p] * conv_s[p * 64 + qn];
        red_s[tid] = a;
    }
    __syncthreads();
    if (tid < 64) v_s[tid] = red_s[tid] + red_s[64 + tid] + red_s[128 + tid] + red_s[192 + tid];
    __syncthreads();

    float a = 0.f;
    for (int k = tid; k < HD_; k += 256) a += htt_s[k] * g_effw[k];
    if (tid < 64) a += v_s[tid] * g_effw[HD_ + tid];
#pragma unroll
    for (int o = 16; o; o >>= 1) a += __shfl_xor_sync(0xffffffffu, a, o);
    if (lane == 0) red_s[warp] = a;
    __syncthreads();
    if (tid == 0) {
        float tot = g_effw[576];
        for (int i = 0; i < 8; i++) tot += red_s[i];
        out[b] = tot;
    }
}

// ---------------- launch ----------------------------------------------------
extern "C" void kernel_launch(void* const* d_in, const int* in_sizes, int n_in,
                              void* d_out, int out_size) {
    const float* x      = (const float*)d_in[0];
    const float* W_ih   = (const float*)d_in[1];
    const float* W_hh   = (const float*)d_in[2];
    const float* b_ih   = (const float*)d_in[3];
    const float* b_hh   = (const float*)d_in[4];
    const float* conv_W = (const float*)d_in[5];
    const float* conv_b = (const float*)d_in[6];
    const float* lin1_W = (const float*)d_in[7];
    const float* lin1_b = (const float*)d_in[8];
    const float* lin2_W = (const float*)d_in[9];
    const float* lin2_b = (const float*)d_in[10];
    const float* out_W  = (const float*)d_in[11];
    const float* out_b  = (const float*)d_in[12];
    float* out = (float*)d_out;

    {   // prep (2 launches)
        size_t tw = (size_t)L_ * NG * KK;
        prep_w_kernel<<<(unsigned)((tw + 255) / 256), 256>>>(W_ih, W_hh, b_ih, b_hh);
        size_t tx = (size_t)T_ * B_ * D_;
        prep_misc_kernel<<<(unsigned)((tx + 255) / 256), 256>>>(x, lin2_W, lin2_b, out_W, out_b);
    }

    // persistent dataflow wavefront (single launch for all 192 cells)
    cudaFuncSetAttribute(lstm_persist, cudaFuncAttributeMaxDynamicSharedMemorySize, DYN_SMEM);
    lstm_persist<<<NPERS, NTHR, DYN_SMEM>>>();

    // head
    cudaFuncSetAttribute(head_kernel, cudaFuncAttributeMaxDynamicSharedMemorySize,
                         HEAD_SMEM_FLOATS * (int)sizeof(float));
    head_kernel<<<B_, 256, HEAD_SMEM_FLOATS * (int)sizeof(float)>>>(
        conv_W, conv_b, lin1_W, lin1_b, out);
}

// round 15
// speedup vs baseline: 2.8543x; 1.4866x over previous
#include <cuda_runtime.h>
#include <cuda_bf16.h>
#include <cuda_fp16.h>
#include <math.h>
#include <stdint.h>

// ---------------- problem constants ----------------------------------------
#define B_ 1024
#define T_ 64
#define D_ 512
#define HD_ 512
#define L_ 3
#define NG 2048          // 4*HD gate columns (gate-interleaved)
#define KK 1024          // D + HD fused K
#define FN_ 64
#define ATT 63
#define NCELL (T_ * L_)          // 192
#define NITEM (NCELL * 128)      // 24576 tiles

// tile geometry (global layout == smem stage image)
#define KCH 64
#define NCH (KK / KCH)            // 16 chunks
#define ROWB 144                  // 128B payload + 16B pad (conflict-free ldmatrix)
#define TB 18432                  // one 128-row tile (128*ROWB)
#define A_OFF 0
#define B_OFF (TB)
#define STAGE_BYTES (2 * TB)      // 36864
#define NSTAGE 6
#define PREF 5
#define DYN_SMEM (NSTAGE * STAGE_BYTES)  // 221184 (1 CTA/SM)
#define NTHR 512
#define NPERS 148

// ---------------- device scratch (tiled operand storage, all fp16) ----------
// W tiled: [l][nBi(16)][chunk(16)] x TB
__device__ __align__(128) uint8_t g_Wt[(size_t)L_ * 16 * 16 * TB];
// x tiled: [t][mBi(8)][chunk(8)] x TB
__device__ __align__(128) uint8_t g_xt[(size_t)T_ * 64 * TB];
// h tiled, write-once: slot s = t+1 holds h(t,l)
__device__ __align__(128) uint8_t g_Ht[(size_t)(T_ + 1) * L_ * 64 * TB];
__device__ float g_c[(size_t)L_ * B_ * HD_];
__device__ __align__(16) float g_bias[L_ * NG];
__device__ __align__(16) float g_ys[(size_t)T_ * B_ * HD_];
__device__ float g_effw[577];
// dataflow scheduling state
__device__ int g_next;
__device__ int g_cnt[T_ * L_ * 8];     // [t][l][mBi] -> arrives 0..16
__device__ int g_cell_tl[NCELL];       // diagonal-major (t<<2)|l

// ---------------- small asm helpers ----------------------------------------
__device__ __forceinline__ uint32_t smem_u32(const void* p) {
    uint32_t a;
    asm("{ .reg .u64 t; cvta.to.shared.u64 t, %1; cvt.u32.u64 %0, t; }" : "=r"(a) : "l"(p));
    return a;
}
__device__ __forceinline__ void cp_bulk(uint32_t dst, const void* src, uint32_t bytes, uint32_t mbar) {
    asm volatile("cp.async.bulk.shared::cluster.global.mbarrier::complete_tx::bytes [%0], [%1], %2, [%3];"
                 :: "r"(dst), "l"(src), "r"(bytes), "r"(mbar) : "memory");
}
#define MBARRIER_INIT(addr, cnt) \
    asm volatile("mbarrier.init.shared.b64 [%0], %1;" :: "r"((uint32_t)(addr)), "r"((uint32_t)(cnt)) : "memory")
#define MBARRIER_ARRIVE(addr) \
    asm volatile("mbarrier.arrive.shared.b64 _, [%0];" :: "r"((uint32_t)(addr)) : "memory")
#define MBARRIER_EXPECT_TX(addr, tx) \
    asm volatile("mbarrier.arrive.expect_tx.shared.b64 _, [%0], %1;" :: "r"((uint32_t)(addr)), "r"((uint32_t)(tx)) : "memory")
#define MBARRIER_WAIT_PARITY(addr, par) do { \
    uint32_t _m = (uint32_t)(addr); uint32_t _p = (uint32_t)(par); uint32_t _d; \
    asm volatile("{ .reg .pred p; mbarrier.try_wait.parity.acquire.cta.shared::cta.b64 p, [%1], %2; selp.b32 %0,1,0,p; }" \
        : "=r"(_d) : "r"(_m), "r"(_p) : "memory"); \
    if (!_d) { \
        asm volatile("{ .reg .pred P1; WL%=: mbarrier.try_wait.parity.acquire.cta.shared::cta.b64 P1, [%0], %1, 0x989680; @P1 bra.uni WD%=; bra.uni WL%=; WD%=: }" \
            :: "r"(_m), "r"(_p) : "memory"); \
    } } while (0)

__device__ __forceinline__ int ld_acq(const int* p) {
    int v;
    asm volatile("ld.acquire.gpu.global.s32 %0, [%1];" : "=r"(v) : "l"(p) : "memory");
    return v;
}
__device__ __forceinline__ void red_rel_add1(int* p) {
    asm volatile("red.release.gpu.global.add.s32 [%0], %1;" :: "l"(p), "r"(1) : "memory");
}

__device__ __forceinline__ void ldsm4(uint32_t* r, uint32_t addr) {
    asm volatile("ldmatrix.sync.aligned.m8n8.x4.shared.b16 {%0,%1,%2,%3}, [%4];"
                 : "=r"(r[0]), "=r"(r[1]), "=r"(r[2]), "=r"(r[3]) : "r"(addr));
}
__device__ __forceinline__ void mma_f16(float* c, const uint32_t* a, const uint32_t* b) {
    asm volatile("mma.sync.aligned.m16n8k16.row.col.f32.f16.f16.f32 "
                 "{%0,%1,%2,%3}, {%4,%5,%6,%7}, {%8,%9}, {%0,%1,%2,%3};"
                 : "+f"(c[0]), "+f"(c[1]), "+f"(c[2]), "+f"(c[3])
                 : "r"(a[0]), "r"(a[1]), "r"(a[2]), "r"(a[3]), "r"(b[0]), "r"(b[1]));
}
__device__ __forceinline__ float sigf(float x) { return 1.f / (1.f + expf(-x)); }

// ---------------- prep kernels ---------------------------------------------
__global__ void prep_w_kernel(const float* __restrict__ W_ih, const float* __restrict__ W_hh,
                              const float* __restrict__ b_ih, const float* __restrict__ b_hh) {
    size_t idx = (size_t)blockIdx.x * blockDim.x + threadIdx.x;
    const size_t total = (size_t)L_ * NG * KK;
    if (idx < total) {
        int l = (int)(idx / ((size_t)NG * KK));
        size_t r = idx % ((size_t)NG * KK);
        int n = (int)(r / KK), k = (int)(r % KK);
        int oc = (n & 3) * HD_ + (n >> 2);
        float v = (k < D_) ? W_ih[((size_t)l * NG + oc) * D_ + k]
                           : W_hh[((size_t)l * NG + oc) * HD_ + (k - D_)];
        size_t blk = ((size_t)l * 16 + (n >> 7)) * 16 + (k >> 6);
        uint8_t* p = g_Wt + blk * TB + (uint32_t)(n & 127) * ROWB + (uint32_t)(k & 63) * 2;
        *(__half*)p = __float2half(v);
    }
    if (idx < (size_t)L_ * NG) {
        int l = (int)(idx / NG), n = (int)(idx % NG);
        int oc = (n & 3) * HD_ + (n >> 2);
        g_bias[idx] = b_ih[(size_t)l * NG + oc] + b_hh[(size_t)l * NG + oc];
    }
}

// merged: x tile-split + h-slot(0..L-1)/c zero + scheduler reset + folded output vec
__global__ void prep_misc_kernel(const float* __restrict__ x,
                                 const float* __restrict__ lin2_W, const float* __restrict__ lin2_b,
                                 const float* __restrict__ out_W, const float* __restrict__ out_b) {
    size_t idx = (size_t)blockIdx.x * blockDim.x + threadIdx.x;
    const size_t totx = (size_t)T_ * B_ * D_;
    if (idx < totx) {
        int t = (int)(idx / ((size_t)B_ * D_));
        size_t r = idx % ((size_t)B_ * D_);
        int b = (int)(r / D_), d = (int)(r % D_);
        float v = x[((size_t)b * T_ + t) * D_ + d];
        size_t blk = (size_t)t * 64 + (size_t)(b >> 7) * 8 + (d >> 6);
        uint8_t* p = g_xt + blk * TB + (uint32_t)(b & 127) * ROWB + (uint32_t)(d & 63) * 2;
        *(__half*)p = __float2half(v);
    }
    // zero h slots 0..L-1 (t=0 recurrent input) incl. padding
    const size_t hz = (size_t)L_ * 64 * TB / 4;
    if (idx < hz) ((uint32_t*)g_Ht)[idx] = 0;
    if (idx < (size_t)L_ * B_ * HD_) g_c[idx] = 0.f;
    if (idx < (size_t)(T_ * L_ * 8)) g_cnt[idx] = 0;
    if (idx == 0) {
        g_next = 0;
        int i = 0;
        for (int d = 0; d < T_ + L_ - 1; d++) {
            int lmin = d - (T_ - 1); if (lmin < 0) lmin = 0;
            int lmax = (d < L_ - 1) ? d : (L_ - 1);
            for (int l = lmin; l <= lmax; l++) g_cell_tl[i++] = ((d - l) << 2) | l;
        }
    }
    if (idx < 576) {
        float a = 0.f;
        for (int j = 0; j < HD_; j++) a += out_W[j] * lin2_W[(size_t)j * 576 + idx];
        g_effw[idx] = a;
    } else if (idx == 576) {
        float a = out_b[0];
        for (int j = 0; j < HD_; j++) a += out_W[j] * lin2_b[j];
        g_effw[576] = a;
    }
}

// ---------------- persistent dataflow LSTM ----------------------------------
// single-pass fp16 GEMM; 6-stage bulk-DMA ring (prefetch 5).
__global__ __launch_bounds__(NTHR, 1)
void lstm_persist() {
    extern __shared__ __align__(128) char dynsm[];
    __shared__ __align__(8) unsigned long long s_full[NSTAGE], s_empty[NSTAGE];
    __shared__ int s_item;
    const uint32_t smb = smem_u32(dynsm);
    const uint32_t mb_full = smem_u32(s_full);
    const uint32_t mb_empty = smem_u32(s_empty);

    const int tid  = threadIdx.x;
    const int lane = tid & 31;
    const int wid  = tid >> 5;               // 0..15
    const int wm   = (wid & 3) * 32;
    const int wn   = (wid >> 2) * 32;

    const uint32_t a_off = (uint32_t)((wm + (lane & 15)) * ROWB + (lane >> 4) * 16);
    const uint32_t b_row = (uint32_t)(wn + (lane & 7) + ((lane >> 4) << 3));
    const uint32_t b_off = b_row * ROWB + (((lane >> 3) & 1) << 4);

    for (;;) {
        // ---- grab next item; init barriers ---------------------------------
        if (tid == 0) s_item = atomicAdd(&g_next, 1);
        __syncthreads();
        const int item = s_item;
        if (item >= NITEM) break;

        const int cell = item >> 7;
        const int tl = g_cell_tl[cell];
        const int t = tl >> 2, l = tl & 3;
        const int tile = item & 127;
        const int mBi = tile & 7, nBi = tile >> 3;
        const int nBase = nBi * 128;

        if (tid == 0) {
#pragma unroll
            for (int s = 0; s < NSTAGE; s++) {
                MBARRIER_INIT(mb_full + s * 8, 1);       // expect_tx arriver
                MBARRIER_INIT(mb_empty + s * 8, NTHR);   // consumer done-reads
            }
        }
        __syncthreads();

        // block bases for this item
        const uint8_t* wbase = g_Wt + (((size_t)l * 16 + nBi) * 16) * TB;
        const uint8_t* a0base = (l == 0)
            ? g_xt + ((size_t)t * 64 + (size_t)mBi * 8) * TB
            : g_Ht + (((size_t)(t + 1) * L_ + (l - 1)) * 64 + (size_t)mBi * 8) * TB;  // h(t,l-1)
        const uint8_t* a1base = g_Ht + (((size_t)t * L_ + l) * 64 + (size_t)mBi * 8) * TB;  // h(t-1,l)

        auto issue_chunk = [&](int c) {      // tid==0 only
            const int s = c % NSTAGE;
            const uint32_t sb = smb + s * STAGE_BYTES;
            MBARRIER_EXPECT_TX(mb_full + s * 8, (uint32_t)STAGE_BYTES);
            cp_bulk(sb + B_OFF, wbase + (size_t)c * TB, TB, mb_full + s * 8);
            const uint8_t* asrc;
            if (c < 8) {
                if (c == 0 && l > 0) {
                    const int* p = &g_cnt[(t * L_ + (l - 1)) * 8 + mBi];
                    while (ld_acq(p) < 16) __nanosleep(32);
                }
                asrc = a0base + (size_t)c * TB;
            } else {
                if (c == 8 && t > 0) {
                    const int* p = &g_cnt[((t - 1) * L_ + l) * 8 + mBi];
                    while (ld_acq(p) < 16) __nanosleep(32);
                }
                asrc = a1base + (size_t)(c - 8) * TB;
            }
            cp_bulk(sb + A_OFF, asrc, TB, mb_full + s * 8);
        };

        float acc[2][4][4];
#pragma unroll
        for (int i = 0; i < 2; i++)
#pragma unroll
            for (int j = 0; j < 4; j++)
#pragma unroll
                for (int q = 0; q < 4; q++) acc[i][j][q] = 0.f;

        if (tid == 0)
            for (int c0 = 0; c0 < PREF; c0++) issue_chunk(c0);

        for (int c = 0; c < NCH; c++) {
            const int s = c % NSTAGE;
            const int k = c / NSTAGE;
            MBARRIER_WAIT_PARITY(mb_full + s * 8, k & 1);
            const uint32_t sb = smb + s * STAGE_BYTES;

#pragma unroll
            for (int kk = 0; kk < 4; kk++) {
                const uint32_t kofs = (uint32_t)(kk * 32);
                uint32_t afr[2][4];
#pragma unroll
                for (int mt = 0; mt < 2; mt++) {
                    uint32_t ad = sb + a_off + (uint32_t)(mt * 16 * ROWB) + kofs + A_OFF;
                    ldsm4(afr[mt], ad);
                }
                uint32_t bfr[4][2];
#pragma unroll
                for (int g = 0; g < 2; g++) {
                    uint32_t bd = sb + b_off + (uint32_t)(g * 16 * ROWB) + kofs + B_OFF;
                    uint32_t r[4];
                    ldsm4(r, bd);
                    bfr[2 * g][0] = r[0]; bfr[2 * g][1] = r[1];
                    bfr[2 * g + 1][0] = r[2]; bfr[2 * g + 1][1] = r[3];
                }
#pragma unroll
                for (int mt = 0; mt < 2; mt++)
#pragma unroll
                    for (int nt = 0; nt < 4; nt++) mma_f16(acc[mt][nt], afr[mt], bfr[nt]);
            }
            MBARRIER_ARRIVE(mb_empty + s * 8);

            const int cp = c + PREF;
            if (tid == 0 && cp < NCH) {
                const int sp = cp % NSTAGE;
                const int kp = cp / NSTAGE;
                if (kp >= 1) MBARRIER_WAIT_PARITY(mb_empty + sp * 8, (kp - 1) & 1);
                issue_chunk(cp);
            }
        }

        // ---- fused LSTM-cell epilogue (h written fp16, tiled) ----------------
        {
            const int q = lane & 3;
            const bool active = (q & 1) == 0;
            float* cbase = g_c + (size_t)l * B_ * HD_;
            uint8_t* hb = g_Ht + (((size_t)(t + 1) * L_ + l) * 64 + (size_t)mBi * 8) * TB;
            float* ys = (l == 2) ? (g_ys + (size_t)t * B_ * HD_) : nullptr;
            const int mBase = mBi * 128;

#pragma unroll
            for (int mt = 0; mt < 2; mt++) {
#pragma unroll
                for (int nt = 0; nt < 4; nt++) {
                    float* cc = acc[mt][nt];
                    float p0 = __shfl_xor_sync(0xffffffffu, cc[0], 1);
                    float p1 = __shfl_xor_sync(0xffffffffu, cc[1], 1);
                    float p2 = __shfl_xor_sync(0xffffffffu, cc[2], 1);
                    float p3 = __shfl_xor_sync(0xffffffffu, cc[3], 1);
                    if (active) {
                        int n0 = nBase + wn + nt * 8 + q * 2;
                        int j = n0 >> 2;
                        const float4 bs = *(const float4*)&g_bias[l * NG + n0];
                        int r0 = wm + mt * 16 + (lane >> 2);    // row within 128-tile
                        uint8_t* hj = hb + (size_t)(j >> 6) * TB + (uint32_t)(j & 63) * 2;
#pragma unroll
                        for (int rg = 0; rg < 2; rg++) {
                            int rowin = r0 + rg * 8;
                            float gi = (rg ? cc[2] : cc[0]) + bs.x;
                            float gf = (rg ? cc[3] : cc[1]) + bs.y;
                            float gg = (rg ? p2 : p0) + bs.z;
                            float go = (rg ? p3 : p1) + bs.w;
                            size_t off = (size_t)(mBase + rowin) * HD_ + j;
                            float cold = cbase[off];
                            float cn = sigf(gf) * cold + sigf(gi) * tanhf(gg);
                            float hn = sigf(go) * tanhf(cn);
                            cbase[off] = cn;
                            *(__half*)(hj + (uint32_t)rowin * ROWB) = __float2half(hn);
                            if (ys) ys[off] = hn;
                        }
                    }
                }
            }
        }

        // publish: stores visible (incl. to async proxy) -> barrier -> release
        __threadfence();
        asm volatile("fence.proxy.async;" ::: "memory");
        __syncthreads();
        if (tid == 0) red_rel_add1(&g_cnt[(t * L_ + l) * 8 + mBi]);
    }
}

// ---------------- attention / TPA head --------------------------------------
#define HEAD_SMEM_FLOATS (32768 + 8064 + 4032 + 512 + 64 + 512 + 64 + 256)

__global__ __launch_bounds__(256)
void head_kernel(const float* __restrict__ conv_W, const float* __restrict__ conv_b,
                 const float* __restrict__ lin1_W, const float* __restrict__ lin1_b,
                 float* __restrict__ out) {
    extern __shared__ float sm[];
    float* conv_s  = sm;                 // [64][512] flat c*512+f
    float* Hblk    = conv_s + 32768;     // [63][128] as float4[63][32]
    float* kW_s    = Hblk + 8064;        // [64][63]
    float* htt_s   = kW_s + 4032;
    float* w_s     = htt_s + 512;
    float* alpha_s = w_s + 64;
    float* v_s     = alpha_s + 512;
    float* red_s   = v_s + 64;

    const int b = blockIdx.x;
    const int tid = threadIdx.x;
    const int lane = tid & 31;
    const int warp = tid >> 5;

    for (int i = tid; i < FN_ * ATT; i += 256) kW_s[i] = conv_W[i];
    for (int i = tid; i < HD_; i += 256)
        htt_s[i] = g_ys[(size_t)(T_ - 1) * B_ * HD_ + (size_t)b * HD_ + i];
    __syncthreads();

    for (int qq = 0; qq < 8; qq++) {
        int qi = warp * 8 + qq;
        float p = 0.f;
        for (int k = lane; k < HD_; k += 32) p += htt_s[k] * lin1_W[(size_t)qi * HD_ + k];
#pragma unroll
        for (int o = 16; o; o >>= 1) p += __shfl_xor_sync(0xffffffffu, p, o);
        if (lane == 0) w_s[qi] = p + lin1_b[qi];
    }

    float4* Hblk4 = (float4*)Hblk;
    float4* conv_s4 = (float4*)conv_s;
    const int fi4 = tid & 31;
    const int cgrp = tid >> 5;
    for (int fb = 0; fb < 4; fb++) {
        int f0 = fb * 128;
        for (int i = tid; i < ATT * 32; i += 256) {
            int tt = i >> 5, f4 = i & 31;
            float4 v = *(const float4*)&g_ys[(size_t)tt * B_ * HD_ + (size_t)b * HD_ + f0 + f4 * 4];
            v.x = fmaxf(v.x, 0.f); v.y = fmaxf(v.y, 0.f);
            v.z = fmaxf(v.z, 0.f); v.w = fmaxf(v.w, 0.f);
            Hblk4[i] = v;
        }
        __syncthreads();

        float4 acc[8];
#pragma unroll
        for (int k = 0; k < 8; k++) {
            float bb = conv_b[cgrp + 8 * k];
            acc[k] = make_float4(bb, bb, bb, bb);
        }
        for (int t = 0; t < ATT; t++) {
            float4 h = Hblk4[t * 32 + fi4];
#pragma unroll
            for (int k = 0; k < 8; k++) {
                float w = kW_s[(cgrp + 8 * k) * ATT + t];
                acc[k].x += w * h.x; acc[k].y += w * h.y;
                acc[k].z += w * h.z; acc[k].w += w * h.w;
            }
        }
#pragma unroll
        for (int k = 0; k < 8; k++) {
            int c = cgrp + 8 * k;
            float4 v = acc[k];
            v.x = fmaxf(v.x, 0.f); v.y = fmaxf(v.y, 0.f);
            v.z = fmaxf(v.z, 0.f); v.w = fmaxf(v.w, 0.f);
            conv_s4[(c << 7) + (f0 >> 2) + fi4] = v;
        }
        __syncthreads();
    }

    for (int p = warp; p < 512; p += 8) {
        float a = conv_s[p * 64 + lane] * w_s[lane]
                + conv_s[p * 64 + 32 + lane] * w_s[32 + lane];
#pragma unroll
        for (int o = 16; o; o >>= 1) a += __shfl_xor_sync(0xffffffffu, a, o);
        if (lane == 0) alpha_s[p] = 1.f / (1.f + expf(-a));
    }
    __syncthreads();

    {
        int qn = tid & 63, part = tid >> 6;
        float a = 0.f;
        for (int p = part; p < 512; p += 4) a += alpha_s[p] * conv_s[p * 64 + qn];
        red_s[tid] = a;
    }
    __syncthreads();
    if (tid < 64) v_s[tid] = red_s[tid] + red_s[64 + tid] + red_s[128 + tid] + red_s[192 + tid];
    __syncthreads();

    float a = 0.f;
    for (int k = tid; k < HD_; k += 256) a += htt_s[k] * g_effw[k];
    if (tid < 64) a += v_s[tid] * g_effw[HD_ + tid];
#pragma unroll
    for (int o = 16; o; o >>= 1) a += __shfl_xor_sync(0xffffffffu, a, o);
    if (lane == 0) red_s[warp] = a;
    __syncthreads();
    if (tid == 0) {
        float tot = g_effw[576];
        for (int i = 0; i < 8; i++) tot += red_s[i];
        out[b] = tot;
    }
}

// ---------------- launch ----------------------------------------------------
extern "C" void kernel_launch(void* const* d_in, const int* in_sizes, int n_in,
                              void* d_out, int out_size) {
    const float* x      = (const float*)d_in[0];
    const float* W_ih   = (const float*)d_in[1];
    const float* W_hh   = (const float*)d_in[2];
    const float* b_ih   = (const float*)d_in[3];
    const float* b_hh   = (const float*)d_in[4];
    const float* conv_W = (const float*)d_in[5];
    const float* conv_b = (const float*)d_in[6];
    const float* lin1_W = (const float*)d_in[7];
    const float* lin1_b = (const float*)d_in[8];
    const float* lin2_W = (const float*)d_in[9];
    const float* lin2_b = (const float*)d_in[10];
    const float* out_W  = (const float*)d_in[11];
    const float* out_b  = (const float*)d_in[12];
    float* out = (float*)d_out;

    {   // prep (2 launches)
        size_t tw = (size_t)L_ * NG * KK;
        prep_w_kernel<<<(unsigned)((tw + 255) / 256), 256>>>(W_ih, W_hh, b_ih, b_hh);
        size_t tx = (size_t)T_ * B_ * D_;
        prep_misc_kernel<<<(unsigned)((tx + 255) / 256), 256>>>(x, lin2_W, lin2_b, out_W, out_b);
    }

    // persistent dataflow wavefront (single launch for all 192 cells)
    cudaFuncSetAttribute(lstm_persist, cudaFuncAttributeMaxDynamicSharedMemorySize, DYN_SMEM);
    lstm_persist<<<NPERS, NTHR, DYN_SMEM>>>();

    // head
    cudaFuncSetAttribute(head_kernel, cudaFuncAttributeMaxDynamicSharedMemorySize,
                         HEAD_SMEM_FLOATS * (int)sizeof(float));
    head_kernel<<<B_, 256, HEAD_SMEM_FLOATS * (int)sizeof(float)>>>(
        conv_W, conv_b, lin1_W, lin1_b, out);
}

// round 16
// speedup vs baseline: 3.2779x; 1.1484x over previous
#include <cuda_runtime.h>
#include <cuda_bf16.h>
#include <cuda_fp16.h>
#include <math.h>
#include <stdint.h>

// ---------------- problem constants ----------------------------------------
#define B_ 1024
#define T_ 64
#define D_ 512
#define HD_ 512
#define L_ 3
#define NG 2048          // 4*HD gate columns (gate-interleaved)
#define KK 1024          // D + HD fused K
#define FN_ 64
#define ATT 63
#define NCELL (T_ * L_)          // 192
#define NITEM (NCELL * 64)       // 12288 items (128x256 tiles)

// tile geometry (global layout == smem stage image)
#define KCH 64
#define NCH (KK / KCH)            // 16 chunks
#define ROWB 144                  // 128B payload + 16B pad (conflict-free ldmatrix)
#define TB 18432                  // A tile: 128 rows (128*ROWB)
#define TBB 36864                 // B tile: 256 rows (256*ROWB)
#define A_OFF 0
#define B_OFF (TB)
#define STAGE_BYTES (TB + TBB)    // 55296
#define NSTAGE 4
#define PREF 3
#define DYN_SMEM (NSTAGE * STAGE_BYTES)  // 221184 (1 CTA/SM)
#define NTHR 512
#define NPERS 148

// ---------------- device scratch (tiled operand storage, all fp16) ----------
// W tiled: [l][nBi2(8)][chunk(16)] x TBB (256 gate-rows per block)
__device__ __align__(128) uint8_t g_Wt[(size_t)L_ * 8 * 16 * TBB];
// x tiled: [t][mBi(8)][chunk(8)] x TB
__device__ __align__(128) uint8_t g_xt[(size_t)T_ * 64 * TB];
// h tiled, write-once: slot s = t+1 holds h(t,l)
__device__ __align__(128) uint8_t g_Ht[(size_t)(T_ + 1) * L_ * 64 * TB];
__device__ float g_c[(size_t)L_ * B_ * HD_];
__device__ __align__(16) float g_bias[L_ * NG];
__device__ __align__(16) float g_ys[(size_t)T_ * B_ * HD_];
__device__ float g_effw[577];
// dataflow scheduling state
__device__ int g_next;
__device__ int g_cnt[T_ * L_ * 8];     // [t][l][mBi] -> arrives 0..8
__device__ int g_cell_tl[NCELL];       // diagonal-major (t<<2)|l

// ---------------- small asm helpers ----------------------------------------
__device__ __forceinline__ uint32_t smem_u32(const void* p) {
    uint32_t a;
    asm("{ .reg .u64 t; cvta.to.shared.u64 t, %1; cvt.u32.u64 %0, t; }" : "=r"(a) : "l"(p));
    return a;
}
__device__ __forceinline__ void cp_bulk(uint32_t dst, const void* src, uint32_t bytes, uint32_t mbar) {
    asm volatile("cp.async.bulk.shared::cluster.global.mbarrier::complete_tx::bytes [%0], [%1], %2, [%3];"
                 :: "r"(dst), "l"(src), "r"(bytes), "r"(mbar) : "memory");
}
#define MBARRIER_INIT(addr, cnt) \
    asm volatile("mbarrier.init.shared.b64 [%0], %1;" :: "r"((uint32_t)(addr)), "r"((uint32_t)(cnt)) : "memory")
#define MBARRIER_ARRIVE(addr) \
    asm volatile("mbarrier.arrive.shared.b64 _, [%0];" :: "r"((uint32_t)(addr)) : "memory")
#define MBARRIER_EXPECT_TX(addr, tx) \
    asm volatile("mbarrier.arrive.expect_tx.shared.b64 _, [%0], %1;" :: "r"((uint32_t)(addr)), "r"((uint32_t)(tx)) : "memory")
#define MBARRIER_WAIT_PARITY(addr, par) do { \
    uint32_t _m = (uint32_t)(addr); uint32_t _p = (uint32_t)(par); uint32_t _d; \
    asm volatile("{ .reg .pred p; mbarrier.try_wait.parity.acquire.cta.shared::cta.b64 p, [%1], %2; selp.b32 %0,1,0,p; }" \
        : "=r"(_d) : "r"(_m), "r"(_p) : "memory"); \
    if (!_d) { \
        asm volatile("{ .reg .pred P1; WL%=: mbarrier.try_wait.parity.acquire.cta.shared::cta.b64 P1, [%0], %1, 0x989680; @P1 bra.uni WD%=; bra.uni WL%=; WD%=: }" \
            :: "r"(_m), "r"(_p) : "memory"); \
    } } while (0)

__device__ __forceinline__ int ld_acq(const int* p) {
    int v;
    asm volatile("ld.acquire.gpu.global.s32 %0, [%1];" : "=r"(v) : "l"(p) : "memory");
    return v;
}
__device__ __forceinline__ void red_rel_add1(int* p) {
    asm volatile("red.release.gpu.global.add.s32 [%0], %1;" :: "l"(p), "r"(1) : "memory");
}

__device__ __forceinline__ void ldsm4(uint32_t* r, uint32_t addr) {
    asm volatile("ldmatrix.sync.aligned.m8n8.x4.shared.b16 {%0,%1,%2,%3}, [%4];"
                 : "=r"(r[0]), "=r"(r[1]), "=r"(r[2]), "=r"(r[3]) : "r"(addr));
}
__device__ __forceinline__ void mma_f16(float* c, const uint32_t* a, const uint32_t* b) {
    asm volatile("mma.sync.aligned.m16n8k16.row.col.f32.f16.f16.f32 "
                 "{%0,%1,%2,%3}, {%4,%5,%6,%7}, {%8,%9}, {%0,%1,%2,%3};"
                 : "+f"(c[0]), "+f"(c[1]), "+f"(c[2]), "+f"(c[3])
                 : "r"(a[0]), "r"(a[1]), "r"(a[2]), "r"(a[3]), "r"(b[0]), "r"(b[1]));
}
__device__ __forceinline__ float sigf(float x) { return 1.f / (1.f + expf(-x)); }

// ---------------- prep kernels ---------------------------------------------
__global__ void prep_w_kernel(const float* __restrict__ W_ih, const float* __restrict__ W_hh,
                              const float* __restrict__ b_ih, const float* __restrict__ b_hh) {
    size_t idx = (size_t)blockIdx.x * blockDim.x + threadIdx.x;
    const size_t total = (size_t)L_ * NG * KK;
    if (idx < total) {
        int l = (int)(idx / ((size_t)NG * KK));
        size_t r = idx % ((size_t)NG * KK);
        int n = (int)(r / KK), k = (int)(r % KK);
        int oc = (n & 3) * HD_ + (n >> 2);
        float v = (k < D_) ? W_ih[((size_t)l * NG + oc) * D_ + k]
                           : W_hh[((size_t)l * NG + oc) * HD_ + (k - D_)];
        size_t blk = ((size_t)l * 8 + (n >> 8)) * 16 + (k >> 6);
        uint8_t* p = g_Wt + blk * TBB + (uint32_t)(n & 255) * ROWB + (uint32_t)(k & 63) * 2;
        *(__half*)p = __float2half(v);
    }
    if (idx < (size_t)L_ * NG) {
        int l = (int)(idx / NG), n = (int)(idx % NG);
        int oc = (n & 3) * HD_ + (n >> 2);
        g_bias[idx] = b_ih[(size_t)l * NG + oc] + b_hh[(size_t)l * NG + oc];
    }
}

// merged: x tile-split + h-slot(0..L-1)/c zero + scheduler reset + folded output vec
__global__ void prep_misc_kernel(const float* __restrict__ x,
                                 const float* __restrict__ lin2_W, const float* __restrict__ lin2_b,
                                 const float* __restrict__ out_W, const float* __restrict__ out_b) {
    size_t idx = (size_t)blockIdx.x * blockDim.x + threadIdx.x;
    const size_t totx = (size_t)T_ * B_ * D_;
    if (idx < totx) {
        int t = (int)(idx / ((size_t)B_ * D_));
        size_t r = idx % ((size_t)B_ * D_);
        int b = (int)(r / D_), d = (int)(r % D_);
        float v = x[((size_t)b * T_ + t) * D_ + d];
        size_t blk = (size_t)t * 64 + (size_t)(b >> 7) * 8 + (d >> 6);
        uint8_t* p = g_xt + blk * TB + (uint32_t)(b & 127) * ROWB + (uint32_t)(d & 63) * 2;
        *(__half*)p = __float2half(v);
    }
    // zero h slots 0..L-1 (t=0 recurrent input) incl. padding
    const size_t hz = (size_t)L_ * 64 * TB / 4;
    if (idx < hz) ((uint32_t*)g_Ht)[idx] = 0;
    if (idx < (size_t)L_ * B_ * HD_) g_c[idx] = 0.f;
    if (idx < (size_t)(T_ * L_ * 8)) g_cnt[idx] = 0;
    if (idx == 0) {
        g_next = 0;
        int i = 0;
        for (int d = 0; d < T_ + L_ - 1; d++) {
            int lmin = d - (T_ - 1); if (lmin < 0) lmin = 0;
            int lmax = (d < L_ - 1) ? d : (L_ - 1);
            for (int l = lmin; l <= lmax; l++) g_cell_tl[i++] = ((d - l) << 2) | l;
        }
    }
    if (idx < 576) {
        float a = 0.f;
        for (int j = 0; j < HD_; j++) a += out_W[j] * lin2_W[(size_t)j * 576 + idx];
        g_effw[idx] = a;
    } else if (idx == 576) {
        float a = out_b[0];
        for (int j = 0; j < HD_; j++) a += out_W[j] * lin2_b[j];
        g_effw[576] = a;
    }
}

// ---------------- persistent dataflow LSTM ----------------------------------
// item = 128(M) x 256(N) tile; warp tile 32x64; single-pass fp16 GEMM;
// 4-stage bulk-DMA ring (prefetch 3).
__global__ __launch_bounds__(NTHR, 1)
void lstm_persist() {
    extern __shared__ __align__(128) char dynsm[];
    __shared__ __align__(8) unsigned long long s_full[NSTAGE], s_empty[NSTAGE];
    __shared__ int s_item;
    const uint32_t smb = smem_u32(dynsm);
    const uint32_t mb_full = smem_u32(s_full);
    const uint32_t mb_empty = smem_u32(s_empty);

    const int tid  = threadIdx.x;
    const int lane = tid & 31;
    const int wid  = tid >> 5;               // 0..15
    const int wm   = (wid & 3) * 32;
    const int wn   = (wid >> 2) * 64;        // 4 n-warps x 64

    const uint32_t a_off = (uint32_t)((wm + (lane & 15)) * ROWB + (lane >> 4) * 16);
    const uint32_t b_row = (uint32_t)(wn + (lane & 7) + ((lane >> 4) << 3));
    const uint32_t b_off = b_row * ROWB + (((lane >> 3) & 1) << 4);

    for (;;) {
        // ---- grab next item; init barriers ---------------------------------
        if (tid == 0) s_item = atomicAdd(&g_next, 1);
        __syncthreads();
        const int item = s_item;
        if (item >= NITEM) break;

        const int cell = item >> 6;
        const int tl = g_cell_tl[cell];
        const int t = tl >> 2, l = tl & 3;
        const int tile = item & 63;
        const int mBi = tile & 7, nBi = tile >> 3;       // nBi: 0..7 (256-wide)
        const int nBase = nBi * 256;

        if (tid == 0) {
#pragma unroll
            for (int s = 0; s < NSTAGE; s++) {
                MBARRIER_INIT(mb_full + s * 8, 1);       // expect_tx arriver
                MBARRIER_INIT(mb_empty + s * 8, NTHR);   // consumer done-reads
            }
        }
        __syncthreads();

        // block bases for this item
        const uint8_t* wbase = g_Wt + (((size_t)l * 8 + nBi) * 16) * TBB;
        const uint8_t* a0base = (l == 0)
            ? g_xt + ((size_t)t * 64 + (size_t)mBi * 8) * TB
            : g_Ht + (((size_t)(t + 1) * L_ + (l - 1)) * 64 + (size_t)mBi * 8) * TB;  // h(t,l-1)
        const uint8_t* a1base = g_Ht + (((size_t)t * L_ + l) * 64 + (size_t)mBi * 8) * TB;  // h(t-1,l)

        auto issue_chunk = [&](int c) {      // tid==0 only
            const int s = c % NSTAGE;
            const uint32_t sb = smb + s * STAGE_BYTES;
            MBARRIER_EXPECT_TX(mb_full + s * 8, (uint32_t)STAGE_BYTES);
            cp_bulk(sb + B_OFF, wbase + (size_t)c * TBB, TBB, mb_full + s * 8);
            const uint8_t* asrc;
            if (c < 8) {
                if (c == 0 && l > 0) {
                    const int* p = &g_cnt[(t * L_ + (l - 1)) * 8 + mBi];
                    while (ld_acq(p) < 8) __nanosleep(32);
                }
                asrc = a0base + (size_t)c * TB;
            } else {
                if (c == 8 && t > 0) {
                    const int* p = &g_cnt[((t - 1) * L_ + l) * 8 + mBi];
                    while (ld_acq(p) < 8) __nanosleep(32);
                }
                asrc = a1base + (size_t)(c - 8) * TB;
            }
            cp_bulk(sb + A_OFF, asrc, TB, mb_full + s * 8);
        };

        float acc[2][8][4];
#pragma unroll
        for (int i = 0; i < 2; i++)
#pragma unroll
            for (int j = 0; j < 8; j++)
#pragma unroll
                for (int q = 0; q < 4; q++) acc[i][j][q] = 0.f;

        if (tid == 0)
            for (int c0 = 0; c0 < PREF; c0++) issue_chunk(c0);

        for (int c = 0; c < NCH; c++) {
            const int s = c % NSTAGE;
            const int k = c / NSTAGE;
            MBARRIER_WAIT_PARITY(mb_full + s * 8, k & 1);
            const uint32_t sb = smb + s * STAGE_BYTES;

#pragma unroll
            for (int kk = 0; kk < 4; kk++) {
                const uint32_t kofs = (uint32_t)(kk * 32);
                uint32_t afr[2][4];
#pragma unroll
                for (int mt = 0; mt < 2; mt++) {
                    uint32_t ad = sb + a_off + (uint32_t)(mt * 16 * ROWB) + kofs + A_OFF;
                    ldsm4(afr[mt], ad);
                }
                uint32_t bfr[8][2];
#pragma unroll
                for (int g = 0; g < 4; g++) {
                    uint32_t bd = sb + b_off + (uint32_t)(g * 16 * ROWB) + kofs + B_OFF;
                    uint32_t r[4];
                    ldsm4(r, bd);
                    bfr[2 * g][0] = r[0]; bfr[2 * g][1] = r[1];
                    bfr[2 * g + 1][0] = r[2]; bfr[2 * g + 1][1] = r[3];
                }
#pragma unroll
                for (int mt = 0; mt < 2; mt++)
#pragma unroll
                    for (int nt = 0; nt < 8; nt++) mma_f16(acc[mt][nt], afr[mt], bfr[nt]);
            }
            MBARRIER_ARRIVE(mb_empty + s * 8);

            const int cp = c + PREF;
            if (tid == 0 && cp < NCH) {
                const int sp = cp % NSTAGE;
                const int kp = cp / NSTAGE;
                if (kp >= 1) MBARRIER_WAIT_PARITY(mb_empty + sp * 8, (kp - 1) & 1);
                issue_chunk(cp);
            }
        }

        // ---- fused LSTM-cell epilogue (h written fp16, tiled) ----------------
        {
            const int q = lane & 3;
            const bool active = (q & 1) == 0;
            float* cbase = g_c + (size_t)l * B_ * HD_;
            uint8_t* hb = g_Ht + (((size_t)(t + 1) * L_ + l) * 64 + (size_t)mBi * 8) * TB;
            float* ys = (l == 2) ? (g_ys + (size_t)t * B_ * HD_) : nullptr;
            const int mBase = mBi * 128;

#pragma unroll
            for (int mt = 0; mt < 2; mt++) {
#pragma unroll
                for (int nt = 0; nt < 8; nt++) {
                    float* cc = acc[mt][nt];
                    float p0 = __shfl_xor_sync(0xffffffffu, cc[0], 1);
                    float p1 = __shfl_xor_sync(0xffffffffu, cc[1], 1);
                    float p2 = __shfl_xor_sync(0xffffffffu, cc[2], 1);
                    float p3 = __shfl_xor_sync(0xffffffffu, cc[3], 1);
                    if (active) {
                        int n0 = nBase + wn + nt * 8 + q * 2;
                        int j = n0 >> 2;
                        const float4 bs = *(const float4*)&g_bias[l * NG + n0];
                        int r0 = wm + mt * 16 + (lane >> 2);    // row within 128-tile
                        uint8_t* hj = hb + (size_t)(j >> 6) * TB + (uint32_t)(j & 63) * 2;
#pragma unroll
                        for (int rg = 0; rg < 2; rg++) {
                            int rowin = r0 + rg * 8;
                            float gi = (rg ? cc[2] : cc[0]) + bs.x;
                            float gf = (rg ? cc[3] : cc[1]) + bs.y;
                            float gg = (rg ? p2 : p0) + bs.z;
                            float go = (rg ? p3 : p1) + bs.w;
                            size_t off = (size_t)(mBase + rowin) * HD_ + j;
                            float cold = cbase[off];
                            float cn = sigf(gf) * cold + sigf(gi) * tanhf(gg);
                            float hn = sigf(go) * tanhf(cn);
                            cbase[off] = cn;
                            *(__half*)(hj + (uint32_t)rowin * ROWB) = __float2half(hn);
                            if (ys) ys[off] = hn;
                        }
                    }
                }
            }
        }

        // publish: stores visible (incl. to async proxy) -> barrier -> release
        __threadfence();
        asm volatile("fence.proxy.async;" ::: "memory");
        __syncthreads();
        if (tid == 0) red_rel_add1(&g_cnt[(t * L_ + l) * 8 + mBi]);
    }
}

// ---------------- attention / TPA head --------------------------------------
#define HEAD_SMEM_FLOATS (32768 + 8064 + 4032 + 512 + 64 + 512 + 64 + 256)

__global__ __launch_bounds__(256)
void head_kernel(const float* __restrict__ conv_W, const float* __restrict__ conv_b,
                 const float* __restrict__ lin1_W, const float* __restrict__ lin1_b,
                 float* __restrict__ out) {
    extern __shared__ float sm[];
    float* conv_s  = sm;                 // [64][512] flat c*512+f
    float* Hblk    = conv_s + 32768;     // [63][128] as float4[63][32]
    float* kW_s    = Hblk + 8064;        // [64][63]
    float* htt_s   = kW_s + 4032;
    float* w_s     = htt_s + 512;
    float* alpha_s = w_s + 64;
    float* v_s     = alpha_s + 512;
    float* red_s   = v_s + 64;

    const int b = blockIdx.x;
    const int tid = threadIdx.x;
    const int lane = tid & 31;
    const int warp = tid >> 5;

    for (int i = tid; i < FN_ * ATT; i += 256) kW_s[i] = conv_W[i];
    for (int i = tid; i < HD_; i += 256)
        htt_s[i] = g_ys[(size_t)(T_ - 1) * B_ * HD_ + (size_t)b * HD_ + i];
    __syncthreads();

    for (int qq = 0; qq < 8; qq++) {
        int qi = warp * 8 + qq;
        float p = 0.f;
        for (int k = lane; k < HD_; k += 32) p += htt_s[k] * lin1_W[(size_t)qi * HD_ + k];
#pragma unroll
        for (int o = 16; o; o >>= 1) p += __shfl_xor_sync(0xffffffffu, p, o);
        if (lane == 0) w_s[qi] = p + lin1_b[qi];
    }

    float4* Hblk4 = (float4*)Hblk;
    float4* conv_s4 = (float4*)conv_s;
    const int fi4 = tid & 31;
    const int cgrp = tid >> 5;
    for (int fb = 0; fb < 4; fb++) {
        int f0 = fb * 128;
        for (int i = tid; i < ATT * 32; i += 256) {
            int tt = i >> 5, f4 = i & 31;
            float4 v = *(const float4*)&g_ys[(size_t)tt * B_ * HD_ + (size_t)b * HD_ + f0 + f4 * 4];
            v.x = fmaxf(v.x, 0.f); v.y = fmaxf(v.y, 0.f);
            v.z = fmaxf(v.z, 0.f); v.w = fmaxf(v.w, 0.f);
            Hblk4[i] = v;
        }
        __syncthreads();

        float4 acc[8];
#pragma unroll
        for (int k = 0; k < 8; k++) {
            float bb = conv_b[cgrp + 8 * k];
            acc[k] = make_float4(bb, bb, bb, bb);
        }
        for (int t = 0; t < ATT; t++) {
            float4 h = Hblk4[t * 32 + fi4];
#pragma unroll
            for (int k = 0; k < 8; k++) {
                float w = kW_s[(cgrp + 8 * k) * ATT + t];
                acc[k].x += w * h.x; acc[k].y += w * h.y;
                acc[k].z += w * h.z; acc[k].w += w * h.w;
            }
        }
#pragma unroll
        for (int k = 0; k < 8; k++) {
            int c = cgrp + 8 * k;
            float4 v = acc[k];
            v.x = fmaxf(v.x, 0.f); v.y = fmaxf(v.y, 0.f);
            v.z = fmaxf(v.z, 0.f); v.w = fmaxf(v.w, 0.f);
            conv_s4[(c << 7) + (f0 >> 2) + fi4] = v;
        }
        __syncthreads();
    }

    for (int p = warp; p < 512; p += 8) {
        float a = conv_s[p * 64 + lane] * w_s[lane]
                + conv_s[p * 64 + 32 + lane] * w_s[32 + lane];
#pragma unroll
        for (int o = 16; o; o >>= 1) a += __shfl_xor_sync(0xffffffffu, a, o);
        if (lane == 0) alpha_s[p] = 1.f / (1.f + expf(-a));
    }
    __syncthreads();

    {
        int qn = tid & 63, part = tid >> 6;
        float a = 0.f;
        for (int p = part; p < 512; p += 4) a += alpha_s[p] * conv_s[p * 64 + qn];
        red_s[tid] = a;
    }
    __syncthreads();
    if (tid < 64) v_s[tid] = red_s[tid] + red_s[64 + tid] + red_s[128 + tid] + red_s[192 + tid];
    __syncthreads();

    float a = 0.f;
    for (int k = tid; k < HD_; k += 256) a += htt_s[k] * g_effw[k];
    if (tid < 64) a += v_s[tid] * g_effw[HD_ + tid];
#pragma unroll
    for (int o = 16; o; o >>= 1) a += __shfl_xor_sync(0xffffffffu, a, o);
    if (lane == 0) red_s[warp] = a;
    __syncthreads();
    if (tid == 0) {
        float tot = g_effw[576];
        for (int i = 0; i < 8; i++) tot += red_s[i];
        out[b] = tot;
    }
}

// ---------------- launch ----------------------------------------------------
extern "C" void kernel_launch(void* const* d_in, const int* in_sizes, int n_in,
                              void* d_out, int out_size) {
    const float* x      = (const float*)d_in[0];
    const float* W_ih   = (const float*)d_in[1];
    const float* W_hh   = (const float*)d_in[2];
    const float* b_ih   = (const float*)d_in[3];
    const float* b_hh   = (const float*)d_in[4];
    const float* conv_W = (const float*)d_in[5];
    const float* conv_b = (const float*)d_in[6];
    const float* lin1_W = (const float*)d_in[7];
    const float* lin1_b = (const float*)d_in[8];
    const float* lin2_W = (const float*)d_in[9];
    const float* lin2_b = (const float*)d_in[10];
    const float* out_W  = (const float*)d_in[11];
    const float* out_b  = (const float*)d_in[12];
    float* out = (float*)d_out;

    {   // prep (2 launches)
        size_t tw = (size_t)L_ * NG * KK;
        prep_w_kernel<<<(unsigned)((tw + 255) / 256), 256>>>(W_ih, W_hh, b_ih, b_hh);
        size_t tx = (size_t)T_ * B_ * D_;
        prep_misc_kernel<<<(unsigned)((tx + 255) / 256), 256>>>(x, lin2_W, lin2_b, out_W, out_b);
    }

    // persistent dataflow wavefront (single launch for all 192 cells)
    cudaFuncSetAttribute(lstm_persist, cudaFuncAttributeMaxDynamicSharedMemorySize, DYN_SMEM);
    lstm_persist<<<NPERS, NTHR, DYN_SMEM>>>();

    // head
    cudaFuncSetAttribute(head_kernel, cudaFuncAttributeMaxDynamicSharedMemorySize,
                         HEAD_SMEM_FLOATS * (int)sizeof(float));
    head_kernel<<<B_, 256, HEAD_SMEM_FLOATS * (int)sizeof(float)>>>(
        conv_W, conv_b, lin1_W, lin1_b, out);
}